// round 10
// baseline (speedup 1.0000x reference)
#include <cuda_runtime.h>
#include <cuda_bf16.h>
#include <math.h>
#include <stdint.h>

// Problem constants
#define DIN   256
#define HCc   256
#define NEG   0.2f
#define MAXN  50000
#define MAXE  1000000

// ---------------- scratch (static device globals) --------------------------
__device__ float g_XL1[(long long)MAXN * HCc];
__device__ float g_XR1[(long long)MAXN * HCc];
__device__ float g_SKIP[(long long)MAXN * HCc];
__device__ float g_XL2[MAXN * 2];
__device__ float g_XR2[MAXN * 2];
__device__ int   g_deg[MAXN];
__device__ int   g_rowptr[MAXN + 1];
__device__ int   g_cur[MAXN];
__device__ int   g_esrc[MAXE];
__device__ int   g_bsum[64];
__device__ int   g_boff[64];
__device__ int   g_is64;
// split-bf16 transposed weights: [sel][N=256][K=256]
__device__ __nv_bfloat16 g_BT_hi[3 * 256 * 256];
__device__ __nv_bfloat16 g_BT_lo[3 * 256 * 256];

// ---------------- small helpers ---------------------------------------------
__device__ __forceinline__ uint32_t smem_u32(const void* p) {
    uint32_t a;
    asm("{ .reg .u64 t; cvta.to.shared.u64 t, %1; cvt.u32.u64 %0, t; }"
        : "=r"(a) : "l"(p));
    return a;
}
__device__ __forceinline__ void ldsm_x4(uint32_t* r, uint32_t addr) {
    asm volatile("ldmatrix.sync.aligned.m8n8.x4.shared.b16 {%0,%1,%2,%3}, [%4];"
        : "=r"(r[0]), "=r"(r[1]), "=r"(r[2]), "=r"(r[3]) : "r"(addr));
}
__device__ __forceinline__ void mma_bf16(float* c, const uint32_t* a,
                                         uint32_t b0, uint32_t b1) {
    asm volatile(
        "mma.sync.aligned.m16n8k16.row.col.f32.bf16.bf16.f32 "
        "{%0,%1,%2,%3}, {%4,%5,%6,%7}, {%8,%9}, {%0,%1,%2,%3};"
        : "+f"(c[0]), "+f"(c[1]), "+f"(c[2]), "+f"(c[3])
        : "r"(a[0]), "r"(a[1]), "r"(a[2]), "r"(a[3]), "r"(b0), "r"(b1));
}
__device__ __forceinline__ void cp_async16(uint32_t dst, const void* src) {
    asm volatile("cp.async.ca.shared.global [%0], [%1], 16;"
                 :: "r"(dst), "l"(src) : "memory");
}
#define CP_COMMIT() asm volatile("cp.async.commit_group;" ::: "memory")
#define CP_WAIT0()  asm volatile("cp.async.wait_group 0;" ::: "memory")

// ---------------- dtype detection for edge_index (int32 vs int64) ---------
__global__ void detect_idx_kernel(const unsigned int* __restrict__ w) {
    int ok = 1;
    #pragma unroll
    for (int i = 0; i < 32; i++) {
        if (w[2 * i + 1] != 0u) { ok = 0; break; }
    }
    g_is64 = ok;
}
__device__ __forceinline__ int ld_idx(const void* ei, long long pos, int is64) {
    if (is64) return (int)(((const long long*)ei)[pos]);
    return ((const int*)ei)[pos];
}

// ---------------- CSR build -------------------------------------------------
__global__ void zero_deg_kernel(int N) {
    int i = blockIdx.x * blockDim.x + threadIdx.x;
    if (i < N) g_deg[i] = 0;
}
__global__ void hist_kernel(const void* __restrict__ ei, long long E) {
    long long e = (long long)blockIdx.x * blockDim.x + threadIdx.x;
    if (e >= E) return;
    int dst = ld_idx(ei, E + e, g_is64);
    atomicAdd(&g_deg[dst], 1);
}
__global__ __launch_bounds__(1024) void scanA_kernel(int N) {
    __shared__ int wsum[32];
    const int lane = threadIdx.x & 31, warp = threadIdx.x >> 5;
    int i = blockIdx.x * 1024 + threadIdx.x;
    int v = (i < N) ? g_deg[i] : 0;
    int x = v;
    #pragma unroll
    for (int o = 1; o < 32; o <<= 1) {
        int y = __shfl_up_sync(0xffffffffu, x, o);
        if (lane >= o) x += y;
    }
    if (lane == 31) wsum[warp] = x;
    __syncthreads();
    if (warp == 0) {
        int w = wsum[lane];
        #pragma unroll
        for (int o = 1; o < 32; o <<= 1) {
            int y = __shfl_up_sync(0xffffffffu, w, o);
            if (lane >= o) w += y;
        }
        wsum[lane] = w;
    }
    __syncthreads();
    int incl = x + (warp > 0 ? wsum[warp - 1] : 0);
    if (i < N) g_rowptr[i + 1] = incl;
    if (threadIdx.x == 1023) g_bsum[blockIdx.x] = incl;
}
__global__ void scanB_kernel(int B) {
    if (threadIdx.x == 0) {
        int acc = 0;
        for (int b = 0; b < B; b++) { int v = g_bsum[b]; g_boff[b] = acc; acc += v; }
    }
}
__global__ __launch_bounds__(1024) void scanC_kernel(int N) {
    int i = blockIdx.x * 1024 + threadIdx.x;
    if (i == 0) g_rowptr[0] = 0;
    if (i < N) {
        int r = g_rowptr[i + 1] + g_boff[blockIdx.x];
        g_rowptr[i + 1] = r;
        g_cur[i] = r - g_deg[i];
    }
}
__global__ void scatter_kernel(const void* __restrict__ ei, long long E) {
    long long e = (long long)blockIdx.x * blockDim.x + threadIdx.x;
    if (e >= E) return;
    int is64 = g_is64;
    int src = ld_idx(ei, e, is64);
    int dst = ld_idx(ei, E + e, is64);
    int pos = atomicAdd(&g_cur[dst], 1);
    g_esrc[pos] = src;
}

// ---------------- B prep: transpose + bf16 split ----------------------------
__global__ void prep_b_kernel(const float* __restrict__ W0,
                              const float* __restrict__ W1,
                              const float* __restrict__ W2) {
    int s = blockIdx.y, k = blockIdx.x, n = threadIdx.x;
    const float* W = (s == 0) ? W0 : (s == 1) ? W1 : W2;
    float v = W[k * 256 + n];
    __nv_bfloat16 hi = __float2bfloat16(v);
    float lo = v - __bfloat162float(hi);
    int idx = (s * 256 + n) * 256 + k;
    g_BT_hi[idx] = hi;
    g_BT_lo[idx] = __float2bfloat16(lo);
}

// ---------------- mma.sync bf16-split triple GEMM ---------------------------
#define PADK 24
#define ABUF (128 * PADK)
#define BUFB (ABUF * 2)

__global__ __launch_bounds__(256, 2) void gemm_mma_kernel(
    const float* __restrict__ A,
    const float* __restrict__ bias0, const float* __restrict__ bias1,
    const float* __restrict__ bias2,
    float* __restrict__ C0, float* __restrict__ C1, float* __restrict__ C2,
    int M)
{
    __shared__ __nv_bfloat16 sAh[2][ABUF];
    __shared__ __nv_bfloat16 sAl[2][ABUF];
    __shared__ __nv_bfloat16 sBh[2][ABUF];
    __shared__ __nv_bfloat16 sBl[2][ABUF];

    const int sel = blockIdx.x >> 1;
    const int n0  = (blockIdx.x & 1) * 128;
    const int m0  = blockIdx.y * 128;
    const float* bias = (sel == 0) ? bias0 : (sel == 1) ? bias1 : bias2;
    float*       C    = (sel == 0) ? C0 : (sel == 1) ? C1 : C2;
    const __nv_bfloat16* BTh = g_BT_hi + sel * 65536 + (long long)n0 * 256;
    const __nv_bfloat16* BTl = g_BT_lo + sel * 65536 + (long long)n0 * 256;

    const int tid  = threadIdx.x;
    const int lane = tid & 31;
    const int wid  = tid >> 5;
    const int wm0  = (wid >> 2) * 64;
    const int wn0  = (wid & 3) * 32;

    const int ar = tid >> 1;
    const int ak = (tid & 1) * 8;
    const bool arow_ok = (m0 + ar) < M;
    const float* Ap = A + (long long)(m0 + ar) * 256 + ak;
    const __nv_bfloat16* gBh = BTh + (long long)ar * 256 + ak;
    const __nv_bfloat16* gBl = BTl + (long long)ar * 256 + ak;
    __nv_bfloat16* pAh0 = &sAh[0][ar * PADK + ak];
    __nv_bfloat16* pAl0 = &sAl[0][ar * PADK + ak];
    const uint32_t dBh0 = smem_u32(&sBh[0][ar * PADK + ak]);
    const uint32_t dBl0 = smem_u32(&sBl[0][ar * PADK + ak]);

    uint32_t a_h[4], a_l[4], b_h[2], b_l[2];
    {
        int arow = lane & 15;
        int acol = (lane >> 4) * 8;
        #pragma unroll
        for (int fm = 0; fm < 4; fm++) {
            int idx = (wm0 + fm * 16 + arow) * PADK + acol;
            a_h[fm] = smem_u32(&sAh[0][idx]);
            a_l[fm] = smem_u32(&sAl[0][idx]);
        }
        int brow = (lane & 7) + (lane >> 4) * 8;
        int bcol = ((lane >> 3) & 1) * 8;
        #pragma unroll
        for (int nb = 0; nb < 2; nb++) {
            int idx = (wn0 + nb * 16 + brow) * PADK + bcol;
            b_h[nb] = smem_u32(&sBh[0][idx]);
            b_l[nb] = smem_u32(&sBl[0][idx]);
        }
    }

    float acc[16][4];
    #pragma unroll
    for (int i = 0; i < 16; i++)
        #pragma unroll
        for (int j = 0; j < 4; j++) acc[i][j] = 0.f;

    // prologue: stage 0 into buffer 0
    cp_async16(dBh0, gBh);
    cp_async16(dBl0, gBl);
    CP_COMMIT();
    float4 v0 = make_float4(0.f, 0.f, 0.f, 0.f);
    float4 v1 = make_float4(0.f, 0.f, 0.f, 0.f);
    if (arow_ok) { v0 = *(const float4*)Ap; v1 = *(const float4*)(Ap + 4); }
    {
        float f[8] = {v0.x, v0.y, v0.z, v0.w, v1.x, v1.y, v1.z, v1.w};
        #pragma unroll
        for (int j = 0; j < 4; j++) {
            __nv_bfloat162 h = __floats2bfloat162_rn(f[2*j], f[2*j+1]);
            __nv_bfloat162 l = __floats2bfloat162_rn(f[2*j]   - __low2float(h),
                                                     f[2*j+1] - __high2float(h));
            *(__nv_bfloat162*)(pAh0 + 2 * j) = h;
            *(__nv_bfloat162*)(pAl0 + 2 * j) = l;
        }
    }
    CP_WAIT0();
    __syncthreads();

    int buf = 0;
    for (int ks = 0; ks < 256; ks += 16) {
        const int nb = buf ^ 1;
        const bool has_next = (ks + 16) < 256;
        if (has_next) {
            cp_async16(dBh0 + nb * BUFB, gBh + ks + 16);
            cp_async16(dBl0 + nb * BUFB, gBl + ks + 16);
            CP_COMMIT();
            v0 = make_float4(0.f, 0.f, 0.f, 0.f);
            v1 = make_float4(0.f, 0.f, 0.f, 0.f);
            if (arow_ok) {
                v0 = *(const float4*)(Ap + ks + 16);
                v1 = *(const float4*)(Ap + ks + 20);
            }
        }
        const uint32_t bofs = buf * BUFB;
        uint32_t Af[4][4], Bf[2][4];
        #pragma unroll
        for (int fm = 0; fm < 4; fm++) ldsm_x4(Af[fm], a_h[fm] + bofs);
        ldsm_x4(Bf[0], b_h[0] + bofs);
        ldsm_x4(Bf[1], b_h[1] + bofs);
        #pragma unroll
        for (int fm = 0; fm < 4; fm++)
            #pragma unroll
            for (int fn = 0; fn < 4; fn++)
                mma_bf16(acc[fm * 4 + fn], Af[fm],
                         Bf[fn >> 1][(fn & 1) * 2], Bf[fn >> 1][(fn & 1) * 2 + 1]);
        #pragma unroll
        for (int fm = 0; fm < 4; fm++) ldsm_x4(Af[fm], a_l[fm] + bofs);
        #pragma unroll
        for (int fm = 0; fm < 4; fm++)
            #pragma unroll
            for (int fn = 0; fn < 4; fn++)
                mma_bf16(acc[fm * 4 + fn], Af[fm],
                         Bf[fn >> 1][(fn & 1) * 2], Bf[fn >> 1][(fn & 1) * 2 + 1]);
        ldsm_x4(Bf[0], b_l[0] + bofs);
        ldsm_x4(Bf[1], b_l[1] + bofs);
        #pragma unroll
        for (int fm = 0; fm < 4; fm++) ldsm_x4(Af[fm], a_h[fm] + bofs);
        #pragma unroll
        for (int fm = 0; fm < 4; fm++)
            #pragma unroll
            for (int fn = 0; fn < 4; fn++)
                mma_bf16(acc[fm * 4 + fn], Af[fm],
                         Bf[fn >> 1][(fn & 1) * 2], Bf[fn >> 1][(fn & 1) * 2 + 1]);
        if (has_next) {
            float f[8] = {v0.x, v0.y, v0.z, v0.w, v1.x, v1.y, v1.z, v1.w};
            __nv_bfloat16* pAh = pAh0 + nb * ABUF;
            __nv_bfloat16* pAl = pAl0 + nb * ABUF;
            #pragma unroll
            for (int j = 0; j < 4; j++) {
                __nv_bfloat162 h = __floats2bfloat162_rn(f[2*j], f[2*j+1]);
                __nv_bfloat162 l = __floats2bfloat162_rn(f[2*j]   - __low2float(h),
                                                         f[2*j+1] - __high2float(h));
                *(__nv_bfloat162*)(pAh + 2 * j) = h;
                *(__nv_bfloat162*)(pAl + 2 * j) = l;
            }
            CP_WAIT0();
        }
        __syncthreads();
        buf = nb;
    }

    #pragma unroll
    for (int fm = 0; fm < 4; fm++) {
        int r0 = m0 + wm0 + fm * 16 + (lane >> 2);
        #pragma unroll
        for (int fn = 0; fn < 4; fn++) {
            int col = n0 + wn0 + fn * 8 + (lane & 3) * 2;
            float2 bv = *(const float2*)(bias + col);
            float* a4 = acc[fm * 4 + fn];
            if (r0 < M) {
                float2 o = make_float2(a4[0] + bv.x, a4[1] + bv.y);
                *(float2*)(C + (long long)r0 * 256 + col) = o;
            }
            int r1 = r0 + 8;
            if (r1 < M) {
                float2 o = make_float2(a4[2] + bv.x, a4[3] + bv.y);
                *(float2*)(C + (long long)r1 * 256 + col) = o;
            }
        }
    }
}

// ------- fused conv1 CSR + softmax + skip + LN + ELU + conv2 projection ----
// One warp per dst node. Branch-free lrelu-dot (0.6e + 0.4|e|), __expf.
__global__ __launch_bounds__(256) void conv1_csr_kernel(
    const float* __restrict__ att1, const float* __restrict__ bias1,
    const float* __restrict__ gamma, const float* __restrict__ beta,
    const float* __restrict__ W2l, const float* __restrict__ b2l,
    const float* __restrict__ W2r, const float* __restrict__ b2r,
    const float* __restrict__ att2, int N)
{
    const int n = blockIdx.x * 8 + (threadIdx.x >> 5);
    const int lane = threadIdx.x & 31;
    if (n >= N) return;

    float att6[8], att4[8];
    {
        float4 a0 = *(const float4*)(att1 + lane * 8);
        float4 a1 = *(const float4*)(att1 + lane * 8 + 4);
        float av[8] = {a0.x,a0.y,a0.z,a0.w,a1.x,a1.y,a1.z,a1.w};
        #pragma unroll
        for (int j = 0; j < 8; j++) { att6[j] = 0.6f * av[j]; att4[j] = 0.4f * av[j]; }
    }
    float xr[8];
    {
        const float* p = g_XR1 + (long long)n * HCc + lane * 8;
        float4 r0 = *(const float4*)p;
        float4 r1 = *(const float4*)(p + 4);
        xr[0]=r0.x; xr[1]=r0.y; xr[2]=r0.z; xr[3]=r0.w;
        xr[4]=r1.x; xr[5]=r1.y; xr[6]=r1.z; xr[7]=r1.w;
    }

    float acc[8], den;
    // self-loop
    {
        const float* p = g_XL1 + (long long)n * HCc + lane * 8;
        float4 l0 = *(const float4*)p;
        float4 l1 = *(const float4*)(p + 4);
        float xl[8] = {l0.x,l0.y,l0.z,l0.w,l1.x,l1.y,l1.z,l1.w};
        float s6 = 0.f, s4 = 0.f;
        #pragma unroll
        for (int j = 0; j < 8; j++) {
            float e = xl[j] + xr[j];
            s6 = fmaf(e, att6[j], s6);
            s4 = fmaf(fabsf(e), att4[j], s4);
        }
        float s = s6 + s4;
        s += __shfl_xor_sync(0xffffffffu, s, 1);
        s += __shfl_xor_sync(0xffffffffu, s, 2);
        s += __shfl_xor_sync(0xffffffffu, s, 4);
        float ex = __expf(s);
        den = ex;
        #pragma unroll
        for (int j = 0; j < 8; j++) acc[j] = ex * xl[j];
    }

    const int row0 = g_rowptr[n];
    const int row1 = g_rowptr[n + 1];
    int i = row0;
    for (; i + 1 < row1; i += 2) {
        int srcA = g_esrc[i];
        int srcB = g_esrc[i + 1];
        const float* pA = g_XL1 + (long long)srcA * HCc + lane * 8;
        const float* pB = g_XL1 + (long long)srcB * HCc + lane * 8;
        float4 a0 = *(const float4*)pA;
        float4 a1 = *(const float4*)(pA + 4);
        float4 b0 = *(const float4*)pB;
        float4 b1 = *(const float4*)(pB + 4);
        float xlA[8] = {a0.x,a0.y,a0.z,a0.w,a1.x,a1.y,a1.z,a1.w};
        float xlB[8] = {b0.x,b0.y,b0.z,b0.w,b1.x,b1.y,b1.z,b1.w};
        float sA6 = 0.f, sA4 = 0.f, sB6 = 0.f, sB4 = 0.f;
        #pragma unroll
        for (int j = 0; j < 8; j++) {
            float eA = xlA[j] + xr[j];
            float eB = xlB[j] + xr[j];
            sA6 = fmaf(eA, att6[j], sA6);
            sA4 = fmaf(fabsf(eA), att4[j], sA4);
            sB6 = fmaf(eB, att6[j], sB6);
            sB4 = fmaf(fabsf(eB), att4[j], sB4);
        }
        float sA = sA6 + sA4, sB = sB6 + sB4;
        #pragma unroll
        for (int o = 1; o <= 4; o <<= 1) {
            sA += __shfl_xor_sync(0xffffffffu, sA, o);
            sB += __shfl_xor_sync(0xffffffffu, sB, o);
        }
        float exA = __expf(sA);
        float exB = __expf(sB);
        den += exA + exB;
        #pragma unroll
        for (int j = 0; j < 8; j++) {
            acc[j] = fmaf(exA, xlA[j], acc[j]);
            acc[j] = fmaf(exB, xlB[j], acc[j]);
        }
    }
    if (i < row1) {
        int src = g_esrc[i];
        const float* p = g_XL1 + (long long)src * HCc + lane * 8;
        float4 l0 = *(const float4*)p;
        float4 l1 = *(const float4*)(p + 4);
        float xl[8] = {l0.x,l0.y,l0.z,l0.w,l1.x,l1.y,l1.z,l1.w};
        float s6 = 0.f, s4 = 0.f;
        #pragma unroll
        for (int j = 0; j < 8; j++) {
            float e = xl[j] + xr[j];
            s6 = fmaf(e, att6[j], s6);
            s4 = fmaf(fabsf(e), att4[j], s4);
        }
        float s = s6 + s4;
        s += __shfl_xor_sync(0xffffffffu, s, 1);
        s += __shfl_xor_sync(0xffffffffu, s, 2);
        s += __shfl_xor_sync(0xffffffffu, s, 4);
        float ex = __expf(s);
        den += ex;
        #pragma unroll
        for (int j = 0; j < 8; j++) acc[j] = fmaf(ex, xl[j], acc[j]);
    }

    const float dinv = 1.0f / den;
    float v[8];
    {
        const float* sp = g_SKIP + (long long)n * HCc + lane * 8;
        float4 s0 = *(const float4*)sp;
        float4 s1 = *(const float4*)(sp + 4);
        float4 b0 = *(const float4*)(bias1 + lane * 8);
        float4 b1 = *(const float4*)(bias1 + lane * 8 + 4);
        float sk[8] = {s0.x,s0.y,s0.z,s0.w,s1.x,s1.y,s1.z,s1.w};
        float bb[8] = {b0.x,b0.y,b0.z,b0.w,b1.x,b1.y,b1.z,b1.w};
        #pragma unroll
        for (int j = 0; j < 8; j++) v[j] = acc[j] * dinv + bb[j] + sk[j];
    }

    float t = 0.f;
    #pragma unroll
    for (int j = 0; j < 8; j++) t += v[j];
    #pragma unroll
    for (int o = 16; o > 0; o >>= 1) t += __shfl_xor_sync(0xffffffffu, t, o);
    const float mu = t * (1.0f / 256.0f);
    float t2 = 0.f;
    #pragma unroll
    for (int j = 0; j < 8; j++) { float d = v[j] - mu; t2 = fmaf(d, d, t2); }
    #pragma unroll
    for (int o = 16; o > 0; o >>= 1) t2 += __shfl_xor_sync(0xffffffffu, t2, o);
    const float rstd = rsqrtf(t2 * (1.0f / 256.0f) + 1e-5f);

    float h[8];
    {
        float4 g0 = *(const float4*)(gamma + lane * 8);
        float4 g1 = *(const float4*)(gamma + lane * 8 + 4);
        float4 e0 = *(const float4*)(beta + lane * 8);
        float4 e1 = *(const float4*)(beta + lane * 8 + 4);
        float gg[8] = {g0.x,g0.y,g0.z,g0.w,g1.x,g1.y,g1.z,g1.w};
        float be[8] = {e0.x,e0.y,e0.z,e0.w,e1.x,e1.y,e1.z,e1.w};
        #pragma unroll
        for (int j = 0; j < 8; j++) {
            float hh = (v[j] - mu) * rstd * gg[j] + be[j];
            h[j] = hh > 0.f ? hh : expm1f(hh);
        }
    }

    float p0 = 0.f, p1 = 0.f, p2 = 0.f, p3 = 0.f;
    {
        const float* wl = W2l + lane * 16;
        const float* wr = W2r + lane * 16;
        float4 wl0 = *(const float4*)wl;
        float4 wl1 = *(const float4*)(wl + 4);
        float4 wl2 = *(const float4*)(wl + 8);
        float4 wl3 = *(const float4*)(wl + 12);
        float4 wr0 = *(const float4*)wr;
        float4 wr1 = *(const float4*)(wr + 4);
        float4 wr2 = *(const float4*)(wr + 8);
        float4 wr3 = *(const float4*)(wr + 12);
        float wlv[16] = {wl0.x,wl0.y,wl0.z,wl0.w, wl1.x,wl1.y,wl1.z,wl1.w,
                         wl2.x,wl2.y,wl2.z,wl2.w, wl3.x,wl3.y,wl3.z,wl3.w};
        float wrv[16] = {wr0.x,wr0.y,wr0.z,wr0.w, wr1.x,wr1.y,wr1.z,wr1.w,
                         wr2.x,wr2.y,wr2.z,wr2.w, wr3.x,wr3.y,wr3.z,wr3.w};
        #pragma unroll
        for (int j = 0; j < 8; j++) {
            p0 = fmaf(h[j], wlv[2 * j + 0], p0);
            p1 = fmaf(h[j], wlv[2 * j + 1], p1);
            p2 = fmaf(h[j], wrv[2 * j + 0], p2);
            p3 = fmaf(h[j], wrv[2 * j + 1], p3);
        }
    }
    #pragma unroll
    for (int o = 16; o > 0; o >>= 1) {
        p0 += __shfl_xor_sync(0xffffffffu, p0, o);
        p1 += __shfl_xor_sync(0xffffffffu, p1, o);
        p2 += __shfl_xor_sync(0xffffffffu, p2, o);
        p3 += __shfl_xor_sync(0xffffffffu, p3, o);
    }
    if (lane == 0) {
        float2 xl2, xr2;
        xl2.x = p0 + b2l[0]; xl2.y = p1 + b2l[1];
        xr2.x = p2 + b2r[0]; xr2.y = p3 + b2r[1];
        *(float2*)&g_XL2[n * 2] = xl2;
        *(float2*)&g_XR2[n * 2] = xr2;
    }
}

// ------------- conv2 CSR + final output (warp per node) --------------------
__global__ __launch_bounds__(256) void conv2_csr_kernel(
    const float* __restrict__ att2, const float* __restrict__ bias2,
    float* __restrict__ out, int N)
{
    const int n = blockIdx.x * 8 + (threadIdx.x >> 5);
    const int lane = threadIdx.x & 31;
    if (n >= N) return;
    const float a0 = att2[0], a1 = att2[1];
    const float a06 = 0.6f * a0, a04 = 0.4f * a0;
    const float a16 = 0.6f * a1, a14 = 0.4f * a1;
    float2 xls = *(const float2*)&g_XL2[n * 2];
    float2 xr  = *(const float2*)&g_XR2[n * 2];

    float den = 0.f, s0 = 0.f, s1 = 0.f;
    const int row0 = g_rowptr[n], row1 = g_rowptr[n + 1];
    for (int i = row0 + lane; i < row1; i += 32) {
        int src = g_esrc[i];
        float2 xl = *(const float2*)&g_XL2[src * 2];
        float f0 = xl.x + xr.x;
        float f1 = xl.y + xr.y;
        float s = fmaf(f0, a06, fmaf(fabsf(f0), a04,
                  fmaf(f1, a16, fabsf(f1) * a14)));
        float exi = __expf(s);
        den += exi;
        s0 = fmaf(exi, xl.x, s0);
        s1 = fmaf(exi, xl.y, s1);
    }
    #pragma unroll
    for (int o = 16; o > 0; o >>= 1) {
        den += __shfl_xor_sync(0xffffffffu, den, o);
        s0  += __shfl_xor_sync(0xffffffffu, s0, o);
        s1  += __shfl_xor_sync(0xffffffffu, s1, o);
    }
    if (lane == 0) {
        // self loop
        float f0 = xls.x + xr.x;
        float f1 = xls.y + xr.y;
        float s = fmaf(f0, a06, fmaf(fabsf(f0), a04,
                  fmaf(f1, a16, fabsf(f1) * a14)));
        float ex = __expf(s);
        den += ex;
        s0 = fmaf(ex, xls.x, s0);
        s1 = fmaf(ex, xls.y, s1);
        float dinv = 1.0f / den;
        float2 o;
        o.x = s0 * dinv + bias2[0];
        o.y = s1 * dinv + bias2[1];
        *(float2*)(out + n * 2) = o;
    }
}

// ---------------------------------------------------------------------------
extern "C" void kernel_launch(void* const* d_in, const int* in_sizes, int n_in,
                              void* d_out, int out_size) {
    const float* x     = (const float*)d_in[0];
    const void*  ei    = d_in[1];
    const float* W1l   = (const float*)d_in[2];
    const float* b1l   = (const float*)d_in[3];
    const float* W1r   = (const float*)d_in[4];
    const float* b1r   = (const float*)d_in[5];
    const float* att1  = (const float*)d_in[6];
    const float* bias1 = (const float*)d_in[7];
    const float* W2l   = (const float*)d_in[8];
    const float* b2l   = (const float*)d_in[9];
    const float* W2r   = (const float*)d_in[10];
    const float* b2r   = (const float*)d_in[11];
    const float* att2  = (const float*)d_in[12];
    const float* bias2 = (const float*)d_in[13];
    const float* Wskip = (const float*)d_in[14];
    const float* bskip = (const float*)d_in[15];
    const float* gamma = (const float*)d_in[16];
    const float* beta  = (const float*)d_in[17];
    float* out = (float*)d_out;

    const int       N = in_sizes[0] / DIN;            // 50000
    const long long E = (long long)in_sizes[1] / 2;   // 800000

    float *dXL1, *dXR1, *dSKIP;
    cudaGetSymbolAddress((void**)&dXL1, g_XL1);
    cudaGetSymbolAddress((void**)&dXR1, g_XR1);
    cudaGetSymbolAddress((void**)&dSKIP, g_SKIP);

    detect_idx_kernel<<<1, 1>>>((const unsigned int*)ei);
    {
        dim3 g(256, 3);
        prep_b_kernel<<<g, 256>>>(W1l, W1r, Wskip);
    }
    const int SB = (N + 1023) / 1024;
    zero_deg_kernel<<<(N + 255) / 256, 256>>>(N);
    hist_kernel<<<(int)((E + 255) / 256), 256>>>(ei, E);
    scanA_kernel<<<SB, 1024>>>(N);
    {
        dim3 g(6, (N + 127) / 128);
        gemm_mma_kernel<<<g, 256>>>(x, b1l, b1r, bskip, dXL1, dXR1, dSKIP, N);
    }
    scanB_kernel<<<1, 32>>>(SB);
    scanC_kernel<<<SB, 1024>>>(N);
    scatter_kernel<<<(int)((E + 255) / 256), 256>>>(ei, E);

    conv1_csr_kernel<<<(N + 7) / 8, 256>>>(att1, bias1, gamma, beta,
                                           W2l, b2l, W2r, b2r, att2, N);
    conv2_csr_kernel<<<(N + 7) / 8, 256>>>(att2, bias2, out, N);
}

// round 11
// speedup vs baseline: 1.0637x; 1.0637x over previous
#include <cuda_runtime.h>
#include <cuda_bf16.h>
#include <math.h>
#include <stdint.h>

// Problem constants
#define DIN   256
#define HCc   256
#define NEG   0.2f
#define MAXN  50000
#define MAXE  1000000
#define MPAD  (MAXN + 128)

// ---------------- scratch (static device globals) --------------------------
__device__ float g_XL1[(long long)MAXN * HCc];
__device__ float g_XR1[(long long)MAXN * HCc];
__device__ float g_SKIP[(long long)MAXN * HCc];
__device__ float g_XL2[MAXN * 2];
__device__ float g_XR2[MAXN * 2];
__device__ int   g_deg[MAXN];
__device__ int   g_rowptr[MAXN + 1];
__device__ int   g_cur[MAXN];
__device__ int   g_esrc[MAXE];
__device__ int   g_bsum[64];
__device__ int   g_boff[64];
__device__ int   g_is64;
// split-bf16 transposed weights: [sel][N=256][K=256]
__device__ __nv_bfloat16 g_BT_hi[3 * 256 * 256];
__device__ __nv_bfloat16 g_BT_lo[3 * 256 * 256];
// split-bf16 A (x): [m][k], padded rows so OOB tile reads stay in-bounds
__device__ __nv_bfloat16 g_AT_hi[(long long)MPAD * 256];
__device__ __nv_bfloat16 g_AT_lo[(long long)MPAD * 256];

// ---------------- small helpers ---------------------------------------------
__device__ __forceinline__ uint32_t smem_u32(const void* p) {
    uint32_t a;
    asm("{ .reg .u64 t; cvta.to.shared.u64 t, %1; cvt.u32.u64 %0, t; }"
        : "=r"(a) : "l"(p));
    return a;
}
__device__ __forceinline__ void ldsm_x4(uint32_t* r, uint32_t addr) {
    asm volatile("ldmatrix.sync.aligned.m8n8.x4.shared.b16 {%0,%1,%2,%3}, [%4];"
        : "=r"(r[0]), "=r"(r[1]), "=r"(r[2]), "=r"(r[3]) : "r"(addr));
}
__device__ __forceinline__ void mma_bf16(float* c, const uint32_t* a,
                                         uint32_t b0, uint32_t b1) {
    asm volatile(
        "mma.sync.aligned.m16n8k16.row.col.f32.bf16.bf16.f32 "
        "{%0,%1,%2,%3}, {%4,%5,%6,%7}, {%8,%9}, {%0,%1,%2,%3};"
        : "+f"(c[0]), "+f"(c[1]), "+f"(c[2]), "+f"(c[3])
        : "r"(a[0]), "r"(a[1]), "r"(a[2]), "r"(a[3]), "r"(b0), "r"(b1));
}
__device__ __forceinline__ void cp_async16(uint32_t dst, const void* src) {
    asm volatile("cp.async.ca.shared.global [%0], [%1], 16;"
                 :: "r"(dst), "l"(src) : "memory");
}
#define CP_COMMIT() asm volatile("cp.async.commit_group;" ::: "memory")
#define CP_WAIT0()  asm volatile("cp.async.wait_group 0;" ::: "memory")

// ---------------- dtype detection for edge_index (int32 vs int64) ---------
__global__ void detect_idx_kernel(const unsigned int* __restrict__ w) {
    int ok = 1;
    #pragma unroll
    for (int i = 0; i < 32; i++) {
        if (w[2 * i + 1] != 0u) { ok = 0; break; }
    }
    g_is64 = ok;
}
__device__ __forceinline__ int ld_idx(const void* ei, long long pos, int is64) {
    if (is64) return (int)(((const long long*)ei)[pos]);
    return ((const int*)ei)[pos];
}

// ---------------- fused prep: B transpose+split AND A split -----------------
// blocks [0,768): B prep (sel = b>>8, k = b&255, n = tid)
// blocks [768,...): A prep, 1024 elements per block via float4
__global__ void prep_ab_kernel(const float* __restrict__ x,
                               const float* __restrict__ W0,
                               const float* __restrict__ W1,
                               const float* __restrict__ W2, int N) {
    int b = blockIdx.x;
    if (b < 768) {
        int s = b >> 8, k = b & 255, n = threadIdx.x;
        const float* W = (s == 0) ? W0 : (s == 1) ? W1 : W2;
        float v = W[k * 256 + n];
        __nv_bfloat16 hi = __float2bfloat16(v);
        float lo = v - __bfloat162float(hi);
        int idx = (s * 256 + n) * 256 + k;
        g_BT_hi[idx] = hi;
        g_BT_lo[idx] = __float2bfloat16(lo);
    } else {
        long long eb = (long long)(b - 768) * 1024 + threadIdx.x * 4;
        if (eb < (long long)N * 256) {
            float4 v = *(const float4*)(x + eb);
            float f[4] = {v.x, v.y, v.z, v.w};
            __nv_bfloat16 h[4], l[4];
            #pragma unroll
            for (int j = 0; j < 4; j++) {
                h[j] = __float2bfloat16(f[j]);
                l[j] = __float2bfloat16(f[j] - __bfloat162float(h[j]));
            }
            *(ulonglong1*)(g_AT_hi + eb) = *(ulonglong1*)h;
            *(ulonglong1*)(g_AT_lo + eb) = *(ulonglong1*)l;
        }
    }
}

// ---------------- CSR build -------------------------------------------------
__global__ void zero_deg_kernel(int N) {
    int i = blockIdx.x * blockDim.x + threadIdx.x;
    if (i < N) g_deg[i] = 0;
}
__global__ void hist_kernel(const void* __restrict__ ei, long long E) {
    long long e = (long long)blockIdx.x * blockDim.x + threadIdx.x;
    if (e >= E) return;
    int dst = ld_idx(ei, E + e, g_is64);
    atomicAdd(&g_deg[dst], 1);
}
__global__ __launch_bounds__(1024) void scanA_kernel(int N) {
    __shared__ int wsum[32];
    const int lane = threadIdx.x & 31, warp = threadIdx.x >> 5;
    int i = blockIdx.x * 1024 + threadIdx.x;
    int v = (i < N) ? g_deg[i] : 0;
    int x = v;
    #pragma unroll
    for (int o = 1; o < 32; o <<= 1) {
        int y = __shfl_up_sync(0xffffffffu, x, o);
        if (lane >= o) x += y;
    }
    if (lane == 31) wsum[warp] = x;
    __syncthreads();
    if (warp == 0) {
        int w = wsum[lane];
        #pragma unroll
        for (int o = 1; o < 32; o <<= 1) {
            int y = __shfl_up_sync(0xffffffffu, w, o);
            if (lane >= o) w += y;
        }
        wsum[lane] = w;
    }
    __syncthreads();
    int incl = x + (warp > 0 ? wsum[warp - 1] : 0);
    if (i < N) g_rowptr[i + 1] = incl;
    if (threadIdx.x == 1023) g_bsum[blockIdx.x] = incl;
}
__global__ void scanB_kernel(int B) {
    if (threadIdx.x == 0) {
        int acc = 0;
        for (int b = 0; b < B; b++) { int v = g_bsum[b]; g_boff[b] = acc; acc += v; }
    }
}
__global__ __launch_bounds__(1024) void scanC_kernel(int N) {
    int i = blockIdx.x * 1024 + threadIdx.x;
    if (i == 0) g_rowptr[0] = 0;
    if (i < N) {
        int r = g_rowptr[i + 1] + g_boff[blockIdx.x];
        g_rowptr[i + 1] = r;
        g_cur[i] = r - g_deg[i];
    }
}
__global__ void scatter_kernel(const void* __restrict__ ei, long long E) {
    long long e = (long long)blockIdx.x * blockDim.x + threadIdx.x;
    if (e >= E) return;
    int is64 = g_is64;
    int src = ld_idx(ei, e, is64);
    int dst = ld_idx(ei, E + e, is64);
    int pos = atomicAdd(&g_cur[dst], 1);
    g_esrc[pos] = src;
}

// ---------------- mma.sync bf16-split triple GEMM ---------------------------
// CTA 128m x 128n x K=256 (16 stages). 8 warps, each 64m x 32n.
// ALL operands bf16 in global (pre-split) -> pure cp.async fills.
#define PADK 24
#define ABUF (128 * PADK)
#define BUFB (ABUF * 2)

__global__ __launch_bounds__(256, 2) void gemm_mma_kernel(
    const float* __restrict__ bias0, const float* __restrict__ bias1,
    const float* __restrict__ bias2,
    float* __restrict__ C0, float* __restrict__ C1, float* __restrict__ C2,
    int M)
{
    __shared__ __nv_bfloat16 sAh[2][ABUF];
    __shared__ __nv_bfloat16 sAl[2][ABUF];
    __shared__ __nv_bfloat16 sBh[2][ABUF];
    __shared__ __nv_bfloat16 sBl[2][ABUF];

    const int sel = blockIdx.x >> 1;
    const int n0  = (blockIdx.x & 1) * 128;
    const int m0  = blockIdx.y * 128;
    const float* bias = (sel == 0) ? bias0 : (sel == 1) ? bias1 : bias2;
    float*       C    = (sel == 0) ? C0 : (sel == 1) ? C1 : C2;
    const __nv_bfloat16* BTh = g_BT_hi + sel * 65536 + (long long)n0 * 256;
    const __nv_bfloat16* BTl = g_BT_lo + sel * 65536 + (long long)n0 * 256;

    const int tid  = threadIdx.x;
    const int lane = tid & 31;
    const int wid  = tid >> 5;
    const int wm0  = (wid >> 2) * 64;
    const int wn0  = (wid & 3) * 32;

    // fill mapping: thread t -> row ar (0..127), k-half ak (0 or 8)
    const int ar = tid >> 1;
    const int ak = (tid & 1) * 8;
    const __nv_bfloat16* gAh = g_AT_hi + (long long)(m0 + ar) * 256 + ak;
    const __nv_bfloat16* gAl = g_AT_lo + (long long)(m0 + ar) * 256 + ak;
    const __nv_bfloat16* gBh = BTh + (long long)ar * 256 + ak;
    const __nv_bfloat16* gBl = BTl + (long long)ar * 256 + ak;
    const uint32_t dAh0 = smem_u32(&sAh[0][ar * PADK + ak]);
    const uint32_t dAl0 = smem_u32(&sAl[0][ar * PADK + ak]);
    const uint32_t dBh0 = smem_u32(&sBh[0][ar * PADK + ak]);
    const uint32_t dBl0 = smem_u32(&sBl[0][ar * PADK + ak]);

    uint32_t a_h[4], a_l[4], b_h[2], b_l[2];
    {
        int arow = lane & 15;
        int acol = (lane >> 4) * 8;
        #pragma unroll
        for (int fm = 0; fm < 4; fm++) {
            int idx = (wm0 + fm * 16 + arow) * PADK + acol;
            a_h[fm] = smem_u32(&sAh[0][idx]);
            a_l[fm] = smem_u32(&sAl[0][idx]);
        }
        int brow = (lane & 7) + (lane >> 4) * 8;
        int bcol = ((lane >> 3) & 1) * 8;
        #pragma unroll
        for (int nb = 0; nb < 2; nb++) {
            int idx = (wn0 + nb * 16 + brow) * PADK + bcol;
            b_h[nb] = smem_u32(&sBh[0][idx]);
            b_l[nb] = smem_u32(&sBl[0][idx]);
        }
    }

    float acc[16][4];
    #pragma unroll
    for (int i = 0; i < 16; i++)
        #pragma unroll
        for (int j = 0; j < 4; j++) acc[i][j] = 0.f;

    // prologue: stage 0 into buffer 0 (pure cp.async)
    cp_async16(dAh0, gAh);
    cp_async16(dAl0, gAl);
    cp_async16(dBh0, gBh);
    cp_async16(dBl0, gBl);
    CP_COMMIT();
    CP_WAIT0();
    __syncthreads();

    int buf = 0;
    for (int ks = 0; ks < 256; ks += 16) {
        const int nb = buf ^ 1;
        const bool has_next = (ks + 16) < 256;
        if (has_next) {
            const uint32_t no = nb * BUFB;
            cp_async16(dAh0 + no, gAh + ks + 16);
            cp_async16(dAl0 + no, gAl + ks + 16);
            cp_async16(dBh0 + no, gBh + ks + 16);
            cp_async16(dBl0 + no, gBl + ks + 16);
            CP_COMMIT();
        }
        const uint32_t bofs = buf * BUFB;
        uint32_t Af[4][4], Bf[2][4];
        // term 1: Ah x Bh
        #pragma unroll
        for (int fm = 0; fm < 4; fm++) ldsm_x4(Af[fm], a_h[fm] + bofs);
        ldsm_x4(Bf[0], b_h[0] + bofs);
        ldsm_x4(Bf[1], b_h[1] + bofs);
        #pragma unroll
        for (int fm = 0; fm < 4; fm++)
            #pragma unroll
            for (int fn = 0; fn < 4; fn++)
                mma_bf16(acc[fm * 4 + fn], Af[fm],
                         Bf[fn >> 1][(fn & 1) * 2], Bf[fn >> 1][(fn & 1) * 2 + 1]);
        // term 2: Ah x Bl (Ah fragments still live)
        ldsm_x4(Bf[0], b_l[0] + bofs);
        ldsm_x4(Bf[1], b_l[1] + bofs);
        #pragma unroll
        for (int fm = 0; fm < 4; fm++)
            #pragma unroll
            for (int fn = 0; fn < 4; fn++)
                mma_bf16(acc[fm * 4 + fn], Af[fm],
                         Bf[fn >> 1][(fn & 1) * 2], Bf[fn >> 1][(fn & 1) * 2 + 1]);
        // term 3: Al x Bh
        #pragma unroll
        for (int fm = 0; fm < 4; fm++) ldsm_x4(Af[fm], a_l[fm] + bofs);
        ldsm_x4(Bf[0], b_h[0] + bofs);
        ldsm_x4(Bf[1], b_h[1] + bofs);
        #pragma unroll
        for (int fm = 0; fm < 4; fm++)
            #pragma unroll
            for (int fn = 0; fn < 4; fn++)
                mma_bf16(acc[fm * 4 + fn], Af[fm],
                         Bf[fn >> 1][(fn & 1) * 2], Bf[fn >> 1][(fn & 1) * 2 + 1]);
        if (has_next) CP_WAIT0();
        __syncthreads();
        buf = nb;
    }

    #pragma unroll
    for (int fm = 0; fm < 4; fm++) {
        int r0 = m0 + wm0 + fm * 16 + (lane >> 2);
        #pragma unroll
        for (int fn = 0; fn < 4; fn++) {
            int col = n0 + wn0 + fn * 8 + (lane & 3) * 2;
            float2 bv = *(const float2*)(bias + col);
            float* a4 = acc[fm * 4 + fn];
            if (r0 < M) {
                float2 o = make_float2(a4[0] + bv.x, a4[1] + bv.y);
                *(float2*)(C + (long long)r0 * 256 + col) = o;
            }
            int r1 = r0 + 8;
            if (r1 < M) {
                float2 o = make_float2(a4[2] + bv.x, a4[3] + bv.y);
                *(float2*)(C + (long long)r1 * 256 + col) = o;
            }
        }
    }
}

// ------- fused conv1 CSR + softmax + skip + LN + ELU + conv2 projection ----
__global__ __launch_bounds__(256) void conv1_csr_kernel(
    const float* __restrict__ att1, const float* __restrict__ bias1,
    const float* __restrict__ gamma, const float* __restrict__ beta,
    const float* __restrict__ W2l, const float* __restrict__ b2l,
    const float* __restrict__ W2r, const float* __restrict__ b2r,
    const float* __restrict__ att2, int N)
{
    const int n = blockIdx.x * 8 + (threadIdx.x >> 5);
    const int lane = threadIdx.x & 31;
    if (n >= N) return;

    float att6[8], att4[8];
    {
        float4 a0 = *(const float4*)(att1 + lane * 8);
        float4 a1 = *(const float4*)(att1 + lane * 8 + 4);
        float av[8] = {a0.x,a0.y,a0.z,a0.w,a1.x,a1.y,a1.z,a1.w};
        #pragma unroll
        for (int j = 0; j < 8; j++) { att6[j] = 0.6f * av[j]; att4[j] = 0.4f * av[j]; }
    }
    float xr[8];
    {
        const float* p = g_XR1 + (long long)n * HCc + lane * 8;
        float4 r0 = *(const float4*)p;
        float4 r1 = *(const float4*)(p + 4);
        xr[0]=r0.x; xr[1]=r0.y; xr[2]=r0.z; xr[3]=r0.w;
        xr[4]=r1.x; xr[5]=r1.y; xr[6]=r1.z; xr[7]=r1.w;
    }

    float acc[8], den;
    {
        const float* p = g_XL1 + (long long)n * HCc + lane * 8;
        float4 l0 = *(const float4*)p;
        float4 l1 = *(const float4*)(p + 4);
        float xl[8] = {l0.x,l0.y,l0.z,l0.w,l1.x,l1.y,l1.z,l1.w};
        float s6 = 0.f, s4 = 0.f;
        #pragma unroll
        for (int j = 0; j < 8; j++) {
            float e = xl[j] + xr[j];
            s6 = fmaf(e, att6[j], s6);
            s4 = fmaf(fabsf(e), att4[j], s4);
        }
        float s = s6 + s4;
        s += __shfl_xor_sync(0xffffffffu, s, 1);
        s += __shfl_xor_sync(0xffffffffu, s, 2);
        s += __shfl_xor_sync(0xffffffffu, s, 4);
        float ex = __expf(s);
        den = ex;
        #pragma unroll
        for (int j = 0; j < 8; j++) acc[j] = ex * xl[j];
    }

    const int row0 = g_rowptr[n];
    const int row1 = g_rowptr[n + 1];
    int i = row0;
    for (; i + 1 < row1; i += 2) {
        int srcA = g_esrc[i];
        int srcB = g_esrc[i + 1];
        const float* pA = g_XL1 + (long long)srcA * HCc + lane * 8;
        const float* pB = g_XL1 + (long long)srcB * HCc + lane * 8;
        float4 a0 = *(const float4*)pA;
        float4 a1 = *(const float4*)(pA + 4);
        float4 b0 = *(const float4*)pB;
        float4 b1 = *(const float4*)(pB + 4);
        float xlA[8] = {a0.x,a0.y,a0.z,a0.w,a1.x,a1.y,a1.z,a1.w};
        float xlB[8] = {b0.x,b0.y,b0.z,b0.w,b1.x,b1.y,b1.z,b1.w};
        float sA6 = 0.f, sA4 = 0.f, sB6 = 0.f, sB4 = 0.f;
        #pragma unroll
        for (int j = 0; j < 8; j++) {
            float eA = xlA[j] + xr[j];
            float eB = xlB[j] + xr[j];
            sA6 = fmaf(eA, att6[j], sA6);
            sA4 = fmaf(fabsf(eA), att4[j], sA4);
            sB6 = fmaf(eB, att6[j], sB6);
            sB4 = fmaf(fabsf(eB), att4[j], sB4);
        }
        float sA = sA6 + sA4, sB = sB6 + sB4;
        #pragma unroll
        for (int o = 1; o <= 4; o <<= 1) {
            sA += __shfl_xor_sync(0xffffffffu, sA, o);
            sB += __shfl_xor_sync(0xffffffffu, sB, o);
        }
        float exA = __expf(sA);
        float exB = __expf(sB);
        den += exA + exB;
        #pragma unroll
        for (int j = 0; j < 8; j++) {
            acc[j] = fmaf(exA, xlA[j], acc[j]);
            acc[j] = fmaf(exB, xlB[j], acc[j]);
        }
    }
    if (i < row1) {
        int src = g_esrc[i];
        const float* p = g_XL1 + (long long)src * HCc + lane * 8;
        float4 l0 = *(const float4*)p;
        float4 l1 = *(const float4*)(p + 4);
        float xl[8] = {l0.x,l0.y,l0.z,l0.w,l1.x,l1.y,l1.z,l1.w};
        float s6 = 0.f, s4 = 0.f;
        #pragma unroll
        for (int j = 0; j < 8; j++) {
            float e = xl[j] + xr[j];
            s6 = fmaf(e, att6[j], s6);
            s4 = fmaf(fabsf(e), att4[j], s4);
        }
        float s = s6 + s4;
        s += __shfl_xor_sync(0xffffffffu, s, 1);
        s += __shfl_xor_sync(0xffffffffu, s, 2);
        s += __shfl_xor_sync(0xffffffffu, s, 4);
        float ex = __expf(s);
        den += ex;
        #pragma unroll
        for (int j = 0; j < 8; j++) acc[j] = fmaf(ex, xl[j], acc[j]);
    }

    const float dinv = 1.0f / den;
    float v[8];
    {
        const float* sp = g_SKIP + (long long)n * HCc + lane * 8;
        float4 s0 = *(const float4*)sp;
        float4 s1 = *(const float4*)(sp + 4);
        float4 b0 = *(const float4*)(bias1 + lane * 8);
        float4 b1 = *(const float4*)(bias1 + lane * 8 + 4);
        float sk[8] = {s0.x,s0.y,s0.z,s0.w,s1.x,s1.y,s1.z,s1.w};
        float bb[8] = {b0.x,b0.y,b0.z,b0.w,b1.x,b1.y,b1.z,b1.w};
        #pragma unroll
        for (int j = 0; j < 8; j++) v[j] = acc[j] * dinv + bb[j] + sk[j];
    }

    float t = 0.f;
    #pragma unroll
    for (int j = 0; j < 8; j++) t += v[j];
    #pragma unroll
    for (int o = 16; o > 0; o >>= 1) t += __shfl_xor_sync(0xffffffffu, t, o);
    const float mu = t * (1.0f / 256.0f);
    float t2 = 0.f;
    #pragma unroll
    for (int j = 0; j < 8; j++) { float d = v[j] - mu; t2 = fmaf(d, d, t2); }
    #pragma unroll
    for (int o = 16; o > 0; o >>= 1) t2 += __shfl_xor_sync(0xffffffffu, t2, o);
    const float rstd = rsqrtf(t2 * (1.0f / 256.0f) + 1e-5f);

    float h[8];
    {
        float4 g0 = *(const float4*)(gamma + lane * 8);
        float4 g1 = *(const float4*)(gamma + lane * 8 + 4);
        float4 e0 = *(const float4*)(beta + lane * 8);
        float4 e1 = *(const float4*)(beta + lane * 8 + 4);
        float gg[8] = {g0.x,g0.y,g0.z,g0.w,g1.x,g1.y,g1.z,g1.w};
        float be[8] = {e0.x,e0.y,e0.z,e0.w,e1.x,e1.y,e1.z,e1.w};
        #pragma unroll
        for (int j = 0; j < 8; j++) {
            float hh = (v[j] - mu) * rstd * gg[j] + be[j];
            h[j] = hh > 0.f ? hh : expm1f(hh);
        }
    }

    float p0 = 0.f, p1 = 0.f, p2 = 0.f, p3 = 0.f;
    {
        const float* wl = W2l + lane * 16;
        const float* wr = W2r + lane * 16;
        float4 wl0 = *(const float4*)wl;
        float4 wl1 = *(const float4*)(wl + 4);
        float4 wl2 = *(const float4*)(wl + 8);
        float4 wl3 = *(const float4*)(wl + 12);
        float4 wr0 = *(const float4*)wr;
        float4 wr1 = *(const float4*)(wr + 4);
        float4 wr2 = *(const float4*)(wr + 8);
        float4 wr3 = *(const float4*)(wr + 12);
        float wlv[16] = {wl0.x,wl0.y,wl0.z,wl0.w, wl1.x,wl1.y,wl1.z,wl1.w,
                         wl2.x,wl2.y,wl2.z,wl2.w, wl3.x,wl3.y,wl3.z,wl3.w};
        float wrv[16] = {wr0.x,wr0.y,wr0.z,wr0.w, wr1.x,wr1.y,wr1.z,wr1.w,
                         wr2.x,wr2.y,wr2.z,wr2.w, wr3.x,wr3.y,wr3.z,wr3.w};
        #pragma unroll
        for (int j = 0; j < 8; j++) {
            p0 = fmaf(h[j], wlv[2 * j + 0], p0);
            p1 = fmaf(h[j], wlv[2 * j + 1], p1);
            p2 = fmaf(h[j], wrv[2 * j + 0], p2);
            p3 = fmaf(h[j], wrv[2 * j + 1], p3);
        }
    }
    #pragma unroll
    for (int o = 16; o > 0; o >>= 1) {
        p0 += __shfl_xor_sync(0xffffffffu, p0, o);
        p1 += __shfl_xor_sync(0xffffffffu, p1, o);
        p2 += __shfl_xor_sync(0xffffffffu, p2, o);
        p3 += __shfl_xor_sync(0xffffffffu, p3, o);
    }
    if (lane == 0) {
        float2 xl2, xr2;
        xl2.x = p0 + b2l[0]; xl2.y = p1 + b2l[1];
        xr2.x = p2 + b2r[0]; xr2.y = p3 + b2r[1];
        *(float2*)&g_XL2[n * 2] = xl2;
        *(float2*)&g_XR2[n * 2] = xr2;
    }
}

// ------------- conv2 CSR + final output (warp per node) --------------------
__global__ __launch_bounds__(256) void conv2_csr_kernel(
    const float* __restrict__ att2, const float* __restrict__ bias2,
    float* __restrict__ out, int N)
{
    const int n = blockIdx.x * 8 + (threadIdx.x >> 5);
    const int lane = threadIdx.x & 31;
    if (n >= N) return;
    const float a0 = att2[0], a1 = att2[1];
    const float a06 = 0.6f * a0, a04 = 0.4f * a0;
    const float a16 = 0.6f * a1, a14 = 0.4f * a1;
    float2 xls = *(const float2*)&g_XL2[n * 2];
    float2 xr  = *(const float2*)&g_XR2[n * 2];

    float den = 0.f, s0 = 0.f, s1 = 0.f;
    const int row0 = g_rowptr[n], row1 = g_rowptr[n + 1];
    for (int i = row0 + lane; i < row1; i += 32) {
        int src = g_esrc[i];
        float2 xl = *(const float2*)&g_XL2[src * 2];
        float f0 = xl.x + xr.x;
        float f1 = xl.y + xr.y;
        float s = fmaf(f0, a06, fmaf(fabsf(f0), a04,
                  fmaf(f1, a16, fabsf(f1) * a14)));
        float exi = __expf(s);
        den += exi;
        s0 = fmaf(exi, xl.x, s0);
        s1 = fmaf(exi, xl.y, s1);
    }
    #pragma unroll
    for (int o = 16; o > 0; o >>= 1) {
        den += __shfl_xor_sync(0xffffffffu, den, o);
        s0  += __shfl_xor_sync(0xffffffffu, s0, o);
        s1  += __shfl_xor_sync(0xffffffffu, s1, o);
    }
    if (lane == 0) {
        float f0 = xls.x + xr.x;
        float f1 = xls.y + xr.y;
        float s = fmaf(f0, a06, fmaf(fabsf(f0), a04,
                  fmaf(f1, a16, fabsf(f1) * a14)));
        float ex = __expf(s);
        den += ex;
        s0 = fmaf(ex, xls.x, s0);
        s1 = fmaf(ex, xls.y, s1);
        float dinv = 1.0f / den;
        float2 o;
        o.x = s0 * dinv + bias2[0];
        o.y = s1 * dinv + bias2[1];
        *(float2*)(out + n * 2) = o;
    }
}

// ---------------------------------------------------------------------------
extern "C" void kernel_launch(void* const* d_in, const int* in_sizes, int n_in,
                              void* d_out, int out_size) {
    const float* x     = (const float*)d_in[0];
    const void*  ei    = d_in[1];
    const float* W1l   = (const float*)d_in[2];
    const float* b1l   = (const float*)d_in[3];
    const float* W1r   = (const float*)d_in[4];
    const float* b1r   = (const float*)d_in[5];
    const float* att1  = (const float*)d_in[6];
    const float* bias1 = (const float*)d_in[7];
    const float* W2l   = (const float*)d_in[8];
    const float* b2l   = (const float*)d_in[9];
    const float* W2r   = (const float*)d_in[10];
    const float* b2r   = (const float*)d_in[11];
    const float* att2  = (const float*)d_in[12];
    const float* bias2 = (const float*)d_in[13];
    const float* Wskip = (const float*)d_in[14];
    const float* bskip = (const float*)d_in[15];
    const float* gamma = (const float*)d_in[16];
    const float* beta  = (const float*)d_in[17];
    float* out = (float*)d_out;

    const int       N = in_sizes[0] / DIN;            // 50000
    const long long E = (long long)in_sizes[1] / 2;   // 800000

    float *dXL1, *dXR1, *dSKIP;
    cudaGetSymbolAddress((void**)&dXL1, g_XL1);
    cudaGetSymbolAddress((void**)&dXR1, g_XR1);
    cudaGetSymbolAddress((void**)&dSKIP, g_SKIP);

    // launch order: gemm at my-launch index 3 (= ncu capture slot)
    detect_idx_kernel<<<1, 1>>>((const unsigned int*)ei);                 // 0
    {
        int ablocks = (int)(((long long)N * 256 + 1023) / 1024);
        prep_ab_kernel<<<768 + ablocks, 256>>>(x, W1l, W1r, Wskip, N);    // 1
    }
    zero_deg_kernel<<<(N + 255) / 256, 256>>>(N);                          // 2
    {
        dim3 g(6, (N + 127) / 128);
        gemm_mma_kernel<<<g, 256>>>(b1l, b1r, bskip, dXL1, dXR1, dSKIP, N); // 3
    }
    const int SB = (N + 1023) / 1024;
    hist_kernel<<<(int)((E + 255) / 256), 256>>>(ei, E);                   // 4
    scanA_kernel<<<SB, 1024>>>(N);                                         // 5
    scanB_kernel<<<1, 32>>>(SB);                                           // 6
    scanC_kernel<<<SB, 1024>>>(N);                                         // 7
    scatter_kernel<<<(int)((E + 255) / 256), 256>>>(ei, E);                // 8

    conv1_csr_kernel<<<(N + 7) / 8, 256>>>(att1, bias1, gamma, beta,
                                           W2l, b2l, W2r, b2r, att2, N);   // 9
    conv2_csr_kernel<<<(N + 7) / 8, 256>>>(att2, bias2, out, N);           // 10
}

// round 12
// speedup vs baseline: 1.0858x; 1.0208x over previous
#include <cuda_runtime.h>
#include <cuda_bf16.h>
#include <math.h>
#include <stdint.h>

// Problem constants
#define DIN   256
#define HCc   256
#define NEG   0.2f
#define MAXN  50000
#define MAXE  1000000
#define MPAD  (MAXN + 128)

// ---------------- scratch (static device globals) --------------------------
__device__ float g_XL1[(long long)MAXN * HCc];
__device__ float g_XR1[(long long)MAXN * HCc];
__device__ float g_SKIP[(long long)MAXN * HCc];
__device__ float g_XL2[MAXN * 2];
__device__ float g_XR2[MAXN * 2];
__device__ int   g_deg[MAXN];
__device__ int   g_rowptr[MAXN + 1];
__device__ int   g_cur[MAXN];
__device__ int   g_esrc[MAXE];
__device__ int   g_bsum[64];
__device__ int   g_boff[64];
__device__ int   g_is64;
// split-bf16 transposed weights: [sel][N=256][K=256]
__device__ __nv_bfloat16 g_BT_hi[3 * 256 * 256];
__device__ __nv_bfloat16 g_BT_lo[3 * 256 * 256];
// split-bf16 A (x): [m][k], padded rows so OOB tile reads stay in-bounds
__device__ __nv_bfloat16 g_AT_hi[(long long)MPAD * 256];
__device__ __nv_bfloat16 g_AT_lo[(long long)MPAD * 256];

// ---------------- small helpers ---------------------------------------------
__device__ __forceinline__ uint32_t smem_u32(const void* p) {
    uint32_t a;
    asm("{ .reg .u64 t; cvta.to.shared.u64 t, %1; cvt.u32.u64 %0, t; }"
        : "=r"(a) : "l"(p));
    return a;
}
__device__ __forceinline__ void ldsm_x4(uint32_t* r, uint32_t addr) {
    asm volatile("ldmatrix.sync.aligned.m8n8.x4.shared.b16 {%0,%1,%2,%3}, [%4];"
        : "=r"(r[0]), "=r"(r[1]), "=r"(r[2]), "=r"(r[3]) : "r"(addr));
}
__device__ __forceinline__ void mma_bf16(float* c, const uint32_t* a,
                                         uint32_t b0, uint32_t b1) {
    asm volatile(
        "mma.sync.aligned.m16n8k16.row.col.f32.bf16.bf16.f32 "
        "{%0,%1,%2,%3}, {%4,%5,%6,%7}, {%8,%9}, {%0,%1,%2,%3};"
        : "+f"(c[0]), "+f"(c[1]), "+f"(c[2]), "+f"(c[3])
        : "r"(a[0]), "r"(a[1]), "r"(a[2]), "r"(a[3]), "r"(b0), "r"(b1));
}
__device__ __forceinline__ void cp_async16(uint32_t dst, const void* src) {
    asm volatile("cp.async.ca.shared.global [%0], [%1], 16;"
                 :: "r"(dst), "l"(src) : "memory");
}
#define CP_COMMIT() asm volatile("cp.async.commit_group;" ::: "memory")
#define CP_WAIT0()  asm volatile("cp.async.wait_group 0;" ::: "memory")

__device__ __forceinline__ int ld_idx(const void* ei, long long pos, int is64) {
    if (is64) return (int)(((const long long*)ei)[pos]);
    return ((const int*)ei)[pos];
}

// ---------------- fused init: zero deg + edge dtype detect ------------------
__global__ void init_kernel(const unsigned int* __restrict__ w, int N) {
    int i = blockIdx.x * blockDim.x + threadIdx.x;
    if (i < N) g_deg[i] = 0;
    if (i == 0) {
        int ok = 1;
        #pragma unroll
        for (int j = 0; j < 32; j++) {
            if (w[2 * j + 1] != 0u) { ok = 0; break; }
        }
        g_is64 = ok;
    }
}

// ---------------- fused prep: B transpose+split AND A split -----------------
__global__ void prep_ab_kernel(const float* __restrict__ x,
                               const float* __restrict__ W0,
                               const float* __restrict__ W1,
                               const float* __restrict__ W2, int N) {
    int b = blockIdx.x;
    if (b < 768) {
        int s = b >> 8, k = b & 255, n = threadIdx.x;
        const float* W = (s == 0) ? W0 : (s == 1) ? W1 : W2;
        float v = W[k * 256 + n];
        __nv_bfloat16 hi = __float2bfloat16(v);
        float lo = v - __bfloat162float(hi);
        int idx = (s * 256 + n) * 256 + k;
        g_BT_hi[idx] = hi;
        g_BT_lo[idx] = __float2bfloat16(lo);
    } else {
        long long eb = (long long)(b - 768) * 1024 + threadIdx.x * 4;
        if (eb < (long long)N * 256) {
            float4 v = *(const float4*)(x + eb);
            float f[4] = {v.x, v.y, v.z, v.w};
            __nv_bfloat16 h[4], l[4];
            #pragma unroll
            for (int j = 0; j < 4; j++) {
                h[j] = __float2bfloat16(f[j]);
                l[j] = __float2bfloat16(f[j] - __bfloat162float(h[j]));
            }
            *(ulonglong1*)(g_AT_hi + eb) = *(ulonglong1*)h;
            *(ulonglong1*)(g_AT_lo + eb) = *(ulonglong1*)l;
        }
    }
}

// ---------------- CSR build -------------------------------------------------
__global__ void hist_kernel(const void* __restrict__ ei, long long E) {
    long long e = (long long)blockIdx.x * blockDim.x + threadIdx.x;
    if (e >= E) return;
    int dst = ld_idx(ei, E + e, g_is64);
    atomicAdd(&g_deg[dst], 1);
}
__global__ __launch_bounds__(1024) void scanA_kernel(int N) {
    __shared__ int wsum[32];
    const int lane = threadIdx.x & 31, warp = threadIdx.x >> 5;
    int i = blockIdx.x * 1024 + threadIdx.x;
    int v = (i < N) ? g_deg[i] : 0;
    int x = v;
    #pragma unroll
    for (int o = 1; o < 32; o <<= 1) {
        int y = __shfl_up_sync(0xffffffffu, x, o);
        if (lane >= o) x += y;
    }
    if (lane == 31) wsum[warp] = x;
    __syncthreads();
    if (warp == 0) {
        int w = wsum[lane];
        #pragma unroll
        for (int o = 1; o < 32; o <<= 1) {
            int y = __shfl_up_sync(0xffffffffu, w, o);
            if (lane >= o) w += y;
        }
        wsum[lane] = w;
    }
    __syncthreads();
    int incl = x + (warp > 0 ? wsum[warp - 1] : 0);
    if (i < N) g_rowptr[i + 1] = incl;
    if (threadIdx.x == 1023) g_bsum[blockIdx.x] = incl;
}
__global__ void scanB_kernel(int B) {
    if (threadIdx.x == 0) {
        int acc = 0;
        for (int b = 0; b < B; b++) { int v = g_bsum[b]; g_boff[b] = acc; acc += v; }
    }
}
__global__ __launch_bounds__(1024) void scanC_kernel(int N) {
    int i = blockIdx.x * 1024 + threadIdx.x;
    if (i == 0) g_rowptr[0] = 0;
    if (i < N) {
        int r = g_rowptr[i + 1] + g_boff[blockIdx.x];
        g_rowptr[i + 1] = r;
        g_cur[i] = r - g_deg[i];
    }
}
__global__ void scatter_kernel(const void* __restrict__ ei, long long E) {
    long long e = (long long)blockIdx.x * blockDim.x + threadIdx.x;
    if (e >= E) return;
    int is64 = g_is64;
    int src = ld_idx(ei, e, is64);
    int dst = ld_idx(ei, E + e, is64);
    int pos = atomicAdd(&g_cur[dst], 1);
    g_esrc[pos] = src;
}

// ---------------- mma.sync bf16-split triple GEMM ---------------------------
// CTA 128m x 128n x K=256 (16 stages). 8 warps, each 64m x 32n.
// Single smem block: [buf][op: Ah,Al,Bh,Bl][128][PADK]. 12 ldsm/warp/stage
// via Ah-reuse (terms 1&2) and Bh-reuse (terms 1&3).
#define PADK 24
#define ABUF (128 * PADK)           // bf16 elems per operand block
#define OPB  (ABUF * 2)             // bytes per operand block (6144)
#define BUFB (OPB * 4)              // bytes per buffer (24576)

__global__ __launch_bounds__(256, 2) void gemm_mma_kernel(
    const float* __restrict__ bias0, const float* __restrict__ bias1,
    const float* __restrict__ bias2,
    float* __restrict__ C0, float* __restrict__ C1, float* __restrict__ C2,
    int M)
{
    __shared__ __nv_bfloat16 sm[2 * 4 * ABUF];   // 48KB

    const int sel = blockIdx.x >> 1;
    const int n0  = (blockIdx.x & 1) * 128;
    const int m0  = blockIdx.y * 128;
    const float* bias = (sel == 0) ? bias0 : (sel == 1) ? bias1 : bias2;
    float*       C    = (sel == 0) ? C0 : (sel == 1) ? C1 : C2;
    const __nv_bfloat16* BTh = g_BT_hi + sel * 65536 + (long long)n0 * 256;
    const __nv_bfloat16* BTl = g_BT_lo + sel * 65536 + (long long)n0 * 256;

    const int tid  = threadIdx.x;
    const int lane = tid & 31;
    const int wid  = tid >> 5;
    const int wm0  = (wid >> 2) * 64;
    const int wn0  = (wid & 3) * 32;

    // fill mapping: thread t -> row ar (0..127), k-half ak (0 or 8)
    const int ar = tid >> 1;
    const int ak = (tid & 1) * 8;
    const __nv_bfloat16* gAh = g_AT_hi + (long long)(m0 + ar) * 256 + ak;
    const __nv_bfloat16* gAl = g_AT_lo + (long long)(m0 + ar) * 256 + ak;
    const __nv_bfloat16* gBh = BTh + (long long)ar * 256 + ak;
    const __nv_bfloat16* gBl = BTl + (long long)ar * 256 + ak;
    const uint32_t dFill = smem_u32(&sm[ar * PADK + ak]);  // op0 buf0 base

    // ldsm lane addresses for buf0: A at op0 (Al = +OPB), B at op2 (Bl = +OPB)
    uint32_t a_h[4], b_h[2];
    {
        int arow = lane & 15;
        int acol = (lane >> 4) * 8;
        #pragma unroll
        for (int fm = 0; fm < 4; fm++)
            a_h[fm] = smem_u32(&sm[(wm0 + fm * 16 + arow) * PADK + acol]);
        int brow = (lane & 7) + (lane >> 4) * 8;
        int bcol = ((lane >> 3) & 1) * 8;
        #pragma unroll
        for (int nb = 0; nb < 2; nb++)
            b_h[nb] = smem_u32(&sm[2 * ABUF + (wn0 + nb * 16 + brow) * PADK + bcol]);
    }

    float acc[16][4];
    #pragma unroll
    for (int i = 0; i < 16; i++)
        #pragma unroll
        for (int j = 0; j < 4; j++) acc[i][j] = 0.f;

    // prologue: stage 0 into buffer 0
    cp_async16(dFill,            gAh);
    cp_async16(dFill + OPB,      gAl);
    cp_async16(dFill + 2 * OPB,  gBh);
    cp_async16(dFill + 3 * OPB,  gBl);
    CP_COMMIT();
    CP_WAIT0();
    __syncthreads();

    int buf = 0;
    for (int ks = 0; ks < 256; ks += 16) {
        const int nb = buf ^ 1;
        const bool has_next = (ks + 16) < 256;
        if (has_next) {
            const uint32_t d = dFill + nb * BUFB;
            cp_async16(d,           gAh + ks + 16);
            cp_async16(d + OPB,     gAl + ks + 16);
            cp_async16(d + 2 * OPB, gBh + ks + 16);
            cp_async16(d + 3 * OPB, gBl + ks + 16);
            CP_COMMIT();
        }
        const uint32_t bofs = buf * BUFB;
        uint32_t AF[4][4], BhF[2][4], BlF[2][4];
        // load Ah + Bh
        #pragma unroll
        for (int fm = 0; fm < 4; fm++) ldsm_x4(AF[fm], a_h[fm] + bofs);
        ldsm_x4(BhF[0], b_h[0] + bofs);
        ldsm_x4(BhF[1], b_h[1] + bofs);
        // term 1: Ah x Bh
        #pragma unroll
        for (int fm = 0; fm < 4; fm++)
            #pragma unroll
            for (int fn = 0; fn < 4; fn++)
                mma_bf16(acc[fm * 4 + fn], AF[fm],
                         BhF[fn >> 1][(fn & 1) * 2], BhF[fn >> 1][(fn & 1) * 2 + 1]);
        // load Bl; term 2: Ah x Bl (Ah reused)
        ldsm_x4(BlF[0], b_h[0] + bofs + OPB);
        ldsm_x4(BlF[1], b_h[1] + bofs + OPB);
        #pragma unroll
        for (int fm = 0; fm < 4; fm++)
            #pragma unroll
            for (int fn = 0; fn < 4; fn++)
                mma_bf16(acc[fm * 4 + fn], AF[fm],
                         BlF[fn >> 1][(fn & 1) * 2], BlF[fn >> 1][(fn & 1) * 2 + 1]);
        // load Al over Ah; term 3: Al x Bh (Bh reused)
        #pragma unroll
        for (int fm = 0; fm < 4; fm++) ldsm_x4(AF[fm], a_h[fm] + bofs + OPB);
        #pragma unroll
        for (int fm = 0; fm < 4; fm++)
            #pragma unroll
            for (int fn = 0; fn < 4; fn++)
                mma_bf16(acc[fm * 4 + fn], AF[fm],
                         BhF[fn >> 1][(fn & 1) * 2], BhF[fn >> 1][(fn & 1) * 2 + 1]);
        if (has_next) CP_WAIT0();
        __syncthreads();
        buf = nb;
    }

    #pragma unroll
    for (int fm = 0; fm < 4; fm++) {
        int r0 = m0 + wm0 + fm * 16 + (lane >> 2);
        #pragma unroll
        for (int fn = 0; fn < 4; fn++) {
            int col = n0 + wn0 + fn * 8 + (lane & 3) * 2;
            float2 bv = *(const float2*)(bias + col);
            float* a4 = acc[fm * 4 + fn];
            if (r0 < M) {
                float2 o = make_float2(a4[0] + bv.x, a4[1] + bv.y);
                *(float2*)(C + (long long)r0 * 256 + col) = o;
            }
            int r1 = r0 + 8;
            if (r1 < M) {
                float2 o = make_float2(a4[2] + bv.x, a4[3] + bv.y);
                *(float2*)(C + (long long)r1 * 256 + col) = o;
            }
        }
    }
}

// ------- fused conv1 CSR + softmax + skip + LN + ELU + conv2 projection ----
__global__ __launch_bounds__(256) void conv1_csr_kernel(
    const float* __restrict__ att1, const float* __restrict__ bias1,
    const float* __restrict__ gamma, const float* __restrict__ beta,
    const float* __restrict__ W2l, const float* __restrict__ b2l,
    const float* __restrict__ W2r, const float* __restrict__ b2r,
    const float* __restrict__ att2, int N)
{
    const int n = blockIdx.x * 8 + (threadIdx.x >> 5);
    const int lane = threadIdx.x & 31;
    if (n >= N) return;

    float att6[8], att4[8];
    {
        float4 a0 = *(const float4*)(att1 + lane * 8);
        float4 a1 = *(const float4*)(att1 + lane * 8 + 4);
        float av[8] = {a0.x,a0.y,a0.z,a0.w,a1.x,a1.y,a1.z,a1.w};
        #pragma unroll
        for (int j = 0; j < 8; j++) { att6[j] = 0.6f * av[j]; att4[j] = 0.4f * av[j]; }
    }
    float xr[8];
    {
        const float* p = g_XR1 + (long long)n * HCc + lane * 8;
        float4 r0 = *(const float4*)p;
        float4 r1 = *(const float4*)(p + 4);
        xr[0]=r0.x; xr[1]=r0.y; xr[2]=r0.z; xr[3]=r0.w;
        xr[4]=r1.x; xr[5]=r1.y; xr[6]=r1.z; xr[7]=r1.w;
    }

    float acc[8], den;
    {
        const float* p = g_XL1 + (long long)n * HCc + lane * 8;
        float4 l0 = *(const float4*)p;
        float4 l1 = *(const float4*)(p + 4);
        float xl[8] = {l0.x,l0.y,l0.z,l0.w,l1.x,l1.y,l1.z,l1.w};
        float s6 = 0.f, s4 = 0.f;
        #pragma unroll
        for (int j = 0; j < 8; j++) {
            float e = xl[j] + xr[j];
            s6 = fmaf(e, att6[j], s6);
            s4 = fmaf(fabsf(e), att4[j], s4);
        }
        float s = s6 + s4;
        s += __shfl_xor_sync(0xffffffffu, s, 1);
        s += __shfl_xor_sync(0xffffffffu, s, 2);
        s += __shfl_xor_sync(0xffffffffu, s, 4);
        float ex = __expf(s);
        den = ex;
        #pragma unroll
        for (int j = 0; j < 8; j++) acc[j] = ex * xl[j];
    }

    const int row0 = g_rowptr[n];
    const int row1 = g_rowptr[n + 1];
    int i = row0;
    for (; i + 1 < row1; i += 2) {
        int srcA = g_esrc[i];
        int srcB = g_esrc[i + 1];
        const float* pA = g_XL1 + (long long)srcA * HCc + lane * 8;
        const float* pB = g_XL1 + (long long)srcB * HCc + lane * 8;
        float4 a0 = *(const float4*)pA;
        float4 a1 = *(const float4*)(pA + 4);
        float4 b0 = *(const float4*)pB;
        float4 b1 = *(const float4*)(pB + 4);
        float xlA[8] = {a0.x,a0.y,a0.z,a0.w,a1.x,a1.y,a1.z,a1.w};
        float xlB[8] = {b0.x,b0.y,b0.z,b0.w,b1.x,b1.y,b1.z,b1.w};
        float sA6 = 0.f, sA4 = 0.f, sB6 = 0.f, sB4 = 0.f;
        #pragma unroll
        for (int j = 0; j < 8; j++) {
            float eA = xlA[j] + xr[j];
            float eB = xlB[j] + xr[j];
            sA6 = fmaf(eA, att6[j], sA6);
            sA4 = fmaf(fabsf(eA), att4[j], sA4);
            sB6 = fmaf(eB, att6[j], sB6);
            sB4 = fmaf(fabsf(eB), att4[j], sB4);
        }
        float sA = sA6 + sA4, sB = sB6 + sB4;
        #pragma unroll
        for (int o = 1; o <= 4; o <<= 1) {
            sA += __shfl_xor_sync(0xffffffffu, sA, o);
            sB += __shfl_xor_sync(0xffffffffu, sB, o);
        }
        float exA = __expf(sA);
        float exB = __expf(sB);
        den += exA + exB;
        #pragma unroll
        for (int j = 0; j < 8; j++) {
            acc[j] = fmaf(exA, xlA[j], acc[j]);
            acc[j] = fmaf(exB, xlB[j], acc[j]);
        }
    }
    if (i < row1) {
        int src = g_esrc[i];
        const float* p = g_XL1 + (long long)src * HCc + lane * 8;
        float4 l0 = *(const float4*)p;
        float4 l1 = *(const float4*)(p + 4);
        float xl[8] = {l0.x,l0.y,l0.z,l0.w,l1.x,l1.y,l1.z,l1.w};
        float s6 = 0.f, s4 = 0.f;
        #pragma unroll
        for (int j = 0; j < 8; j++) {
            float e = xl[j] + xr[j];
            s6 = fmaf(e, att6[j], s6);
            s4 = fmaf(fabsf(e), att4[j], s4);
        }
        float s = s6 + s4;
        s += __shfl_xor_sync(0xffffffffu, s, 1);
        s += __shfl_xor_sync(0xffffffffu, s, 2);
        s += __shfl_xor_sync(0xffffffffu, s, 4);
        float ex = __expf(s);
        den += ex;
        #pragma unroll
        for (int j = 0; j < 8; j++) acc[j] = fmaf(ex, xl[j], acc[j]);
    }

    const float dinv = 1.0f / den;
    float v[8];
    {
        const float* sp = g_SKIP + (long long)n * HCc + lane * 8;
        float4 s0 = *(const float4*)sp;
        float4 s1 = *(const float4*)(sp + 4);
        float4 b0 = *(const float4*)(bias1 + lane * 8);
        float4 b1 = *(const float4*)(bias1 + lane * 8 + 4);
        float sk[8] = {s0.x,s0.y,s0.z,s0.w,s1.x,s1.y,s1.z,s1.w};
        float bb[8] = {b0.x,b0.y,b0.z,b0.w,b1.x,b1.y,b1.z,b1.w};
        #pragma unroll
        for (int j = 0; j < 8; j++) v[j] = acc[j] * dinv + bb[j] + sk[j];
    }

    float t = 0.f;
    #pragma unroll
    for (int j = 0; j < 8; j++) t += v[j];
    #pragma unroll
    for (int o = 16; o > 0; o >>= 1) t += __shfl_xor_sync(0xffffffffu, t, o);
    const float mu = t * (1.0f / 256.0f);
    float t2 = 0.f;
    #pragma unroll
    for (int j = 0; j < 8; j++) { float d = v[j] - mu; t2 = fmaf(d, d, t2); }
    #pragma unroll
    for (int o = 16; o > 0; o >>= 1) t2 += __shfl_xor_sync(0xffffffffu, t2, o);
    const float rstd = rsqrtf(t2 * (1.0f / 256.0f) + 1e-5f);

    float h[8];
    {
        float4 g0 = *(const float4*)(gamma + lane * 8);
        float4 g1 = *(const float4*)(gamma + lane * 8 + 4);
        float4 e0 = *(const float4*)(beta + lane * 8);
        float4 e1 = *(const float4*)(beta + lane * 8 + 4);
        float gg[8] = {g0.x,g0.y,g0.z,g0.w,g1.x,g1.y,g1.z,g1.w};
        float be[8] = {e0.x,e0.y,e0.z,e0.w,e1.x,e1.y,e1.z,e1.w};
        #pragma unroll
        for (int j = 0; j < 8; j++) {
            float hh = (v[j] - mu) * rstd * gg[j] + be[j];
            h[j] = hh > 0.f ? hh : expm1f(hh);
        }
    }

    float p0 = 0.f, p1 = 0.f, p2 = 0.f, p3 = 0.f;
    {
        const float* wl = W2l + lane * 16;
        const float* wr = W2r + lane * 16;
        float4 wl0 = *(const float4*)wl;
        float4 wl1 = *(const float4*)(wl + 4);
        float4 wl2 = *(const float4*)(wl + 8);
        float4 wl3 = *(const float4*)(wl + 12);
        float4 wr0 = *(const float4*)wr;
        float4 wr1 = *(const float4*)(wr + 4);
        float4 wr2 = *(const float4*)(wr + 8);
        float4 wr3 = *(const float4*)(wr + 12);
        float wlv[16] = {wl0.x,wl0.y,wl0.z,wl0.w, wl1.x,wl1.y,wl1.z,wl1.w,
                         wl2.x,wl2.y,wl2.z,wl2.w, wl3.x,wl3.y,wl3.z,wl3.w};
        float wrv[16] = {wr0.x,wr0.y,wr0.z,wr0.w, wr1.x,wr1.y,wr1.z,wr1.w,
                         wr2.x,wr2.y,wr2.z,wr2.w, wr3.x,wr3.y,wr3.z,wr3.w};
        #pragma unroll
        for (int j = 0; j < 8; j++) {
            p0 = fmaf(h[j], wlv[2 * j + 0], p0);
            p1 = fmaf(h[j], wlv[2 * j + 1], p1);
            p2 = fmaf(h[j], wrv[2 * j + 0], p2);
            p3 = fmaf(h[j], wrv[2 * j + 1], p3);
        }
    }
    #pragma unroll
    for (int o = 16; o > 0; o >>= 1) {
        p0 += __shfl_xor_sync(0xffffffffu, p0, o);
        p1 += __shfl_xor_sync(0xffffffffu, p1, o);
        p2 += __shfl_xor_sync(0xffffffffu, p2, o);
        p3 += __shfl_xor_sync(0xffffffffu, p3, o);
    }
    if (lane == 0) {
        float2 xl2, xr2;
        xl2.x = p0 + b2l[0]; xl2.y = p1 + b2l[1];
        xr2.x = p2 + b2r[0]; xr2.y = p3 + b2r[1];
        *(float2*)&g_XL2[n * 2] = xl2;
        *(float2*)&g_XR2[n * 2] = xr2;
    }
}

// ------------- conv2 CSR + final output (warp per node) --------------------
__global__ __launch_bounds__(256) void conv2_csr_kernel(
    const float* __restrict__ att2, const float* __restrict__ bias2,
    float* __restrict__ out, int N)
{
    const int n = blockIdx.x * 8 + (threadIdx.x >> 5);
    const int lane = threadIdx.x & 31;
    if (n >= N) return;
    const float a0 = att2[0], a1 = att2[1];
    const float a06 = 0.6f * a0, a04 = 0.4f * a0;
    const float a16 = 0.6f * a1, a14 = 0.4f * a1;
    float2 xls = *(const float2*)&g_XL2[n * 2];
    float2 xr  = *(const float2*)&g_XR2[n * 2];

    float den = 0.f, s0 = 0.f, s1 = 0.f;
    const int row0 = g_rowptr[n], row1 = g_rowptr[n + 1];
    for (int i = row0 + lane; i < row1; i += 32) {
        int src = g_esrc[i];
        float2 xl = *(const float2*)&g_XL2[src * 2];
        float f0 = xl.x + xr.x;
        float f1 = xl.y + xr.y;
        float s = fmaf(f0, a06, fmaf(fabsf(f0), a04,
                  fmaf(f1, a16, fabsf(f1) * a14)));
        float exi = __expf(s);
        den += exi;
        s0 = fmaf(exi, xl.x, s0);
        s1 = fmaf(exi, xl.y, s1);
    }
    #pragma unroll
    for (int o = 16; o > 0; o >>= 1) {
        den += __shfl_xor_sync(0xffffffffu, den, o);
        s0  += __shfl_xor_sync(0xffffffffu, s0, o);
        s1  += __shfl_xor_sync(0xffffffffu, s1, o);
    }
    if (lane == 0) {
        float f0 = xls.x + xr.x;
        float f1 = xls.y + xr.y;
        float s = fmaf(f0, a06, fmaf(fabsf(f0), a04,
                  fmaf(f1, a16, fabsf(f1) * a14)));
        float ex = __expf(s);
        den += ex;
        s0 = fmaf(ex, xls.x, s0);
        s1 = fmaf(ex, xls.y, s1);
        float dinv = 1.0f / den;
        float2 o;
        o.x = s0 * dinv + bias2[0];
        o.y = s1 * dinv + bias2[1];
        *(float2*)(out + n * 2) = o;
    }
}

// ---------------------------------------------------------------------------
extern "C" void kernel_launch(void* const* d_in, const int* in_sizes, int n_in,
                              void* d_out, int out_size) {
    const float* x     = (const float*)d_in[0];
    const void*  ei    = d_in[1];
    const float* W1l   = (const float*)d_in[2];
    const float* b1l   = (const float*)d_in[3];
    const float* W1r   = (const float*)d_in[4];
    const float* b1r   = (const float*)d_in[5];
    const float* att1  = (const float*)d_in[6];
    const float* bias1 = (const float*)d_in[7];
    const float* W2l   = (const float*)d_in[8];
    const float* b2l   = (const float*)d_in[9];
    const float* W2r   = (const float*)d_in[10];
    const float* b2r   = (const float*)d_in[11];
    const float* att2  = (const float*)d_in[12];
    const float* bias2 = (const float*)d_in[13];
    const float* Wskip = (const float*)d_in[14];
    const float* bskip = (const float*)d_in[15];
    const float* gamma = (const float*)d_in[16];
    const float* beta  = (const float*)d_in[17];
    float* out = (float*)d_out;

    const int       N = in_sizes[0] / DIN;            // 50000
    const long long E = (long long)in_sizes[1] / 2;   // 800000

    float *dXL1, *dXR1, *dSKIP;
    cudaGetSymbolAddress((void**)&dXL1, g_XL1);
    cudaGetSymbolAddress((void**)&dXR1, g_XR1);
    cudaGetSymbolAddress((void**)&dSKIP, g_SKIP);

    // launch order keeps gemm at my-launch index 3 (= ncu capture slot)
    init_kernel<<<(N + 255) / 256, 256>>>((const unsigned int*)ei, N);      // 0
    {
        int ablocks = (int)(((long long)N * 256 + 1023) / 1024);
        prep_ab_kernel<<<768 + ablocks, 256>>>(x, W1l, W1r, Wskip, N);      // 1
    }
    hist_kernel<<<(int)((E + 255) / 256), 256>>>(ei, E);                    // 2
    {
        dim3 g(6, (N + 127) / 128);
        gemm_mma_kernel<<<g, 256>>>(b1l, b1r, bskip, dXL1, dXR1, dSKIP, N); // 3
    }
    const int SB = (N + 1023) / 1024;
    scanA_kernel<<<SB, 1024>>>(N);                                          // 4
    scanB_kernel<<<1, 32>>>(SB);                                            // 5
    scanC_kernel<<<SB, 1024>>>(N);                                          // 6
    scatter_kernel<<<(int)((E + 255) / 256), 256>>>(ei, E);                 // 7

    conv1_csr_kernel<<<(N + 7) / 8, 256>>>(att1, bias1, gamma, beta,
                                           W2l, b2l, W2r, b2r, att2, N);    // 8
    conv2_csr_kernel<<<(N + 7) / 8, 256>>>(att2, bias2, out, N);            // 9
}

// round 13
// speedup vs baseline: 1.1377x; 1.0478x over previous
#include <cuda_runtime.h>
#include <cuda_bf16.h>
#include <math.h>
#include <stdint.h>

// Problem constants
#define DIN   256
#define HCc   256
#define NEG   0.2f
#define MAXN  50000
#define MAXE  1000000
#define MPAD  (MAXN + 128)

// ---------------- scratch (static device globals) --------------------------
__device__ float g_XL1[(long long)MAXN * HCc];
__device__ float g_XR1[(long long)MAXN * HCc];
__device__ float g_SKIP[(long long)MAXN * HCc];
__device__ float g_XL2[MAXN * 2];
__device__ float g_XR2[MAXN * 2];
__device__ int   g_deg[MAXN];
__device__ int   g_rowptr[MAXN + 1];
__device__ int   g_cur[MAXN];
__device__ int   g_esrc[MAXE];
__device__ int   g_bsum[64];
__device__ int   g_boff[64];
__device__ int   g_is64;
__device__ __nv_bfloat16 g_BT_hi[3 * 256 * 256];
__device__ __nv_bfloat16 g_BT_lo[3 * 256 * 256];
__device__ __nv_bfloat16 g_AT_hi[(long long)MPAD * 256];
__device__ __nv_bfloat16 g_AT_lo[(long long)MPAD * 256];

// ---------------- small helpers ---------------------------------------------
__device__ __forceinline__ uint32_t smem_u32(const void* p) {
    uint32_t a;
    asm("{ .reg .u64 t; cvta.to.shared.u64 t, %1; cvt.u32.u64 %0, t; }"
        : "=r"(a) : "l"(p));
    return a;
}
__device__ __forceinline__ void ldsm_x4(uint32_t* r, uint32_t addr) {
    asm volatile("ldmatrix.sync.aligned.m8n8.x4.shared.b16 {%0,%1,%2,%3}, [%4];"
        : "=r"(r[0]), "=r"(r[1]), "=r"(r[2]), "=r"(r[3]) : "r"(addr));
}
__device__ __forceinline__ void mma_bf16(float* c, const uint32_t* a,
                                         uint32_t b0, uint32_t b1) {
    asm volatile(
        "mma.sync.aligned.m16n8k16.row.col.f32.bf16.bf16.f32 "
        "{%0,%1,%2,%3}, {%4,%5,%6,%7}, {%8,%9}, {%0,%1,%2,%3};"
        : "+f"(c[0]), "+f"(c[1]), "+f"(c[2]), "+f"(c[3])
        : "r"(a[0]), "r"(a[1]), "r"(a[2]), "r"(a[3]), "r"(b0), "r"(b1));
}
__device__ __forceinline__ void cp_async16(uint32_t dst, const void* src) {
    asm volatile("cp.async.ca.shared.global [%0], [%1], 16;"
                 :: "r"(dst), "l"(src) : "memory");
}
#define CP_COMMIT() asm volatile("cp.async.commit_group;" ::: "memory")
#define CP_WAIT0()  asm volatile("cp.async.wait_group 0;" ::: "memory")

__device__ __forceinline__ int ld_idx(const void* ei, long long pos, int is64) {
    if (is64) return (int)(((const long long*)ei)[pos]);
    return ((const int*)ei)[pos];
}

// ---------------- fused init: zero deg + edge dtype detect ------------------
__global__ void init_kernel(const unsigned int* __restrict__ w, int N) {
    int i = blockIdx.x * blockDim.x + threadIdx.x;
    if (i < N) g_deg[i] = 0;
    if (i == 0) {
        int ok = 1;
        #pragma unroll
        for (int j = 0; j < 32; j++) {
            if (w[2 * j + 1] != 0u) { ok = 0; break; }
        }
        g_is64 = ok;
    }
}

// ---------------- fused prep: B transpose+split AND A split -----------------
__global__ void prep_ab_kernel(const float* __restrict__ x,
                               const float* __restrict__ W0,
                               const float* __restrict__ W1,
                               const float* __restrict__ W2, int N) {
    int b = blockIdx.x;
    if (b < 768) {
        int s = b >> 8, k = b & 255, n = threadIdx.x;
        const float* W = (s == 0) ? W0 : (s == 1) ? W1 : W2;
        float v = W[k * 256 + n];
        __nv_bfloat16 hi = __float2bfloat16(v);
        float lo = v - __bfloat162float(hi);
        int idx = (s * 256 + n) * 256 + k;
        g_BT_hi[idx] = hi;
        g_BT_lo[idx] = __float2bfloat16(lo);
    } else {
        long long eb = (long long)(b - 768) * 1024 + threadIdx.x * 4;
        if (eb < (long long)N * 256) {
            float4 v = *(const float4*)(x + eb);
            float f[4] = {v.x, v.y, v.z, v.w};
            __nv_bfloat16 h[4], l[4];
            #pragma unroll
            for (int j = 0; j < 4; j++) {
                h[j] = __float2bfloat16(f[j]);
                l[j] = __float2bfloat16(f[j] - __bfloat162float(h[j]));
            }
            *(ulonglong1*)(g_AT_hi + eb) = *(ulonglong1*)h;
            *(ulonglong1*)(g_AT_lo + eb) = *(ulonglong1*)l;
        }
    }
}

// ---------------- CSR build -------------------------------------------------
__global__ void hist_kernel(const void* __restrict__ ei, long long E) {
    long long e = (long long)blockIdx.x * blockDim.x + threadIdx.x;
    if (e >= E) return;
    int dst = ld_idx(ei, E + e, g_is64);
    atomicAdd(&g_deg[dst], 1);
}
__global__ __launch_bounds__(1024) void scanA_kernel(int N) {
    __shared__ int wsum[32];
    const int lane = threadIdx.x & 31, warp = threadIdx.x >> 5;
    int i = blockIdx.x * 1024 + threadIdx.x;
    int v = (i < N) ? g_deg[i] : 0;
    int x = v;
    #pragma unroll
    for (int o = 1; o < 32; o <<= 1) {
        int y = __shfl_up_sync(0xffffffffu, x, o);
        if (lane >= o) x += y;
    }
    if (lane == 31) wsum[warp] = x;
    __syncthreads();
    if (warp == 0) {
        int w = wsum[lane];
        #pragma unroll
        for (int o = 1; o < 32; o <<= 1) {
            int y = __shfl_up_sync(0xffffffffu, w, o);
            if (lane >= o) w += y;
        }
        wsum[lane] = w;
    }
    __syncthreads();
    int incl = x + (warp > 0 ? wsum[warp - 1] : 0);
    if (i < N) g_rowptr[i + 1] = incl;
    if (threadIdx.x == 1023) g_bsum[blockIdx.x] = incl;
}
__global__ void scanB_kernel(int B) {
    if (threadIdx.x == 0) {
        int acc = 0;
        for (int b = 0; b < B; b++) { int v = g_bsum[b]; g_boff[b] = acc; acc += v; }
    }
}
__global__ __launch_bounds__(1024) void scanC_kernel(int N) {
    int i = blockIdx.x * 1024 + threadIdx.x;
    if (i == 0) g_rowptr[0] = 0;
    if (i < N) {
        int r = g_rowptr[i + 1] + g_boff[blockIdx.x];
        g_rowptr[i + 1] = r;
        g_cur[i] = r - g_deg[i];
    }
}
__global__ void scatter_kernel(const void* __restrict__ ei, long long E) {
    long long e = (long long)blockIdx.x * blockDim.x + threadIdx.x;
    if (e >= E) return;
    int is64 = g_is64;
    int src = ld_idx(ei, e, is64);
    int dst = ld_idx(ei, E + e, is64);
    int pos = atomicAdd(&g_cur[dst], 1);
    g_esrc[pos] = src;
}

// ---------------- mma.sync bf16-split triple GEMM ---------------------------
#define PADK 24
#define ABUF (128 * PADK)
#define OPB  (ABUF * 2)
#define BUFB (OPB * 4)

__global__ __launch_bounds__(256, 2) void gemm_mma_kernel(
    const float* __restrict__ bias0, const float* __restrict__ bias1,
    const float* __restrict__ bias2,
    float* __restrict__ C0, float* __restrict__ C1, float* __restrict__ C2,
    int M)
{
    __shared__ __nv_bfloat16 sm[2 * 4 * ABUF];   // 48KB

    const int sel = blockIdx.x >> 1;
    const int n0  = (blockIdx.x & 1) * 128;
    const int m0  = blockIdx.y * 128;
    const float* bias = (sel == 0) ? bias0 : (sel == 1) ? bias1 : bias2;
    float*       C    = (sel == 0) ? C0 : (sel == 1) ? C1 : C2;
    const __nv_bfloat16* BTh = g_BT_hi + sel * 65536 + (long long)n0 * 256;
    const __nv_bfloat16* BTl = g_BT_lo + sel * 65536 + (long long)n0 * 256;

    const int tid  = threadIdx.x;
    const int lane = tid & 31;
    const int wid  = tid >> 5;
    const int wm0  = (wid >> 2) * 64;
    const int wn0  = (wid & 3) * 32;

    const int ar = tid >> 1;
    const int ak = (tid & 1) * 8;
    const __nv_bfloat16* gAh = g_AT_hi + (long long)(m0 + ar) * 256 + ak;
    const __nv_bfloat16* gAl = g_AT_lo + (long long)(m0 + ar) * 256 + ak;
    const __nv_bfloat16* gBh = BTh + (long long)ar * 256 + ak;
    const __nv_bfloat16* gBl = BTl + (long long)ar * 256 + ak;
    const uint32_t dFill = smem_u32(&sm[ar * PADK + ak]);

    uint32_t a_h[4], b_h[2];
    {
        int arow = lane & 15;
        int acol = (lane >> 4) * 8;
        #pragma unroll
        for (int fm = 0; fm < 4; fm++)
            a_h[fm] = smem_u32(&sm[(wm0 + fm * 16 + arow) * PADK + acol]);
        int brow = (lane & 7) + (lane >> 4) * 8;
        int bcol = ((lane >> 3) & 1) * 8;
        #pragma unroll
        for (int nb = 0; nb < 2; nb++)
            b_h[nb] = smem_u32(&sm[2 * ABUF + (wn0 + nb * 16 + brow) * PADK + bcol]);
    }

    float acc[16][4];
    #pragma unroll
    for (int i = 0; i < 16; i++)
        #pragma unroll
        for (int j = 0; j < 4; j++) acc[i][j] = 0.f;

    cp_async16(dFill,            gAh);
    cp_async16(dFill + OPB,      gAl);
    cp_async16(dFill + 2 * OPB,  gBh);
    cp_async16(dFill + 3 * OPB,  gBl);
    CP_COMMIT();
    CP_WAIT0();
    __syncthreads();

    int buf = 0;
    for (int ks = 0; ks < 256; ks += 16) {
        const int nb = buf ^ 1;
        const bool has_next = (ks + 16) < 256;
        if (has_next) {
            const uint32_t d = dFill + nb * BUFB;
            cp_async16(d,           gAh + ks + 16);
            cp_async16(d + OPB,     gAl + ks + 16);
            cp_async16(d + 2 * OPB, gBh + ks + 16);
            cp_async16(d + 3 * OPB, gBl + ks + 16);
            CP_COMMIT();
        }
        const uint32_t bofs = buf * BUFB;
        uint32_t AF[4][4], BhF[2][4], BlF[2][4];
        #pragma unroll
        for (int fm = 0; fm < 4; fm++) ldsm_x4(AF[fm], a_h[fm] + bofs);
        ldsm_x4(BhF[0], b_h[0] + bofs);
        ldsm_x4(BhF[1], b_h[1] + bofs);
        #pragma unroll
        for (int fm = 0; fm < 4; fm++)
            #pragma unroll
            for (int fn = 0; fn < 4; fn++)
                mma_bf16(acc[fm * 4 + fn], AF[fm],
                         BhF[fn >> 1][(fn & 1) * 2], BhF[fn >> 1][(fn & 1) * 2 + 1]);
        ldsm_x4(BlF[0], b_h[0] + bofs + OPB);
        ldsm_x4(BlF[1], b_h[1] + bofs + OPB);
        #pragma unroll
        for (int fm = 0; fm < 4; fm++)
            #pragma unroll
            for (int fn = 0; fn < 4; fn++)
                mma_bf16(acc[fm * 4 + fn], AF[fm],
                         BlF[fn >> 1][(fn & 1) * 2], BlF[fn >> 1][(fn & 1) * 2 + 1]);
        #pragma unroll
        for (int fm = 0; fm < 4; fm++) ldsm_x4(AF[fm], a_h[fm] + bofs + OPB);
        #pragma unroll
        for (int fm = 0; fm < 4; fm++)
            #pragma unroll
            for (int fn = 0; fn < 4; fn++)
                mma_bf16(acc[fm * 4 + fn], AF[fm],
                         BhF[fn >> 1][(fn & 1) * 2], BhF[fn >> 1][(fn & 1) * 2 + 1]);
        if (has_next) CP_WAIT0();
        __syncthreads();
        buf = nb;
    }

    #pragma unroll
    for (int fm = 0; fm < 4; fm++) {
        int r0 = m0 + wm0 + fm * 16 + (lane >> 2);
        #pragma unroll
        for (int fn = 0; fn < 4; fn++) {
            int col = n0 + wn0 + fn * 8 + (lane & 3) * 2;
            float2 bv = *(const float2*)(bias + col);
            float* a4 = acc[fm * 4 + fn];
            if (r0 < M) {
                float2 o = make_float2(a4[0] + bv.x, a4[1] + bv.y);
                *(float2*)(C + (long long)r0 * 256 + col) = o;
            }
            int r1 = r0 + 8;
            if (r1 < M) {
                float2 o = make_float2(a4[2] + bv.x, a4[3] + bv.y);
                *(float2*)(C + (long long)r1 * 256 + col) = o;
            }
        }
    }
}

// ------- fused conv1 CSR + softmax + skip + LN + ELU + conv2 projection ----
__global__ __launch_bounds__(256) void conv1_csr_kernel(
    const float* __restrict__ att1, const float* __restrict__ bias1,
    const float* __restrict__ gamma, const float* __restrict__ beta,
    const float* __restrict__ W2l, const float* __restrict__ b2l,
    const float* __restrict__ W2r, const float* __restrict__ b2r,
    const float* __restrict__ att2, int N)
{
    const int n = blockIdx.x * 8 + (threadIdx.x >> 5);
    const int lane = threadIdx.x & 31;
    if (n >= N) return;

    float att6[8], att4[8];
    {
        float4 a0 = *(const float4*)(att1 + lane * 8);
        float4 a1 = *(const float4*)(att1 + lane * 8 + 4);
        float av[8] = {a0.x,a0.y,a0.z,a0.w,a1.x,a1.y,a1.z,a1.w};
        #pragma unroll
        for (int j = 0; j < 8; j++) { att6[j] = 0.6f * av[j]; att4[j] = 0.4f * av[j]; }
    }
    float xr[8];
    {
        const float* p = g_XR1 + (long long)n * HCc + lane * 8;
        float4 r0 = *(const float4*)p;
        float4 r1 = *(const float4*)(p + 4);
        xr[0]=r0.x; xr[1]=r0.y; xr[2]=r0.z; xr[3]=r0.w;
        xr[4]=r1.x; xr[5]=r1.y; xr[6]=r1.z; xr[7]=r1.w;
    }

    float acc[8], den;
    {
        const float* p = g_XL1 + (long long)n * HCc + lane * 8;
        float4 l0 = *(const float4*)p;
        float4 l1 = *(const float4*)(p + 4);
        float xl[8] = {l0.x,l0.y,l0.z,l0.w,l1.x,l1.y,l1.z,l1.w};
        float s6 = 0.f, s4 = 0.f;
        #pragma unroll
        for (int j = 0; j < 8; j++) {
            float e = xl[j] + xr[j];
            s6 = fmaf(e, att6[j], s6);
            s4 = fmaf(fabsf(e), att4[j], s4);
        }
        float s = s6 + s4;
        s += __shfl_xor_sync(0xffffffffu, s, 1);
        s += __shfl_xor_sync(0xffffffffu, s, 2);
        s += __shfl_xor_sync(0xffffffffu, s, 4);
        float ex = __expf(s);
        den = ex;
        #pragma unroll
        for (int j = 0; j < 8; j++) acc[j] = ex * xl[j];
    }

    const int row0 = g_rowptr[n];
    const int row1 = g_rowptr[n + 1];
    int i = row0;
    for (; i + 1 < row1; i += 2) {
        int srcA = g_esrc[i];
        int srcB = g_esrc[i + 1];
        const float* pA = g_XL1 + (long long)srcA * HCc + lane * 8;
        const float* pB = g_XL1 + (long long)srcB * HCc + lane * 8;
        float4 a0 = *(const float4*)pA;
        float4 a1 = *(const float4*)(pA + 4);
        float4 b0 = *(const float4*)pB;
        float4 b1 = *(const float4*)(pB + 4);
        float xlA[8] = {a0.x,a0.y,a0.z,a0.w,a1.x,a1.y,a1.z,a1.w};
        float xlB[8] = {b0.x,b0.y,b0.z,b0.w,b1.x,b1.y,b1.z,b1.w};
        float sA6 = 0.f, sA4 = 0.f, sB6 = 0.f, sB4 = 0.f;
        #pragma unroll
        for (int j = 0; j < 8; j++) {
            float eA = xlA[j] + xr[j];
            float eB = xlB[j] + xr[j];
            sA6 = fmaf(eA, att6[j], sA6);
            sA4 = fmaf(fabsf(eA), att4[j], sA4);
            sB6 = fmaf(eB, att6[j], sB6);
            sB4 = fmaf(fabsf(eB), att4[j], sB4);
        }
        float sA = sA6 + sA4, sB = sB6 + sB4;
        #pragma unroll
        for (int o = 1; o <= 4; o <<= 1) {
            sA += __shfl_xor_sync(0xffffffffu, sA, o);
            sB += __shfl_xor_sync(0xffffffffu, sB, o);
        }
        float exA = __expf(sA);
        float exB = __expf(sB);
        den += exA + exB;
        #pragma unroll
        for (int j = 0; j < 8; j++) {
            acc[j] = fmaf(exA, xlA[j], acc[j]);
            acc[j] = fmaf(exB, xlB[j], acc[j]);
        }
    }
    if (i < row1) {
        int src = g_esrc[i];
        const float* p = g_XL1 + (long long)src * HCc + lane * 8;
        float4 l0 = *(const float4*)p;
        float4 l1 = *(const float4*)(p + 4);
        float xl[8] = {l0.x,l0.y,l0.z,l0.w,l1.x,l1.y,l1.z,l1.w};
        float s6 = 0.f, s4 = 0.f;
        #pragma unroll
        for (int j = 0; j < 8; j++) {
            float e = xl[j] + xr[j];
            s6 = fmaf(e, att6[j], s6);
            s4 = fmaf(fabsf(e), att4[j], s4);
        }
        float s = s6 + s4;
        s += __shfl_xor_sync(0xffffffffu, s, 1);
        s += __shfl_xor_sync(0xffffffffu, s, 2);
        s += __shfl_xor_sync(0xffffffffu, s, 4);
        float ex = __expf(s);
        den += ex;
        #pragma unroll
        for (int j = 0; j < 8; j++) acc[j] = fmaf(ex, xl[j], acc[j]);
    }

    const float dinv = 1.0f / den;
    float v[8];
    {
        const float* sp = g_SKIP + (long long)n * HCc + lane * 8;
        float4 s0 = *(const float4*)sp;
        float4 s1 = *(const float4*)(sp + 4);
        float4 b0 = *(const float4*)(bias1 + lane * 8);
        float4 b1 = *(const float4*)(bias1 + lane * 8 + 4);
        float sk[8] = {s0.x,s0.y,s0.z,s0.w,s1.x,s1.y,s1.z,s1.w};
        float bb[8] = {b0.x,b0.y,b0.z,b0.w,b1.x,b1.y,b1.z,b1.w};
        #pragma unroll
        for (int j = 0; j < 8; j++) v[j] = acc[j] * dinv + bb[j] + sk[j];
    }

    float t = 0.f;
    #pragma unroll
    for (int j = 0; j < 8; j++) t += v[j];
    #pragma unroll
    for (int o = 16; o > 0; o >>= 1) t += __shfl_xor_sync(0xffffffffu, t, o);
    const float mu = t * (1.0f / 256.0f);
    float t2 = 0.f;
    #pragma unroll
    for (int j = 0; j < 8; j++) { float d = v[j] - mu; t2 = fmaf(d, d, t2); }
    #pragma unroll
    for (int o = 16; o > 0; o >>= 1) t2 += __shfl_xor_sync(0xffffffffu, t2, o);
    const float rstd = rsqrtf(t2 * (1.0f / 256.0f) + 1e-5f);

    float h[8];
    {
        float4 g0 = *(const float4*)(gamma + lane * 8);
        float4 g1 = *(const float4*)(gamma + lane * 8 + 4);
        float4 e0 = *(const float4*)(beta + lane * 8);
        float4 e1 = *(const float4*)(beta + lane * 8 + 4);
        float gg[8] = {g0.x,g0.y,g0.z,g0.w,g1.x,g1.y,g1.z,g1.w};
        float be[8] = {e0.x,e0.y,e0.z,e0.w,e1.x,e1.y,e1.z,e1.w};
        #pragma unroll
        for (int j = 0; j < 8; j++) {
            float hh = (v[j] - mu) * rstd * gg[j] + be[j];
            h[j] = hh > 0.f ? hh : expm1f(hh);
        }
    }

    float p0 = 0.f, p1 = 0.f, p2 = 0.f, p3 = 0.f;
    {
        const float* wl = W2l + lane * 16;
        const float* wr = W2r + lane * 16;
        float4 wl0 = *(const float4*)wl;
        float4 wl1 = *(const float4*)(wl + 4);
        float4 wl2 = *(const float4*)(wl + 8);
        float4 wl3 = *(const float4*)(wl + 12);
        float4 wr0 = *(const float4*)wr;
        float4 wr1 = *(const float4*)(wr + 4);
        float4 wr2 = *(const float4*)(wr + 8);
        float4 wr3 = *(const float4*)(wr + 12);
        float wlv[16] = {wl0.x,wl0.y,wl0.z,wl0.w, wl1.x,wl1.y,wl1.z,wl1.w,
                         wl2.x,wl2.y,wl2.z,wl2.w, wl3.x,wl3.y,wl3.z,wl3.w};
        float wrv[16] = {wr0.x,wr0.y,wr0.z,wr0.w, wr1.x,wr1.y,wr1.z,wr1.w,
                         wr2.x,wr2.y,wr2.z,wr2.w, wr3.x,wr3.y,wr3.z,wr3.w};
        #pragma unroll
        for (int j = 0; j < 8; j++) {
            p0 = fmaf(h[j], wlv[2 * j + 0], p0);
            p1 = fmaf(h[j], wlv[2 * j + 1], p1);
            p2 = fmaf(h[j], wrv[2 * j + 0], p2);
            p3 = fmaf(h[j], wrv[2 * j + 1], p3);
        }
    }
    #pragma unroll
    for (int o = 16; o > 0; o >>= 1) {
        p0 += __shfl_xor_sync(0xffffffffu, p0, o);
        p1 += __shfl_xor_sync(0xffffffffu, p1, o);
        p2 += __shfl_xor_sync(0xffffffffu, p2, o);
        p3 += __shfl_xor_sync(0xffffffffu, p3, o);
    }
    if (lane == 0) {
        float2 xl2, xr2;
        xl2.x = p0 + b2l[0]; xl2.y = p1 + b2l[1];
        xr2.x = p2 + b2r[0]; xr2.y = p3 + b2r[1];
        *(float2*)&g_XL2[n * 2] = xl2;
        *(float2*)&g_XR2[n * 2] = xr2;
    }
}

// ------------- conv2 CSR + final output (warp per node) --------------------
__global__ __launch_bounds__(256) void conv2_csr_kernel(
    const float* __restrict__ att2, const float* __restrict__ bias2,
    float* __restrict__ out, int N)
{
    const int n = blockIdx.x * 8 + (threadIdx.x >> 5);
    const int lane = threadIdx.x & 31;
    if (n >= N) return;
    const float a0 = att2[0], a1 = att2[1];
    const float a06 = 0.6f * a0, a04 = 0.4f * a0;
    const float a16 = 0.6f * a1, a14 = 0.4f * a1;
    float2 xls = *(const float2*)&g_XL2[n * 2];
    float2 xr  = *(const float2*)&g_XR2[n * 2];

    float den = 0.f, s0 = 0.f, s1 = 0.f;
    const int row0 = g_rowptr[n], row1 = g_rowptr[n + 1];
    for (int i = row0 + lane; i < row1; i += 32) {
        int src = g_esrc[i];
        float2 xl = *(const float2*)&g_XL2[src * 2];
        float f0 = xl.x + xr.x;
        float f1 = xl.y + xr.y;
        float s = fmaf(f0, a06, fmaf(fabsf(f0), a04,
                  fmaf(f1, a16, fabsf(f1) * a14)));
        float exi = __expf(s);
        den += exi;
        s0 = fmaf(exi, xl.x, s0);
        s1 = fmaf(exi, xl.y, s1);
    }
    #pragma unroll
    for (int o = 16; o > 0; o >>= 1) {
        den += __shfl_xor_sync(0xffffffffu, den, o);
        s0  += __shfl_xor_sync(0xffffffffu, s0, o);
        s1  += __shfl_xor_sync(0xffffffffu, s1, o);
    }
    if (lane == 0) {
        float f0 = xls.x + xr.x;
        float f1 = xls.y + xr.y;
        float s = fmaf(f0, a06, fmaf(fabsf(f0), a04,
                  fmaf(f1, a16, fabsf(f1) * a14)));
        float ex = __expf(s);
        den += ex;
        s0 = fmaf(ex, xls.x, s0);
        s1 = fmaf(ex, xls.y, s1);
        float dinv = 1.0f / den;
        float2 o;
        o.x = s0 * dinv + bias2[0];
        o.y = s1 * dinv + bias2[1];
        *(float2*)(out + n * 2) = o;
    }
}

// ---------------------------------------------------------------------------
extern "C" void kernel_launch(void* const* d_in, const int* in_sizes, int n_in,
                              void* d_out, int out_size) {
    const float* x     = (const float*)d_in[0];
    const void*  ei    = d_in[1];
    const float* W1l   = (const float*)d_in[2];
    const float* b1l   = (const float*)d_in[3];
    const float* W1r   = (const float*)d_in[4];
    const float* b1r   = (const float*)d_in[5];
    const float* att1  = (const float*)d_in[6];
    const float* bias1 = (const float*)d_in[7];
    const float* W2l   = (const float*)d_in[8];
    const float* b2l   = (const float*)d_in[9];
    const float* W2r   = (const float*)d_in[10];
    const float* b2r   = (const float*)d_in[11];
    const float* att2  = (const float*)d_in[12];
    const float* bias2 = (const float*)d_in[13];
    const float* Wskip = (const float*)d_in[14];
    const float* bskip = (const float*)d_in[15];
    const float* gamma = (const float*)d_in[16];
    const float* beta  = (const float*)d_in[17];
    float* out = (float*)d_out;

    const int       N = in_sizes[0] / DIN;            // 50000
    const long long E = (long long)in_sizes[1] / 2;   // 800000

    float *dXL1, *dXR1, *dSKIP;
    cudaGetSymbolAddress((void**)&dXL1, g_XL1);
    cudaGetSymbolAddress((void**)&dXR1, g_XR1);
    cudaGetSymbolAddress((void**)&dSKIP, g_SKIP);

    // one-time infra (created on the eager correctness call, reused in capture)
    static cudaStream_t s2 = nullptr;
    static cudaEvent_t evFork = nullptr, evJoin = nullptr;
    if (s2 == nullptr) {
        cudaStreamCreateWithFlags(&s2, cudaStreamNonBlocking);
        cudaEventCreateWithFlags(&evFork, cudaEventDisableTiming);
        cudaEventCreateWithFlags(&evJoin, cudaEventDisableTiming);
    }

    // ---- stage 0 (main stream): init (needed by both branches) ----
    init_kernel<<<(N + 255) / 256, 256>>>((const unsigned int*)ei, N);

    // ---- fork: CSR build on s2, concurrent with prep+GEMM on main ----
    cudaEventRecord(evFork, 0);
    cudaStreamWaitEvent(s2, evFork, 0);

    const int SB = (N + 1023) / 1024;
    hist_kernel<<<(int)((E + 255) / 256), 256, 0, s2>>>(ei, E);
    scanA_kernel<<<SB, 1024, 0, s2>>>(N);
    scanB_kernel<<<1, 32, 0, s2>>>(SB);
    scanC_kernel<<<SB, 1024, 0, s2>>>(N);
    scatter_kernel<<<(int)((E + 255) / 256), 256, 0, s2>>>(ei, E);
    cudaEventRecord(evJoin, s2);

    // main stream: prep + GEMM (independent of CSR)
    {
        int ablocks = (int)(((long long)N * 256 + 1023) / 1024);
        prep_ab_kernel<<<768 + ablocks, 256>>>(x, W1l, W1r, Wskip, N);
    }
    {
        dim3 g(6, (N + 127) / 128);
        gemm_mma_kernel<<<g, 256>>>(b1l, b1r, bskip, dXL1, dXR1, dSKIP, N);
    }

    // ---- join: conv1 needs both GEMM outputs and CSR ----
    cudaStreamWaitEvent(0, evJoin, 0);

    conv1_csr_kernel<<<(N + 7) / 8, 256>>>(att1, bias1, gamma, beta,
                                           W2l, b2l, W2r, b2r, att2, N);
    conv2_csr_kernel<<<(N + 7) / 8, 256>>>(att2, bias2, out, N);
}

// round 14
// speedup vs baseline: 1.2584x; 1.1061x over previous
#include <cuda_runtime.h>
#include <cuda_fp16.h>
#include <math.h>
#include <stdint.h>

// Problem constants
#define DIN   256
#define HCc   256
#define NEG   0.2f
#define MAXN  50000
#define MAXE  1000000
#define MPAD  (MAXN + 128)

// ---------------- scratch (static device globals) --------------------------
__device__ float g_XL1[(long long)MAXN * HCc];
__device__ float g_XR1[(long long)MAXN * HCc];
__device__ float g_SKIP[(long long)MAXN * HCc];
__device__ float g_XL2[MAXN * 2];
__device__ float g_XR2[MAXN * 2];
__device__ int   g_deg[MAXN];
__device__ int   g_rowptr[MAXN + 1];
__device__ int   g_cur[MAXN];
__device__ int   g_esrc[MAXE];
__device__ int   g_bsum[64];
__device__ int   g_boff[64];
__device__ int   g_is64;
// fp16 transposed weights (single-rounded): [sel][N=256][K=256]
__device__ __half g_BTf[3 * 256 * 256];
// fp16 2-term split A (x): [m][k]
__device__ __half g_AT_hi[(long long)MPAD * 256];
__device__ __half g_AT_lo[(long long)MPAD * 256];

// ---------------- small helpers ---------------------------------------------
__device__ __forceinline__ uint32_t smem_u32(const void* p) {
    uint32_t a;
    asm("{ .reg .u64 t; cvta.to.shared.u64 t, %1; cvt.u32.u64 %0, t; }"
        : "=r"(a) : "l"(p));
    return a;
}
__device__ __forceinline__ void ldsm_x4(uint32_t* r, uint32_t addr) {
    asm volatile("ldmatrix.sync.aligned.m8n8.x4.shared.b16 {%0,%1,%2,%3}, [%4];"
        : "=r"(r[0]), "=r"(r[1]), "=r"(r[2]), "=r"(r[3]) : "r"(addr));
}
__device__ __forceinline__ void mma_fp16(float* c, const uint32_t* a,
                                         uint32_t b0, uint32_t b1) {
    asm volatile(
        "mma.sync.aligned.m16n8k16.row.col.f32.f16.f16.f32 "
        "{%0,%1,%2,%3}, {%4,%5,%6,%7}, {%8,%9}, {%0,%1,%2,%3};"
        : "+f"(c[0]), "+f"(c[1]), "+f"(c[2]), "+f"(c[3])
        : "r"(a[0]), "r"(a[1]), "r"(a[2]), "r"(a[3]), "r"(b0), "r"(b1));
}
__device__ __forceinline__ void cp_async16(uint32_t dst, const void* src) {
    asm volatile("cp.async.ca.shared.global [%0], [%1], 16;"
                 :: "r"(dst), "l"(src) : "memory");
}
#define CP_COMMIT() asm volatile("cp.async.commit_group;" ::: "memory")
#define CP_WAIT0()  asm volatile("cp.async.wait_group 0;" ::: "memory")

__device__ __forceinline__ int ld_idx(const void* ei, long long pos, int is64) {
    if (is64) return (int)(((const long long*)ei)[pos]);
    return ((const int*)ei)[pos];
}

// ---------------- fused init: zero deg + edge dtype detect ------------------
__global__ void init_kernel(const unsigned int* __restrict__ w, int N) {
    int i = blockIdx.x * blockDim.x + threadIdx.x;
    if (i < N) g_deg[i] = 0;
    if (i == 0) {
        int ok = 1;
        #pragma unroll
        for (int j = 0; j < 32; j++) {
            if (w[2 * j + 1] != 0u) { ok = 0; break; }
        }
        g_is64 = ok;
    }
}

// ---------------- fused prep: B transpose (fp16) AND A split (fp16 hi/lo) ---
__global__ void prep_ab_kernel(const float* __restrict__ x,
                               const float* __restrict__ W0,
                               const float* __restrict__ W1,
                               const float* __restrict__ W2, int N) {
    int b = blockIdx.x;
    if (b < 768) {
        int s = b >> 8, k = b & 255, n = threadIdx.x;
        const float* W = (s == 0) ? W0 : (s == 1) ? W1 : W2;
        float v = W[k * 256 + n];
        g_BTf[(s * 256 + n) * 256 + k] = __float2half(v);
    } else {
        long long eb = (long long)(b - 768) * 1024 + threadIdx.x * 4;
        if (eb < (long long)N * 256) {
            float4 v = *(const float4*)(x + eb);
            float f[4] = {v.x, v.y, v.z, v.w};
            __half h[4], l[4];
            #pragma unroll
            for (int j = 0; j < 4; j++) {
                h[j] = __float2half(f[j]);
                l[j] = __float2half(f[j] - __half2float(h[j]));
            }
            *(ulonglong1*)(g_AT_hi + eb) = *(ulonglong1*)h;
            *(ulonglong1*)(g_AT_lo + eb) = *(ulonglong1*)l;
        }
    }
}

// ---------------- CSR build -------------------------------------------------
__global__ void hist_kernel(const void* __restrict__ ei, long long E) {
    long long e = (long long)blockIdx.x * blockDim.x + threadIdx.x;
    if (e >= E) return;
    int dst = ld_idx(ei, E + e, g_is64);
    atomicAdd(&g_deg[dst], 1);
}
__global__ __launch_bounds__(1024) void scanA_kernel(int N) {
    __shared__ int wsum[32];
    const int lane = threadIdx.x & 31, warp = threadIdx.x >> 5;
    int i = blockIdx.x * 1024 + threadIdx.x;
    int v = (i < N) ? g_deg[i] : 0;
    int x = v;
    #pragma unroll
    for (int o = 1; o < 32; o <<= 1) {
        int y = __shfl_up_sync(0xffffffffu, x, o);
        if (lane >= o) x += y;
    }
    if (lane == 31) wsum[warp] = x;
    __syncthreads();
    if (warp == 0) {
        int w = wsum[lane];
        #pragma unroll
        for (int o = 1; o < 32; o <<= 1) {
            int y = __shfl_up_sync(0xffffffffu, w, o);
            if (lane >= o) w += y;
        }
        wsum[lane] = w;
    }
    __syncthreads();
    int incl = x + (warp > 0 ? wsum[warp - 1] : 0);
    if (i < N) g_rowptr[i + 1] = incl;
    if (threadIdx.x == 1023) g_bsum[blockIdx.x] = incl;
}
__global__ void scanB_kernel(int B) {
    if (threadIdx.x == 0) {
        int acc = 0;
        for (int b = 0; b < B; b++) { int v = g_bsum[b]; g_boff[b] = acc; acc += v; }
    }
}
__global__ __launch_bounds__(1024) void scanC_kernel(int N) {
    int i = blockIdx.x * 1024 + threadIdx.x;
    if (i == 0) g_rowptr[0] = 0;
    if (i < N) {
        int r = g_rowptr[i + 1] + g_boff[blockIdx.x];
        g_rowptr[i + 1] = r;
        g_cur[i] = r - g_deg[i];
    }
}
__global__ void scatter_kernel(const void* __restrict__ ei, long long E) {
    long long e = (long long)blockIdx.x * blockDim.x + threadIdx.x;
    if (e >= E) return;
    int is64 = g_is64;
    int src = ld_idx(ei, e, is64);
    int dst = ld_idx(ei, E + e, is64);
    int pos = atomicAdd(&g_cur[dst], 1);
    g_esrc[pos] = src;
}

// ---------------- mma.sync fp16 2-term triple GEMM ---------------------------
// CTA 128m x 128n x K=256 (16 stages). 8 warps, each 64m x 32n.
// D = Ah*Bf + Al*Bf (fp32 accum): A split to 22 bits, B single fp16.
#define PADK 24
#define ABUF (128 * PADK)           // half elems per operand block
#define OPB  (ABUF * 2)             // bytes per operand block (6144)
#define BUFB (OPB * 3)              // bytes per buffer (18432)

__global__ __launch_bounds__(256, 2) void gemm_mma_kernel(
    const float* __restrict__ bias0, const float* __restrict__ bias1,
    const float* __restrict__ bias2,
    float* __restrict__ C0, float* __restrict__ C1, float* __restrict__ C2,
    int M)
{
    __shared__ __half sm[2 * 3 * ABUF];   // 36KB

    const int sel = blockIdx.x >> 1;
    const int n0  = (blockIdx.x & 1) * 128;
    const int m0  = blockIdx.y * 128;
    const float* bias = (sel == 0) ? bias0 : (sel == 1) ? bias1 : bias2;
    float*       C    = (sel == 0) ? C0 : (sel == 1) ? C1 : C2;
    const __half* BTf = g_BTf + sel * 65536 + (long long)n0 * 256;

    const int tid  = threadIdx.x;
    const int lane = tid & 31;
    const int wid  = tid >> 5;
    const int wm0  = (wid >> 2) * 64;
    const int wn0  = (wid & 3) * 32;

    // fill mapping: thread t -> row ar (0..127), k-half ak (0 or 8)
    const int ar = tid >> 1;
    const int ak = (tid & 1) * 8;
    const __half* gAh = g_AT_hi + (long long)(m0 + ar) * 256 + ak;
    const __half* gAl = g_AT_lo + (long long)(m0 + ar) * 256 + ak;
    const __half* gBf = BTf + (long long)ar * 256 + ak;
    const uint32_t dFill = smem_u32(&sm[ar * PADK + ak]);   // op0 buf0

    // ldsm lane addresses for buf0: Ah at op0, Al at +OPB, Bf at +2*OPB
    uint32_t a_h[4], b_f[2];
    {
        int arow = lane & 15;
        int acol = (lane >> 4) * 8;
        #pragma unroll
        for (int fm = 0; fm < 4; fm++)
            a_h[fm] = smem_u32(&sm[(wm0 + fm * 16 + arow) * PADK + acol]);
        int brow = (lane & 7) + (lane >> 4) * 8;
        int bcol = ((lane >> 3) & 1) * 8;
        #pragma unroll
        for (int nb = 0; nb < 2; nb++)
            b_f[nb] = smem_u32(&sm[2 * ABUF + (wn0 + nb * 16 + brow) * PADK + bcol]);
    }

    float acc[16][4];
    #pragma unroll
    for (int i = 0; i < 16; i++)
        #pragma unroll
        for (int j = 0; j < 4; j++) acc[i][j] = 0.f;

    // prologue: stage 0 into buffer 0
    cp_async16(dFill,           gAh);
    cp_async16(dFill + OPB,     gAl);
    cp_async16(dFill + 2 * OPB, gBf);
    CP_COMMIT();
    CP_WAIT0();
    __syncthreads();

    int buf = 0;
    for (int ks = 0; ks < 256; ks += 16) {
        const int nb = buf ^ 1;
        const bool has_next = (ks + 16) < 256;
        if (has_next) {
            const uint32_t d = dFill + nb * BUFB;
            cp_async16(d,           gAh + ks + 16);
            cp_async16(d + OPB,     gAl + ks + 16);
            cp_async16(d + 2 * OPB, gBf + ks + 16);
            CP_COMMIT();
        }
        const uint32_t bofs = buf * BUFB;
        uint32_t AF[4][4], BF[2][4];
        // load Ah + Bf
        #pragma unroll
        for (int fm = 0; fm < 4; fm++) ldsm_x4(AF[fm], a_h[fm] + bofs);
        ldsm_x4(BF[0], b_f[0] + bofs);
        ldsm_x4(BF[1], b_f[1] + bofs);
        // term 1: Ah x Bf
        #pragma unroll
        for (int fm = 0; fm < 4; fm++)
            #pragma unroll
            for (int fn = 0; fn < 4; fn++)
                mma_fp16(acc[fm * 4 + fn], AF[fm],
                         BF[fn >> 1][(fn & 1) * 2], BF[fn >> 1][(fn & 1) * 2 + 1]);
        // load Al over Ah; term 2: Al x Bf (Bf reused)
        #pragma unroll
        for (int fm = 0; fm < 4; fm++) ldsm_x4(AF[fm], a_h[fm] + bofs + OPB);
        #pragma unroll
        for (int fm = 0; fm < 4; fm++)
            #pragma unroll
            for (int fn = 0; fn < 4; fn++)
                mma_fp16(acc[fm * 4 + fn], AF[fm],
                         BF[fn >> 1][(fn & 1) * 2], BF[fn >> 1][(fn & 1) * 2 + 1]);
        if (has_next) CP_WAIT0();
        __syncthreads();
        buf = nb;
    }

    #pragma unroll
    for (int fm = 0; fm < 4; fm++) {
        int r0 = m0 + wm0 + fm * 16 + (lane >> 2);
        #pragma unroll
        for (int fn = 0; fn < 4; fn++) {
            int col = n0 + wn0 + fn * 8 + (lane & 3) * 2;
            float2 bv = *(const float2*)(bias + col);
            float* a4 = acc[fm * 4 + fn];
            if (r0 < M) {
                float2 o = make_float2(a4[0] + bv.x, a4[1] + bv.y);
                *(float2*)(C + (long long)r0 * 256 + col) = o;
            }
            int r1 = r0 + 8;
            if (r1 < M) {
                float2 o = make_float2(a4[2] + bv.x, a4[3] + bv.y);
                *(float2*)(C + (long long)r1 * 256 + col) = o;
            }
        }
    }
}

// ------- fused conv1 CSR + softmax + skip + LN + ELU + conv2 projection ----
__global__ __launch_bounds__(256) void conv1_csr_kernel(
    const float* __restrict__ att1, const float* __restrict__ bias1,
    const float* __restrict__ gamma, const float* __restrict__ beta,
    const float* __restrict__ W2l, const float* __restrict__ b2l,
    const float* __restrict__ W2r, const float* __restrict__ b2r,
    const float* __restrict__ att2, int N)
{
    const int n = blockIdx.x * 8 + (threadIdx.x >> 5);
    const int lane = threadIdx.x & 31;
    if (n >= N) return;

    float att6[8], att4[8];
    {
        float4 a0 = *(const float4*)(att1 + lane * 8);
        float4 a1 = *(const float4*)(att1 + lane * 8 + 4);
        float av[8] = {a0.x,a0.y,a0.z,a0.w,a1.x,a1.y,a1.z,a1.w};
        #pragma unroll
        for (int j = 0; j < 8; j++) { att6[j] = 0.6f * av[j]; att4[j] = 0.4f * av[j]; }
    }
    float xr[8];
    {
        const float* p = g_XR1 + (long long)n * HCc + lane * 8;
        float4 r0 = *(const float4*)p;
        float4 r1 = *(const float4*)(p + 4);
        xr[0]=r0.x; xr[1]=r0.y; xr[2]=r0.z; xr[3]=r0.w;
        xr[4]=r1.x; xr[5]=r1.y; xr[6]=r1.z; xr[7]=r1.w;
    }

    float acc[8], den;
    {
        const float* p = g_XL1 + (long long)n * HCc + lane * 8;
        float4 l0 = *(const float4*)p;
        float4 l1 = *(const float4*)(p + 4);
        float xl[8] = {l0.x,l0.y,l0.z,l0.w,l1.x,l1.y,l1.z,l1.w};
        float s6 = 0.f, s4 = 0.f;
        #pragma unroll
        for (int j = 0; j < 8; j++) {
            float e = xl[j] + xr[j];
            s6 = fmaf(e, att6[j], s6);
            s4 = fmaf(fabsf(e), att4[j], s4);
        }
        float s = s6 + s4;
        s += __shfl_xor_sync(0xffffffffu, s, 1);
        s += __shfl_xor_sync(0xffffffffu, s, 2);
        s += __shfl_xor_sync(0xffffffffu, s, 4);
        float ex = __expf(s);
        den = ex;
        #pragma unroll
        for (int j = 0; j < 8; j++) acc[j] = ex * xl[j];
    }

    const int row0 = g_rowptr[n];
    const int row1 = g_rowptr[n + 1];
    int i = row0;
    for (; i + 1 < row1; i += 2) {
        int srcA = g_esrc[i];
        int srcB = g_esrc[i + 1];
        const float* pA = g_XL1 + (long long)srcA * HCc + lane * 8;
        const float* pB = g_XL1 + (long long)srcB * HCc + lane * 8;
        float4 a0 = *(const float4*)pA;
        float4 a1 = *(const float4*)(pA + 4);
        float4 b0 = *(const float4*)pB;
        float4 b1 = *(const float4*)(pB + 4);
        float xlA[8] = {a0.x,a0.y,a0.z,a0.w,a1.x,a1.y,a1.z,a1.w};
        float xlB[8] = {b0.x,b0.y,b0.z,b0.w,b1.x,b1.y,b1.z,b1.w};
        float sA6 = 0.f, sA4 = 0.f, sB6 = 0.f, sB4 = 0.f;
        #pragma unroll
        for (int j = 0; j < 8; j++) {
            float eA = xlA[j] + xr[j];
            float eB = xlB[j] + xr[j];
            sA6 = fmaf(eA, att6[j], sA6);
            sA4 = fmaf(fabsf(eA), att4[j], sA4);
            sB6 = fmaf(eB, att6[j], sB6);
            sB4 = fmaf(fabsf(eB), att4[j], sB4);
        }
        float sA = sA6 + sA4, sB = sB6 + sB4;
        #pragma unroll
        for (int o = 1; o <= 4; o <<= 1) {
            sA += __shfl_xor_sync(0xffffffffu, sA, o);
            sB += __shfl_xor_sync(0xffffffffu, sB, o);
        }
        float exA = __expf(sA);
        float exB = __expf(sB);
        den += exA + exB;
        #pragma unroll
        for (int j = 0; j < 8; j++) {
            acc[j] = fmaf(exA, xlA[j], acc[j]);
            acc[j] = fmaf(exB, xlB[j], acc[j]);
        }
    }
    if (i < row1) {
        int src = g_esrc[i];
        const float* p = g_XL1 + (long long)src * HCc + lane * 8;
        float4 l0 = *(const float4*)p;
        float4 l1 = *(const float4*)(p + 4);
        float xl[8] = {l0.x,l0.y,l0.z,l0.w,l1.x,l1.y,l1.z,l1.w};
        float s6 = 0.f, s4 = 0.f;
        #pragma unroll
        for (int j = 0; j < 8; j++) {
            float e = xl[j] + xr[j];
            s6 = fmaf(e, att6[j], s6);
            s4 = fmaf(fabsf(e), att4[j], s4);
        }
        float s = s6 + s4;
        s += __shfl_xor_sync(0xffffffffu, s, 1);
        s += __shfl_xor_sync(0xffffffffu, s, 2);
        s += __shfl_xor_sync(0xffffffffu, s, 4);
        float ex = __expf(s);
        den += ex;
        #pragma unroll
        for (int j = 0; j < 8; j++) acc[j] = fmaf(ex, xl[j], acc[j]);
    }

    const float dinv = 1.0f / den;
    float v[8];
    {
        const float* sp = g_SKIP + (long long)n * HCc + lane * 8;
        float4 s0 = *(const float4*)sp;
        float4 s1 = *(const float4*)(sp + 4);
        float4 b0 = *(const float4*)(bias1 + lane * 8);
        float4 b1 = *(const float4*)(bias1 + lane * 8 + 4);
        float sk[8] = {s0.x,s0.y,s0.z,s0.w,s1.x,s1.y,s1.z,s1.w};
        float bb[8] = {b0.x,b0.y,b0.z,b0.w,b1.x,b1.y,b1.z,b1.w};
        #pragma unroll
        for (int j = 0; j < 8; j++) v[j] = acc[j] * dinv + bb[j] + sk[j];
    }

    float t = 0.f;
    #pragma unroll
    for (int j = 0; j < 8; j++) t += v[j];
    #pragma unroll
    for (int o = 16; o > 0; o >>= 1) t += __shfl_xor_sync(0xffffffffu, t, o);
    const float mu = t * (1.0f / 256.0f);
    float t2 = 0.f;
    #pragma unroll
    for (int j = 0; j < 8; j++) { float d = v[j] - mu; t2 = fmaf(d, d, t2); }
    #pragma unroll
    for (int o = 16; o > 0; o >>= 1) t2 += __shfl_xor_sync(0xffffffffu, t2, o);
    const float rstd = rsqrtf(t2 * (1.0f / 256.0f) + 1e-5f);

    float h[8];
    {
        float4 g0 = *(const float4*)(gamma + lane * 8);
        float4 g1 = *(const float4*)(gamma + lane * 8 + 4);
        float4 e0 = *(const float4*)(beta + lane * 8);
        float4 e1 = *(const float4*)(beta + lane * 8 + 4);
        float gg[8] = {g0.x,g0.y,g0.z,g0.w,g1.x,g1.y,g1.z,g1.w};
        float be[8] = {e0.x,e0.y,e0.z,e0.w,e1.x,e1.y,e1.z,e1.w};
        #pragma unroll
        for (int j = 0; j < 8; j++) {
            float hh = (v[j] - mu) * rstd * gg[j] + be[j];
            h[j] = hh > 0.f ? hh : expm1f(hh);
        }
    }

    float p0 = 0.f, p1 = 0.f, p2 = 0.f, p3 = 0.f;
    {
        const float* wl = W2l + lane * 16;
        const float* wr = W2r + lane * 16;
        float4 wl0 = *(const float4*)wl;
        float4 wl1 = *(const float4*)(wl + 4);
        float4 wl2 = *(const float4*)(wl + 8);
        float4 wl3 = *(const float4*)(wl + 12);
        float4 wr0 = *(const float4*)wr;
        float4 wr1 = *(const float4*)(wr + 4);
        float4 wr2 = *(const float4*)(wr + 8);
        float4 wr3 = *(const float4*)(wr + 12);
        float wlv[16] = {wl0.x,wl0.y,wl0.z,wl0.w, wl1.x,wl1.y,wl1.z,wl1.w,
                         wl2.x,wl2.y,wl2.z,wl2.w, wl3.x,wl3.y,wl3.z,wl3.w};
        float wrv[16] = {wr0.x,wr0.y,wr0.z,wr0.w, wr1.x,wr1.y,wr1.z,wr1.w,
                         wr2.x,wr2.y,wr2.z,wr2.w, wr3.x,wr3.y,wr3.z,wr3.w};
        #pragma unroll
        for (int j = 0; j < 8; j++) {
            p0 = fmaf(h[j], wlv[2 * j + 0], p0);
            p1 = fmaf(h[j], wlv[2 * j + 1], p1);
            p2 = fmaf(h[j], wrv[2 * j + 0], p2);
            p3 = fmaf(h[j], wrv[2 * j + 1], p3);
        }
    }
    #pragma unroll
    for (int o = 16; o > 0; o >>= 1) {
        p0 += __shfl_xor_sync(0xffffffffu, p0, o);
        p1 += __shfl_xor_sync(0xffffffffu, p1, o);
        p2 += __shfl_xor_sync(0xffffffffu, p2, o);
        p3 += __shfl_xor_sync(0xffffffffu, p3, o);
    }
    if (lane == 0) {
        float2 xl2, xr2;
        xl2.x = p0 + b2l[0]; xl2.y = p1 + b2l[1];
        xr2.x = p2 + b2r[0]; xr2.y = p3 + b2r[1];
        *(float2*)&g_XL2[n * 2] = xl2;
        *(float2*)&g_XR2[n * 2] = xr2;
    }
}

// ------------- conv2 CSR + final output (warp per node) --------------------
__global__ __launch_bounds__(256) void conv2_csr_kernel(
    const float* __restrict__ att2, const float* __restrict__ bias2,
    float* __restrict__ out, int N)
{
    const int n = blockIdx.x * 8 + (threadIdx.x >> 5);
    const int lane = threadIdx.x & 31;
    if (n >= N) return;
    const float a0 = att2[0], a1 = att2[1];
    const float a06 = 0.6f * a0, a04 = 0.4f * a0;
    const float a16 = 0.6f * a1, a14 = 0.4f * a1;
    float2 xls = *(const float2*)&g_XL2[n * 2];
    float2 xr  = *(const float2*)&g_XR2[n * 2];

    float den = 0.f, s0 = 0.f, s1 = 0.f;
    const int row0 = g_rowptr[n], row1 = g_rowptr[n + 1];
    for (int i = row0 + lane; i < row1; i += 32) {
        int src = g_esrc[i];
        float2 xl = *(const float2*)&g_XL2[src * 2];
        float f0 = xl.x + xr.x;
        float f1 = xl.y + xr.y;
        float s = fmaf(f0, a06, fmaf(fabsf(f0), a04,
                  fmaf(f1, a16, fabsf(f1) * a14)));
        float exi = __expf(s);
        den += exi;
        s0 = fmaf(exi, xl.x, s0);
        s1 = fmaf(exi, xl.y, s1);
    }
    #pragma unroll
    for (int o = 16; o > 0; o >>= 1) {
        den += __shfl_xor_sync(0xffffffffu, den, o);
        s0  += __shfl_xor_sync(0xffffffffu, s0, o);
        s1  += __shfl_xor_sync(0xffffffffu, s1, o);
    }
    if (lane == 0) {
        float f0 = xls.x + xr.x;
        float f1 = xls.y + xr.y;
        float s = fmaf(f0, a06, fmaf(fabsf(f0), a04,
                  fmaf(f1, a16, fabsf(f1) * a14)));
        float ex = __expf(s);
        den += ex;
        s0 = fmaf(ex, xls.x, s0);
        s1 = fmaf(ex, xls.y, s1);
        float dinv = 1.0f / den;
        float2 o;
        o.x = s0 * dinv + bias2[0];
        o.y = s1 * dinv + bias2[1];
        *(float2*)(out + n * 2) = o;
    }
}

// ---------------------------------------------------------------------------
extern "C" void kernel_launch(void* const* d_in, const int* in_sizes, int n_in,
                              void* d_out, int out_size) {
    const float* x     = (const float*)d_in[0];
    const void*  ei    = d_in[1];
    const float* W1l   = (const float*)d_in[2];
    const float* b1l   = (const float*)d_in[3];
    const float* W1r   = (const float*)d_in[4];
    const float* b1r   = (const float*)d_in[5];
    const float* att1  = (const float*)d_in[6];
    const float* bias1 = (const float*)d_in[7];
    const float* W2l   = (const float*)d_in[8];
    const float* b2l   = (const float*)d_in[9];
    const float* W2r   = (const float*)d_in[10];
    const float* b2r   = (const float*)d_in[11];
    const float* att2  = (const float*)d_in[12];
    const float* bias2 = (const float*)d_in[13];
    const float* Wskip = (const float*)d_in[14];
    const float* bskip = (const float*)d_in[15];
    const float* gamma = (const float*)d_in[16];
    const float* beta  = (const float*)d_in[17];
    float* out = (float*)d_out;

    const int       N = in_sizes[0] / DIN;            // 50000
    const long long E = (long long)in_sizes[1] / 2;   // 800000

    float *dXL1, *dXR1, *dSKIP;
    cudaGetSymbolAddress((void**)&dXL1, g_XL1);
    cudaGetSymbolAddress((void**)&dXR1, g_XR1);
    cudaGetSymbolAddress((void**)&dSKIP, g_SKIP);

    // one-time infra (created on the eager correctness call, reused in capture)
    static cudaStream_t s2 = nullptr;
    static cudaEvent_t evFork = nullptr, evJoin = nullptr;
    if (s2 == nullptr) {
        cudaStreamCreateWithFlags(&s2, cudaStreamNonBlocking);
        cudaEventCreateWithFlags(&evFork, cudaEventDisableTiming);
        cudaEventCreateWithFlags(&evJoin, cudaEventDisableTiming);
    }

    // ---- stage 0 (main stream): init (needed by both branches) ----
    init_kernel<<<(N + 255) / 256, 256>>>((const unsigned int*)ei, N);

    // ---- fork: CSR build on s2, concurrent with prep+GEMM on main ----
    cudaEventRecord(evFork, 0);
    cudaStreamWaitEvent(s2, evFork, 0);

    const int SB = (N + 1023) / 1024;
    hist_kernel<<<(int)((E + 255) / 256), 256, 0, s2>>>(ei, E);
    scanA_kernel<<<SB, 1024, 0, s2>>>(N);
    scanB_kernel<<<1, 32, 0, s2>>>(SB);
    scanC_kernel<<<SB, 1024, 0, s2>>>(N);
    scatter_kernel<<<(int)((E + 255) / 256), 256, 0, s2>>>(ei, E);
    cudaEventRecord(evJoin, s2);

    // main stream: prep + GEMM (independent of CSR)
    {
        int ablocks = (int)(((long long)N * 256 + 1023) / 1024);
        prep_ab_kernel<<<768 + ablocks, 256>>>(x, W1l, W1r, Wskip, N);
    }
    {
        dim3 g(6, (N + 127) / 128);
        gemm_mma_kernel<<<g, 256>>>(b1l, b1r, bskip, dXL1, dXR1, dSKIP, N);
    }

    // ---- join: conv1 needs both GEMM outputs and CSR ----
    cudaStreamWaitEvent(0, evJoin, 0);

    conv1_csr_kernel<<<(N + 7) / 8, 256>>>(att1, bias1, gamma, beta,
                                           W2l, b2l, W2r, b2r, att2, N);
    conv2_csr_kernel<<<(N + 7) / 8, 256>>>(att2, bias2, out, N);
}

// round 15
// speedup vs baseline: 1.2820x; 1.0188x over previous
#include <cuda_runtime.h>
#include <cuda_fp16.h>
#include <math.h>
#include <stdint.h>

// Problem constants
#define DIN   256
#define HCc   256
#define NEG   0.2f
#define MAXN  50000
#define MAXE  1000000
#define MPAD  (MAXN + 128)

// ---------------- scratch (static device globals) --------------------------
__device__ __half g_XL1h[(long long)MAXN * HCc];   // conv1 xl in fp16 (gathered per edge)
__device__ float g_XR1[(long long)MAXN * HCc];
__device__ float g_SKIP[(long long)MAXN * HCc];
__device__ float g_XL2[MAXN * 2];
__device__ float g_XR2[MAXN * 2];
__device__ int   g_deg[MAXN];
__device__ int   g_rowptr[MAXN + 1];
__device__ int   g_cur[MAXN];
__device__ int   g_esrc[MAXE];
__device__ int   g_bsum[64];
__device__ int   g_boff[64];
__device__ int   g_is64;
// fp16 transposed weights (single-rounded): [sel][N=256][K=256]
__device__ __half g_BTf[3 * 256 * 256];
// fp16 2-term split A (x): [m][k]
__device__ __half g_AT_hi[(long long)MPAD * 256];
__device__ __half g_AT_lo[(long long)MPAD * 256];

// ---------------- small helpers ---------------------------------------------
__device__ __forceinline__ uint32_t smem_u32(const void* p) {
    uint32_t a;
    asm("{ .reg .u64 t; cvta.to.shared.u64 t, %1; cvt.u32.u64 %0, t; }"
        : "=r"(a) : "l"(p));
    return a;
}
__device__ __forceinline__ void ldsm_x4(uint32_t* r, uint32_t addr) {
    asm volatile("ldmatrix.sync.aligned.m8n8.x4.shared.b16 {%0,%1,%2,%3}, [%4];"
        : "=r"(r[0]), "=r"(r[1]), "=r"(r[2]), "=r"(r[3]) : "r"(addr));
}
__device__ __forceinline__ void mma_fp16(float* c, const uint32_t* a,
                                         uint32_t b0, uint32_t b1) {
    asm volatile(
        "mma.sync.aligned.m16n8k16.row.col.f32.f16.f16.f32 "
        "{%0,%1,%2,%3}, {%4,%5,%6,%7}, {%8,%9}, {%0,%1,%2,%3};"
        : "+f"(c[0]), "+f"(c[1]), "+f"(c[2]), "+f"(c[3])
        : "r"(a[0]), "r"(a[1]), "r"(a[2]), "r"(a[3]), "r"(b0), "r"(b1));
}
__device__ __forceinline__ void cp_async16(uint32_t dst, const void* src) {
    asm volatile("cp.async.ca.shared.global [%0], [%1], 16;"
                 :: "r"(dst), "l"(src) : "memory");
}
#define CP_COMMIT() asm volatile("cp.async.commit_group;" ::: "memory")
#define CP_WAIT0()  asm volatile("cp.async.wait_group 0;" ::: "memory")

__device__ __forceinline__ int ld_idx(const void* ei, long long pos, int is64) {
    if (is64) return (int)(((const long long*)ei)[pos]);
    return ((const int*)ei)[pos];
}

// ---------------- fused init: zero deg + edge dtype detect ------------------
__global__ void init_kernel(const unsigned int* __restrict__ w, int N) {
    int i = blockIdx.x * blockDim.x + threadIdx.x;
    if (i < N) g_deg[i] = 0;
    if (i == 0) {
        int ok = 1;
        #pragma unroll
        for (int j = 0; j < 32; j++) {
            if (w[2 * j + 1] != 0u) { ok = 0; break; }
        }
        g_is64 = ok;
    }
}

// ---------------- fused prep: B transpose (fp16) AND A split (fp16 hi/lo) ---
__global__ void prep_ab_kernel(const float* __restrict__ x,
                               const float* __restrict__ W0,
                               const float* __restrict__ W1,
                               const float* __restrict__ W2, int N) {
    int b = blockIdx.x;
    if (b < 768) {
        int s = b >> 8, k = b & 255, n = threadIdx.x;
        const float* W = (s == 0) ? W0 : (s == 1) ? W1 : W2;
        float v = W[k * 256 + n];
        g_BTf[(s * 256 + n) * 256 + k] = __float2half(v);
    } else {
        long long eb = (long long)(b - 768) * 1024 + threadIdx.x * 4;
        if (eb < (long long)N * 256) {
            float4 v = *(const float4*)(x + eb);
            float f[4] = {v.x, v.y, v.z, v.w};
            __half h[4], l[4];
            #pragma unroll
            for (int j = 0; j < 4; j++) {
                h[j] = __float2half(f[j]);
                l[j] = __float2half(f[j] - __half2float(h[j]));
            }
            *(ulonglong1*)(g_AT_hi + eb) = *(ulonglong1*)h;
            *(ulonglong1*)(g_AT_lo + eb) = *(ulonglong1*)l;
        }
    }
}

// ---------------- CSR build -------------------------------------------------
__global__ void hist_kernel(const void* __restrict__ ei, long long E) {
    long long e = (long long)blockIdx.x * blockDim.x + threadIdx.x;
    if (e >= E) return;
    int dst = ld_idx(ei, E + e, g_is64);
    atomicAdd(&g_deg[dst], 1);
}
__global__ __launch_bounds__(1024) void scanA_kernel(int N) {
    __shared__ int wsum[32];
    const int lane = threadIdx.x & 31, warp = threadIdx.x >> 5;
    int i = blockIdx.x * 1024 + threadIdx.x;
    int v = (i < N) ? g_deg[i] : 0;
    int x = v;
    #pragma unroll
    for (int o = 1; o < 32; o <<= 1) {
        int y = __shfl_up_sync(0xffffffffu, x, o);
        if (lane >= o) x += y;
    }
    if (lane == 31) wsum[warp] = x;
    __syncthreads();
    if (warp == 0) {
        int w = wsum[lane];
        #pragma unroll
        for (int o = 1; o < 32; o <<= 1) {
            int y = __shfl_up_sync(0xffffffffu, w, o);
            if (lane >= o) w += y;
        }
        wsum[lane] = w;
    }
    __syncthreads();
    int incl = x + (warp > 0 ? wsum[warp - 1] : 0);
    if (i < N) g_rowptr[i + 1] = incl;
    if (threadIdx.x == 1023) g_bsum[blockIdx.x] = incl;
}
__global__ void scanB_kernel(int B) {
    if (threadIdx.x == 0) {
        int acc = 0;
        for (int b = 0; b < B; b++) { int v = g_bsum[b]; g_boff[b] = acc; acc += v; }
    }
}
__global__ __launch_bounds__(1024) void scanC_kernel(int N) {
    int i = blockIdx.x * 1024 + threadIdx.x;
    if (i == 0) g_rowptr[0] = 0;
    if (i < N) {
        int r = g_rowptr[i + 1] + g_boff[blockIdx.x];
        g_rowptr[i + 1] = r;
        g_cur[i] = r - g_deg[i];
    }
}
__global__ void scatter_kernel(const void* __restrict__ ei, long long E) {
    long long e = (long long)blockIdx.x * blockDim.x + threadIdx.x;
    if (e >= E) return;
    int is64 = g_is64;
    int src = ld_idx(ei, e, is64);
    int dst = ld_idx(ei, E + e, is64);
    int pos = atomicAdd(&g_cur[dst], 1);
    g_esrc[pos] = src;
}

// ---------------- mma.sync fp16 2-term triple GEMM ---------------------------
// sel 0 (XL1) writes fp16; sel 1,2 write fp32.
#define PADK 24
#define ABUF (128 * PADK)
#define OPB  (ABUF * 2)
#define BUFB (OPB * 3)

__global__ __launch_bounds__(256, 2) void gemm_mma_kernel(
    const float* __restrict__ bias0, const float* __restrict__ bias1,
    const float* __restrict__ bias2,
    float* __restrict__ C1f, float* __restrict__ C2f,
    int M)
{
    __shared__ __half sm[2 * 3 * ABUF];   // 36KB

    const int sel = blockIdx.x >> 1;
    const int n0  = (blockIdx.x & 1) * 128;
    const int m0  = blockIdx.y * 128;
    const float* bias = (sel == 0) ? bias0 : (sel == 1) ? bias1 : bias2;
    float* Cf = (sel == 1) ? C1f : C2f;
    const __half* BTf = g_BTf + sel * 65536 + (long long)n0 * 256;

    const int tid  = threadIdx.x;
    const int lane = tid & 31;
    const int wid  = tid >> 5;
    const int wm0  = (wid >> 2) * 64;
    const int wn0  = (wid & 3) * 32;

    const int ar = tid >> 1;
    const int ak = (tid & 1) * 8;
    const __half* gAh = g_AT_hi + (long long)(m0 + ar) * 256 + ak;
    const __half* gAl = g_AT_lo + (long long)(m0 + ar) * 256 + ak;
    const __half* gBf = BTf + (long long)ar * 256 + ak;
    const uint32_t dFill = smem_u32(&sm[ar * PADK + ak]);

    uint32_t a_h[4], b_f[2];
    {
        int arow = lane & 15;
        int acol = (lane >> 4) * 8;
        #pragma unroll
        for (int fm = 0; fm < 4; fm++)
            a_h[fm] = smem_u32(&sm[(wm0 + fm * 16 + arow) * PADK + acol]);
        int brow = (lane & 7) + (lane >> 4) * 8;
        int bcol = ((lane >> 3) & 1) * 8;
        #pragma unroll
        for (int nb = 0; nb < 2; nb++)
            b_f[nb] = smem_u32(&sm[2 * ABUF + (wn0 + nb * 16 + brow) * PADK + bcol]);
    }

    float acc[16][4];
    #pragma unroll
    for (int i = 0; i < 16; i++)
        #pragma unroll
        for (int j = 0; j < 4; j++) acc[i][j] = 0.f;

    cp_async16(dFill,           gAh);
    cp_async16(dFill + OPB,     gAl);
    cp_async16(dFill + 2 * OPB, gBf);
    CP_COMMIT();
    CP_WAIT0();
    __syncthreads();

    int buf = 0;
    for (int ks = 0; ks < 256; ks += 16) {
        const int nb = buf ^ 1;
        const bool has_next = (ks + 16) < 256;
        if (has_next) {
            const uint32_t d = dFill + nb * BUFB;
            cp_async16(d,           gAh + ks + 16);
            cp_async16(d + OPB,     gAl + ks + 16);
            cp_async16(d + 2 * OPB, gBf + ks + 16);
            CP_COMMIT();
        }
        const uint32_t bofs = buf * BUFB;
        uint32_t AF[4][4], BF[2][4];
        #pragma unroll
        for (int fm = 0; fm < 4; fm++) ldsm_x4(AF[fm], a_h[fm] + bofs);
        ldsm_x4(BF[0], b_f[0] + bofs);
        ldsm_x4(BF[1], b_f[1] + bofs);
        #pragma unroll
        for (int fm = 0; fm < 4; fm++)
            #pragma unroll
            for (int fn = 0; fn < 4; fn++)
                mma_fp16(acc[fm * 4 + fn], AF[fm],
                         BF[fn >> 1][(fn & 1) * 2], BF[fn >> 1][(fn & 1) * 2 + 1]);
        #pragma unroll
        for (int fm = 0; fm < 4; fm++) ldsm_x4(AF[fm], a_h[fm] + bofs + OPB);
        #pragma unroll
        for (int fm = 0; fm < 4; fm++)
            #pragma unroll
            for (int fn = 0; fn < 4; fn++)
                mma_fp16(acc[fm * 4 + fn], AF[fm],
                         BF[fn >> 1][(fn & 1) * 2], BF[fn >> 1][(fn & 1) * 2 + 1]);
        if (has_next) CP_WAIT0();
        __syncthreads();
        buf = nb;
    }

    #pragma unroll
    for (int fm = 0; fm < 4; fm++) {
        int r0 = m0 + wm0 + fm * 16 + (lane >> 2);
        #pragma unroll
        for (int fn = 0; fn < 4; fn++) {
            int col = n0 + wn0 + fn * 8 + (lane & 3) * 2;
            float2 bv = *(const float2*)(bias + col);
            float* a4 = acc[fm * 4 + fn];
            float2 o0 = make_float2(a4[0] + bv.x, a4[1] + bv.y);
            float2 o1 = make_float2(a4[2] + bv.x, a4[3] + bv.y);
            int r1 = r0 + 8;
            if (sel == 0) {
                if (r0 < M) *(__half2*)(g_XL1h + (long long)r0 * 256 + col) =
                    __floats2half2_rn(o0.x, o0.y);
                if (r1 < M) *(__half2*)(g_XL1h + (long long)r1 * 256 + col) =
                    __floats2half2_rn(o1.x, o1.y);
            } else {
                if (r0 < M) *(float2*)(Cf + (long long)r0 * 256 + col) = o0;
                if (r1 < M) *(float2*)(Cf + (long long)r1 * 256 + col) = o1;
            }
        }
    }
}

// ------- fused conv1 CSR + softmax + skip + LN + ELU + conv2 projection ----
// One warp per dst node; xl gathered as fp16 (16B per lane per edge).
__device__ __forceinline__ void load_xl8(const __half* base, int lane, float* xl) {
    uint4 hv = *(const uint4*)(base + lane * 8);
    float2 f0 = __half22float2(*(__half2*)&hv.x);
    float2 f1 = __half22float2(*(__half2*)&hv.y);
    float2 f2 = __half22float2(*(__half2*)&hv.z);
    float2 f3 = __half22float2(*(__half2*)&hv.w);
    xl[0]=f0.x; xl[1]=f0.y; xl[2]=f1.x; xl[3]=f1.y;
    xl[4]=f2.x; xl[5]=f2.y; xl[6]=f3.x; xl[7]=f3.y;
}

__global__ __launch_bounds__(256) void conv1_csr_kernel(
    const float* __restrict__ att1, const float* __restrict__ bias1,
    const float* __restrict__ gamma, const float* __restrict__ beta,
    const float* __restrict__ W2l, const float* __restrict__ b2l,
    const float* __restrict__ W2r, const float* __restrict__ b2r,
    const float* __restrict__ att2, int N)
{
    const int n = blockIdx.x * 8 + (threadIdx.x >> 5);
    const int lane = threadIdx.x & 31;
    if (n >= N) return;

    float att6[8], att4[8];
    {
        float4 a0 = *(const float4*)(att1 + lane * 8);
        float4 a1 = *(const float4*)(att1 + lane * 8 + 4);
        float av[8] = {a0.x,a0.y,a0.z,a0.w,a1.x,a1.y,a1.z,a1.w};
        #pragma unroll
        for (int j = 0; j < 8; j++) { att6[j] = 0.6f * av[j]; att4[j] = 0.4f * av[j]; }
    }
    float xr[8];
    {
        const float* p = g_XR1 + (long long)n * HCc + lane * 8;
        float4 r0 = *(const float4*)p;
        float4 r1 = *(const float4*)(p + 4);
        xr[0]=r0.x; xr[1]=r0.y; xr[2]=r0.z; xr[3]=r0.w;
        xr[4]=r1.x; xr[5]=r1.y; xr[6]=r1.z; xr[7]=r1.w;
    }

    float acc[8], den;
    // self-loop
    {
        float xl[8];
        load_xl8(g_XL1h + (long long)n * HCc, lane, xl);
        float s6 = 0.f, s4 = 0.f;
        #pragma unroll
        for (int j = 0; j < 8; j++) {
            float e = xl[j] + xr[j];
            s6 = fmaf(e, att6[j], s6);
            s4 = fmaf(fabsf(e), att4[j], s4);
        }
        float s = s6 + s4;
        s += __shfl_xor_sync(0xffffffffu, s, 1);
        s += __shfl_xor_sync(0xffffffffu, s, 2);
        s += __shfl_xor_sync(0xffffffffu, s, 4);
        float ex = __expf(s);
        den = ex;
        #pragma unroll
        for (int j = 0; j < 8; j++) acc[j] = ex * xl[j];
    }

    const int row0 = g_rowptr[n];
    const int row1 = g_rowptr[n + 1];
    int i = row0;
    for (; i + 1 < row1; i += 2) {
        int srcA = g_esrc[i];
        int srcB = g_esrc[i + 1];
        float xlA[8], xlB[8];
        load_xl8(g_XL1h + (long long)srcA * HCc, lane, xlA);
        load_xl8(g_XL1h + (long long)srcB * HCc, lane, xlB);
        float sA6 = 0.f, sA4 = 0.f, sB6 = 0.f, sB4 = 0.f;
        #pragma unroll
        for (int j = 0; j < 8; j++) {
            float eA = xlA[j] + xr[j];
            float eB = xlB[j] + xr[j];
            sA6 = fmaf(eA, att6[j], sA6);
            sA4 = fmaf(fabsf(eA), att4[j], sA4);
            sB6 = fmaf(eB, att6[j], sB6);
            sB4 = fmaf(fabsf(eB), att4[j], sB4);
        }
        float sA = sA6 + sA4, sB = sB6 + sB4;
        #pragma unroll
        for (int o = 1; o <= 4; o <<= 1) {
            sA += __shfl_xor_sync(0xffffffffu, sA, o);
            sB += __shfl_xor_sync(0xffffffffu, sB, o);
        }
        float exA = __expf(sA);
        float exB = __expf(sB);
        den += exA + exB;
        #pragma unroll
        for (int j = 0; j < 8; j++) {
            acc[j] = fmaf(exA, xlA[j], acc[j]);
            acc[j] = fmaf(exB, xlB[j], acc[j]);
        }
    }
    if (i < row1) {
        int src = g_esrc[i];
        float xl[8];
        load_xl8(g_XL1h + (long long)src * HCc, lane, xl);
        float s6 = 0.f, s4 = 0.f;
        #pragma unroll
        for (int j = 0; j < 8; j++) {
            float e = xl[j] + xr[j];
            s6 = fmaf(e, att6[j], s6);
            s4 = fmaf(fabsf(e), att4[j], s4);
        }
        float s = s6 + s4;
        s += __shfl_xor_sync(0xffffffffu, s, 1);
        s += __shfl_xor_sync(0xffffffffu, s, 2);
        s += __shfl_xor_sync(0xffffffffu, s, 4);
        float ex = __expf(s);
        den += ex;
        #pragma unroll
        for (int j = 0; j < 8; j++) acc[j] = fmaf(ex, xl[j], acc[j]);
    }

    const float dinv = 1.0f / den;
    float v[8];
    {
        const float* sp = g_SKIP + (long long)n * HCc + lane * 8;
        float4 s0 = *(const float4*)sp;
        float4 s1 = *(const float4*)(sp + 4);
        float4 b0 = *(const float4*)(bias1 + lane * 8);
        float4 b1 = *(const float4*)(bias1 + lane * 8 + 4);
        float sk[8] = {s0.x,s0.y,s0.z,s0.w,s1.x,s1.y,s1.z,s1.w};
        float bb[8] = {b0.x,b0.y,b0.z,b0.w,b1.x,b1.y,b1.z,b1.w};
        #pragma unroll
        for (int j = 0; j < 8; j++) v[j] = acc[j] * dinv + bb[j] + sk[j];
    }

    float t = 0.f;
    #pragma unroll
    for (int j = 0; j < 8; j++) t += v[j];
    #pragma unroll
    for (int o = 16; o > 0; o >>= 1) t += __shfl_xor_sync(0xffffffffu, t, o);
    const float mu = t * (1.0f / 256.0f);
    float t2 = 0.f;
    #pragma unroll
    for (int j = 0; j < 8; j++) { float d = v[j] - mu; t2 = fmaf(d, d, t2); }
    #pragma unroll
    for (int o = 16; o > 0; o >>= 1) t2 += __shfl_xor_sync(0xffffffffu, t2, o);
    const float rstd = rsqrtf(t2 * (1.0f / 256.0f) + 1e-5f);

    float h[8];
    {
        float4 g0 = *(const float4*)(gamma + lane * 8);
        float4 g1 = *(const float4*)(gamma + lane * 8 + 4);
        float4 e0 = *(const float4*)(beta + lane * 8);
        float4 e1 = *(const float4*)(beta + lane * 8 + 4);
        float gg[8] = {g0.x,g0.y,g0.z,g0.w,g1.x,g1.y,g1.z,g1.w};
        float be[8] = {e0.x,e0.y,e0.z,e0.w,e1.x,e1.y,e1.z,e1.w};
        #pragma unroll
        for (int j = 0; j < 8; j++) {
            float hh = (v[j] - mu) * rstd * gg[j] + be[j];
            h[j] = hh > 0.f ? hh : expm1f(hh);
        }
    }

    float p0 = 0.f, p1 = 0.f, p2 = 0.f, p3 = 0.f;
    {
        const float* wl = W2l + lane * 16;
        const float* wr = W2r + lane * 16;
        float4 wl0 = *(const float4*)wl;
        float4 wl1 = *(const float4*)(wl + 4);
        float4 wl2 = *(const float4*)(wl + 8);
        float4 wl3 = *(const float4*)(wl + 12);
        float4 wr0 = *(const float4*)wr;
        float4 wr1 = *(const float4*)(wr + 4);
        float4 wr2 = *(const float4*)(wr + 8);
        float4 wr3 = *(const float4*)(wr + 12);
        float wlv[16] = {wl0.x,wl0.y,wl0.z,wl0.w, wl1.x,wl1.y,wl1.z,wl1.w,
                         wl2.x,wl2.y,wl2.z,wl2.w, wl3.x,wl3.y,wl3.z,wl3.w};
        float wrv[16] = {wr0.x,wr0.y,wr0.z,wr0.w, wr1.x,wr1.y,wr1.z,wr1.w,
                         wr2.x,wr2.y,wr2.z,wr2.w, wr3.x,wr3.y,wr3.z,wr3.w};
        #pragma unroll
        for (int j = 0; j < 8; j++) {
            p0 = fmaf(h[j], wlv[2 * j + 0], p0);
            p1 = fmaf(h[j], wlv[2 * j + 1], p1);
            p2 = fmaf(h[j], wrv[2 * j + 0], p2);
            p3 = fmaf(h[j], wrv[2 * j + 1], p3);
        }
    }
    #pragma unroll
    for (int o = 16; o > 0; o >>= 1) {
        p0 += __shfl_xor_sync(0xffffffffu, p0, o);
        p1 += __shfl_xor_sync(0xffffffffu, p1, o);
        p2 += __shfl_xor_sync(0xffffffffu, p2, o);
        p3 += __shfl_xor_sync(0xffffffffu, p3, o);
    }
    if (lane == 0) {
        float2 xl2, xr2;
        xl2.x = p0 + b2l[0]; xl2.y = p1 + b2l[1];
        xr2.x = p2 + b2r[0]; xr2.y = p3 + b2r[1];
        *(float2*)&g_XL2[n * 2] = xl2;
        *(float2*)&g_XR2[n * 2] = xr2;
    }
}

// ------------- conv2 CSR + final output (warp per node) --------------------
__global__ __launch_bounds__(256) void conv2_csr_kernel(
    const float* __restrict__ att2, const float* __restrict__ bias2,
    float* __restrict__ out, int N)
{
    const int n = blockIdx.x * 8 + (threadIdx.x >> 5);
    const int lane = threadIdx.x & 31;
    if (n >= N) return;
    const float a0 = att2[0], a1 = att2[1];
    const float a06 = 0.6f * a0, a04 = 0.4f * a0;
    const float a16 = 0.6f * a1, a14 = 0.4f * a1;
    float2 xls = *(const float2*)&g_XL2[n * 2];
    float2 xr  = *(const float2*)&g_XR2[n * 2];

    float den = 0.f, s0 = 0.f, s1 = 0.f;
    const int row0 = g_rowptr[n], row1 = g_rowptr[n + 1];
    for (int i = row0 + lane; i < row1; i += 32) {
        int src = g_esrc[i];
        float2 xl = *(const float2*)&g_XL2[src * 2];
        float f0 = xl.x + xr.x;
        float f1 = xl.y + xr.y;
        float s = fmaf(f0, a06, fmaf(fabsf(f0), a04,
                  fmaf(f1, a16, fabsf(f1) * a14)));
        float exi = __expf(s);
        den += exi;
        s0 = fmaf(exi, xl.x, s0);
        s1 = fmaf(exi, xl.y, s1);
    }
    #pragma unroll
    for (int o = 16; o > 0; o >>= 1) {
        den += __shfl_xor_sync(0xffffffffu, den, o);
        s0  += __shfl_xor_sync(0xffffffffu, s0, o);
        s1  += __shfl_xor_sync(0xffffffffu, s1, o);
    }
    if (lane == 0) {
        float f0 = xls.x + xr.x;
        float f1 = xls.y + xr.y;
        float s = fmaf(f0, a06, fmaf(fabsf(f0), a04,
                  fmaf(f1, a16, fabsf(f1) * a14)));
        float ex = __expf(s);
        den += ex;
        s0 = fmaf(ex, xls.x, s0);
        s1 = fmaf(ex, xls.y, s1);
        float dinv = 1.0f / den;
        float2 o;
        o.x = s0 * dinv + bias2[0];
        o.y = s1 * dinv + bias2[1];
        *(float2*)(out + n * 2) = o;
    }
}

// ---------------------------------------------------------------------------
extern "C" void kernel_launch(void* const* d_in, const int* in_sizes, int n_in,
                              void* d_out, int out_size) {
    const float* x     = (const float*)d_in[0];
    const void*  ei    = d_in[1];
    const float* W1l   = (const float*)d_in[2];
    const float* b1l   = (const float*)d_in[3];
    const float* W1r   = (const float*)d_in[4];
    const float* b1r   = (const float*)d_in[5];
    const float* att1  = (const float*)d_in[6];
    const float* bias1 = (const float*)d_in[7];
    const float* W2l   = (const float*)d_in[8];
    const float* b2l   = (const float*)d_in[9];
    const float* W2r   = (const float*)d_in[10];
    const float* b2r   = (const float*)d_in[11];
    const float* att2  = (const float*)d_in[12];
    const float* bias2 = (const float*)d_in[13];
    const float* Wskip = (const float*)d_in[14];
    const float* bskip = (const float*)d_in[15];
    const float* gamma = (const float*)d_in[16];
    const float* beta  = (const float*)d_in[17];
    float* out = (float*)d_out;

    const int       N = in_sizes[0] / DIN;            // 50000
    const long long E = (long long)in_sizes[1] / 2;   // 800000

    float *dXR1, *dSKIP;
    cudaGetSymbolAddress((void**)&dXR1, g_XR1);
    cudaGetSymbolAddress((void**)&dSKIP, g_SKIP);

    // one-time infra
    static cudaStream_t s2 = nullptr;
    static cudaEvent_t evFork = nullptr, evJoin = nullptr;
    if (s2 == nullptr) {
        cudaStreamCreateWithFlags(&s2, cudaStreamNonBlocking);
        cudaEventCreateWithFlags(&evFork, cudaEventDisableTiming);
        cudaEventCreateWithFlags(&evJoin, cudaEventDisableTiming);
    }

    // ---- stage 0 (main stream): init ----
    init_kernel<<<(N + 255) / 256, 256>>>((const unsigned int*)ei, N);

    // ---- fork: CSR build on s2, concurrent with prep+GEMM on main ----
    cudaEventRecord(evFork, 0);
    cudaStreamWaitEvent(s2, evFork, 0);

    const int SB = (N + 1023) / 1024;
    hist_kernel<<<(int)((E + 255) / 256), 256, 0, s2>>>(ei, E);
    scanA_kernel<<<SB, 1024, 0, s2>>>(N);
    scanB_kernel<<<1, 32, 0, s2>>>(SB);
    scanC_kernel<<<SB, 1024, 0, s2>>>(N);
    scatter_kernel<<<(int)((E + 255) / 256), 256, 0, s2>>>(ei, E);
    cudaEventRecord(evJoin, s2);

    // main stream: prep + GEMM
    {
        int ablocks = (int)(((long long)N * 256 + 1023) / 1024);
        prep_ab_kernel<<<768 + ablocks, 256>>>(x, W1l, W1r, Wskip, N);
    }
    {
        dim3 g(6, (N + 127) / 128);
        gemm_mma_kernel<<<g, 256>>>(b1l, b1r, bskip, dXR1, dSKIP, N);
    }

    // ---- join ----
    cudaStreamWaitEvent(0, evJoin, 0);

    conv1_csr_kernel<<<(N + 7) / 8, 256>>>(att1, bias1, gamma, beta,
                                           W2l, b2l, W2r, b2r, att2, N);
    conv2_csr_kernel<<<(N + 7) / 8, 256>>>(att2, bias2, out, N);
}

// round 16
// speedup vs baseline: 1.3568x; 1.0583x over previous
#include <cuda_runtime.h>
#include <cuda_fp16.h>
#include <math.h>
#include <stdint.h>

// Problem constants
#define DIN   256
#define HCc   256
#define NEG   0.2f
#define MAXN  50000
#define MAXE  1000000
#define MPAD  (MAXN + 128)

// ---------------- scratch (static device globals) --------------------------
__device__ __half g_XL1h[(long long)MAXN * HCc];
__device__ float g_XR1[(long long)MAXN * HCc];
__device__ float g_SKIP[(long long)MAXN * HCc];
__device__ float g_XL2[MAXN * 2];
__device__ float g_XR2[MAXN * 2];
__device__ int   g_deg[MAXN];
__device__ int   g_rowptr[MAXN + 1];
__device__ int   g_cur[MAXN];
__device__ int   g_esrc[MAXE];
__device__ int   g_bsum[64];
__device__ int   g_boff[64];
__device__ int   g_is64;
__device__ __half g_BTf[3 * 256 * 256];
__device__ __half g_AT_hi[(long long)MPAD * 256];
__device__ __half g_AT_lo[(long long)MPAD * 256];

// ---------------- small helpers ---------------------------------------------
__device__ __forceinline__ uint32_t smem_u32(const void* p) {
    uint32_t a;
    asm("{ .reg .u64 t; cvta.to.shared.u64 t, %1; cvt.u32.u64 %0, t; }"
        : "=r"(a) : "l"(p));
    return a;
}
__device__ __forceinline__ void ldsm_x4(uint32_t* r, uint32_t addr) {
    asm volatile("ldmatrix.sync.aligned.m8n8.x4.shared.b16 {%0,%1,%2,%3}, [%4];"
        : "=r"(r[0]), "=r"(r[1]), "=r"(r[2]), "=r"(r[3]) : "r"(addr));
}
__device__ __forceinline__ void mma_fp16(float* c, const uint32_t* a,
                                         uint32_t b0, uint32_t b1) {
    asm volatile(
        "mma.sync.aligned.m16n8k16.row.col.f32.f16.f16.f32 "
        "{%0,%1,%2,%3}, {%4,%5,%6,%7}, {%8,%9}, {%0,%1,%2,%3};"
        : "+f"(c[0]), "+f"(c[1]), "+f"(c[2]), "+f"(c[3])
        : "r"(a[0]), "r"(a[1]), "r"(a[2]), "r"(a[3]), "r"(b0), "r"(b1));
}
__device__ __forceinline__ void cp_async16(uint32_t dst, const void* src) {
    asm volatile("cp.async.ca.shared.global [%0], [%1], 16;"
                 :: "r"(dst), "l"(src) : "memory");
}
#define CP_COMMIT() asm volatile("cp.async.commit_group;" ::: "memory")
#define CP_WAIT0()  asm volatile("cp.async.wait_group 0;" ::: "memory")

__device__ __forceinline__ int ld_idx(const void* ei, long long pos, int is64) {
    if (is64) return (int)(((const long long*)ei)[pos]);
    return ((const int*)ei)[pos];
}

// ---------------- fused init: zero deg + edge dtype detect ------------------
__global__ void init_kernel(const unsigned int* __restrict__ w, int N) {
    int i = blockIdx.x * blockDim.x + threadIdx.x;
    if (i < N) g_deg[i] = 0;
    if (i == 0) {
        int ok = 1;
        #pragma unroll
        for (int j = 0; j < 32; j++) {
            if (w[2 * j + 1] != 0u) { ok = 0; break; }
        }
        g_is64 = ok;
    }
}

// ---------------- fused prep: B transpose (fp16) AND A split (fp16 hi/lo) ---
__global__ void prep_ab_kernel(const float* __restrict__ x,
                               const float* __restrict__ W0,
                               const float* __restrict__ W1,
                               const float* __restrict__ W2, int N) {
    int b = blockIdx.x;
    if (b < 768) {
        int s = b >> 8, k = b & 255, n = threadIdx.x;
        const float* W = (s == 0) ? W0 : (s == 1) ? W1 : W2;
        float v = W[k * 256 + n];
        g_BTf[(s * 256 + n) * 256 + k] = __float2half(v);
    } else {
        long long eb = (long long)(b - 768) * 1024 + threadIdx.x * 4;
        if (eb < (long long)N * 256) {
            float4 v = *(const float4*)(x + eb);
            float f[4] = {v.x, v.y, v.z, v.w};
            __half h[4], l[4];
            #pragma unroll
            for (int j = 0; j < 4; j++) {
                h[j] = __float2half(f[j]);
                l[j] = __float2half(f[j] - __half2float(h[j]));
            }
            *(ulonglong1*)(g_AT_hi + eb) = *(ulonglong1*)h;
            *(ulonglong1*)(g_AT_lo + eb) = *(ulonglong1*)l;
        }
    }
}

// ---------------- CSR build -------------------------------------------------
__global__ void hist_kernel(const void* __restrict__ ei, long long E) {
    long long e = (long long)blockIdx.x * blockDim.x + threadIdx.x;
    if (e >= E) return;
    int dst = ld_idx(ei, E + e, g_is64);
    atomicAdd(&g_deg[dst], 1);
}
__global__ __launch_bounds__(1024) void scanA_kernel(int N) {
    __shared__ int wsum[32];
    const int lane = threadIdx.x & 31, warp = threadIdx.x >> 5;
    int i = blockIdx.x * 1024 + threadIdx.x;
    int v = (i < N) ? g_deg[i] : 0;
    int x = v;
    #pragma unroll
    for (int o = 1; o < 32; o <<= 1) {
        int y = __shfl_up_sync(0xffffffffu, x, o);
        if (lane >= o) x += y;
    }
    if (lane == 31) wsum[warp] = x;
    __syncthreads();
    if (warp == 0) {
        int w = wsum[lane];
        #pragma unroll
        for (int o = 1; o < 32; o <<= 1) {
            int y = __shfl_up_sync(0xffffffffu, w, o);
            if (lane >= o) w += y;
        }
        wsum[lane] = w;
    }
    __syncthreads();
    int incl = x + (warp > 0 ? wsum[warp - 1] : 0);
    if (i < N) g_rowptr[i + 1] = incl;
    if (threadIdx.x == 1023) g_bsum[blockIdx.x] = incl;
}
__global__ void scanB_kernel(int B) {
    if (threadIdx.x == 0) {
        int acc = 0;
        for (int b = 0; b < B; b++) { int v = g_bsum[b]; g_boff[b] = acc; acc += v; }
    }
}
__global__ __launch_bounds__(1024) void scanC_kernel(int N) {
    int i = blockIdx.x * 1024 + threadIdx.x;
    if (i == 0) g_rowptr[0] = 0;
    if (i < N) {
        int r = g_rowptr[i + 1] + g_boff[blockIdx.x];
        g_rowptr[i + 1] = r;
        g_cur[i] = r - g_deg[i];
    }
}
__global__ void scatter_kernel(const void* __restrict__ ei, long long E) {
    long long e = (long long)blockIdx.x * blockDim.x + threadIdx.x;
    if (e >= E) return;
    int is64 = g_is64;
    int src = ld_idx(ei, e, is64);
    int dst = ld_idx(ei, E + e, is64);
    int pos = atomicAdd(&g_cur[dst], 1);
    g_esrc[pos] = src;
}

// ---------------- mma.sync fp16 triple GEMM ---------------------------------
// sel 0 (XL1, fp16 out, 2-term), sel 1 (XR1, fp32, 2-term), sel 2 (SKIP, fp32,
// 1-term: skip enters additively pre-LN, fp16 single-round is enough).
#define PADK 24
#define ABUF (128 * PADK)
#define OPB  (ABUF * 2)
#define BUFB (OPB * 3)

__global__ __launch_bounds__(256, 2) void gemm_mma_kernel(
    const float* __restrict__ bias0, const float* __restrict__ bias1,
    const float* __restrict__ bias2,
    float* __restrict__ C1f, float* __restrict__ C2f,
    int M)
{
    __shared__ __half sm[2 * 3 * ABUF];   // 36KB

    const int sel = blockIdx.x >> 1;
    const int n0  = (blockIdx.x & 1) * 128;
    const int m0  = blockIdx.y * 128;
    const float* bias = (sel == 0) ? bias0 : (sel == 1) ? bias1 : bias2;
    float* Cf = (sel == 1) ? C1f : C2f;
    const __half* BTf = g_BTf + sel * 65536 + (long long)n0 * 256;
    const bool two_term = (sel != 2);

    const int tid  = threadIdx.x;
    const int lane = tid & 31;
    const int wid  = tid >> 5;
    const int wm0  = (wid >> 2) * 64;
    const int wn0  = (wid & 3) * 32;

    const int ar = tid >> 1;
    const int ak = (tid & 1) * 8;
    const __half* gAh = g_AT_hi + (long long)(m0 + ar) * 256 + ak;
    const __half* gAl = g_AT_lo + (long long)(m0 + ar) * 256 + ak;
    const __half* gBf = BTf + (long long)ar * 256 + ak;
    const uint32_t dFill = smem_u32(&sm[ar * PADK + ak]);

    uint32_t a_h[4], b_f[2];
    {
        int arow = lane & 15;
        int acol = (lane >> 4) * 8;
        #pragma unroll
        for (int fm = 0; fm < 4; fm++)
            a_h[fm] = smem_u32(&sm[(wm0 + fm * 16 + arow) * PADK + acol]);
        int brow = (lane & 7) + (lane >> 4) * 8;
        int bcol = ((lane >> 3) & 1) * 8;
        #pragma unroll
        for (int nb = 0; nb < 2; nb++)
            b_f[nb] = smem_u32(&sm[2 * ABUF + (wn0 + nb * 16 + brow) * PADK + bcol]);
    }

    float acc[16][4];
    #pragma unroll
    for (int i = 0; i < 16; i++)
        #pragma unroll
        for (int j = 0; j < 4; j++) acc[i][j] = 0.f;

    cp_async16(dFill,           gAh);
    if (two_term) cp_async16(dFill + OPB, gAl);
    cp_async16(dFill + 2 * OPB, gBf);
    CP_COMMIT();
    CP_WAIT0();
    __syncthreads();

    int buf = 0;
    for (int ks = 0; ks < 256; ks += 16) {
        const int nb = buf ^ 1;
        const bool has_next = (ks + 16) < 256;
        if (has_next) {
            const uint32_t d = dFill + nb * BUFB;
            cp_async16(d,           gAh + ks + 16);
            if (two_term) cp_async16(d + OPB, gAl + ks + 16);
            cp_async16(d + 2 * OPB, gBf + ks + 16);
            CP_COMMIT();
        }
        const uint32_t bofs = buf * BUFB;
        uint32_t AF[4][4], BF[2][4];
        #pragma unroll
        for (int fm = 0; fm < 4; fm++) ldsm_x4(AF[fm], a_h[fm] + bofs);
        ldsm_x4(BF[0], b_f[0] + bofs);
        ldsm_x4(BF[1], b_f[1] + bofs);
        #pragma unroll
        for (int fm = 0; fm < 4; fm++)
            #pragma unroll
            for (int fn = 0; fn < 4; fn++)
                mma_fp16(acc[fm * 4 + fn], AF[fm],
                         BF[fn >> 1][(fn & 1) * 2], BF[fn >> 1][(fn & 1) * 2 + 1]);
        if (two_term) {
            #pragma unroll
            for (int fm = 0; fm < 4; fm++) ldsm_x4(AF[fm], a_h[fm] + bofs + OPB);
            #pragma unroll
            for (int fm = 0; fm < 4; fm++)
                #pragma unroll
                for (int fn = 0; fn < 4; fn++)
                    mma_fp16(acc[fm * 4 + fn], AF[fm],
                             BF[fn >> 1][(fn & 1) * 2], BF[fn >> 1][(fn & 1) * 2 + 1]);
        }
        if (has_next) CP_WAIT0();
        __syncthreads();
        buf = nb;
    }

    #pragma unroll
    for (int fm = 0; fm < 4; fm++) {
        int r0 = m0 + wm0 + fm * 16 + (lane >> 2);
        #pragma unroll
        for (int fn = 0; fn < 4; fn++) {
            int col = n0 + wn0 + fn * 8 + (lane & 3) * 2;
            float2 bv = *(const float2*)(bias + col);
            float* a4 = acc[fm * 4 + fn];
            float2 o0 = make_float2(a4[0] + bv.x, a4[1] + bv.y);
            float2 o1 = make_float2(a4[2] + bv.x, a4[3] + bv.y);
            int r1 = r0 + 8;
            if (sel == 0) {
                if (r0 < M) *(__half2*)(g_XL1h + (long long)r0 * 256 + col) =
                    __floats2half2_rn(o0.x, o0.y);
                if (r1 < M) *(__half2*)(g_XL1h + (long long)r1 * 256 + col) =
                    __floats2half2_rn(o1.x, o1.y);
            } else {
                if (r0 < M) *(float2*)(Cf + (long long)r0 * 256 + col) = o0;
                if (r1 < M) *(float2*)(Cf + (long long)r1 * 256 + col) = o1;
            }
        }
    }
}

// ------- fused conv1 CSR + softmax + skip + LN + ELU + conv2 projection ----
// One warp per dst node; xl gathered as fp16. Register cap -> 4 CTAs/SM so
// the gather latency is covered; epilogue may spill (runs once per node).
__device__ __forceinline__ void load_xl8(const __half* base, int lane, float* xl) {
    uint4 hv = *(const uint4*)(base + lane * 8);
    float2 f0 = __half22float2(*(__half2*)&hv.x);
    float2 f1 = __half22float2(*(__half2*)&hv.y);
    float2 f2 = __half22float2(*(__half2*)&hv.z);
    float2 f3 = __half22float2(*(__half2*)&hv.w);
    xl[0]=f0.x; xl[1]=f0.y; xl[2]=f1.x; xl[3]=f1.y;
    xl[4]=f2.x; xl[5]=f2.y; xl[6]=f3.x; xl[7]=f3.y;
}

__global__ __launch_bounds__(256, 4) void conv1_csr_kernel(
    const float* __restrict__ att1, const float* __restrict__ bias1,
    const float* __restrict__ gamma, const float* __restrict__ beta,
    const float* __restrict__ W2l, const float* __restrict__ b2l,
    const float* __restrict__ W2r, const float* __restrict__ b2r,
    const float* __restrict__ att2, int N)
{
    const int n = blockIdx.x * 8 + (threadIdx.x >> 5);
    const int lane = threadIdx.x & 31;
    if (n >= N) return;

    float att6[8], att4[8];
    {
        float4 a0 = *(const float4*)(att1 + lane * 8);
        float4 a1 = *(const float4*)(att1 + lane * 8 + 4);
        float av[8] = {a0.x,a0.y,a0.z,a0.w,a1.x,a1.y,a1.z,a1.w};
        #pragma unroll
        for (int j = 0; j < 8; j++) { att6[j] = 0.6f * av[j]; att4[j] = 0.4f * av[j]; }
    }
    float xr[8];
    {
        const float* p = g_XR1 + (long long)n * HCc + lane * 8;
        float4 r0 = *(const float4*)p;
        float4 r1 = *(const float4*)(p + 4);
        xr[0]=r0.x; xr[1]=r0.y; xr[2]=r0.z; xr[3]=r0.w;
        xr[4]=r1.x; xr[5]=r1.y; xr[6]=r1.z; xr[7]=r1.w;
    }

    float acc[8], den;
    {
        float xl[8];
        load_xl8(g_XL1h + (long long)n * HCc, lane, xl);
        float s6 = 0.f, s4 = 0.f;
        #pragma unroll
        for (int j = 0; j < 8; j++) {
            float e = xl[j] + xr[j];
            s6 = fmaf(e, att6[j], s6);
            s4 = fmaf(fabsf(e), att4[j], s4);
        }
        float s = s6 + s4;
        s += __shfl_xor_sync(0xffffffffu, s, 1);
        s += __shfl_xor_sync(0xffffffffu, s, 2);
        s += __shfl_xor_sync(0xffffffffu, s, 4);
        float ex = __expf(s);
        den = ex;
        #pragma unroll
        for (int j = 0; j < 8; j++) acc[j] = ex * xl[j];
    }

    const int row0 = g_rowptr[n];
    const int row1 = g_rowptr[n + 1];
    int i = row0;
    for (; i + 1 < row1; i += 2) {
        int srcA = g_esrc[i];
        int srcB = g_esrc[i + 1];
        float xlA[8], xlB[8];
        load_xl8(g_XL1h + (long long)srcA * HCc, lane, xlA);
        load_xl8(g_XL1h + (long long)srcB * HCc, lane, xlB);
        float sA6 = 0.f, sA4 = 0.f, sB6 = 0.f, sB4 = 0.f;
        #pragma unroll
        for (int j = 0; j < 8; j++) {
            float eA = xlA[j] + xr[j];
            float eB = xlB[j] + xr[j];
            sA6 = fmaf(eA, att6[j], sA6);
            sA4 = fmaf(fabsf(eA), att4[j], sA4);
            sB6 = fmaf(eB, att6[j], sB6);
            sB4 = fmaf(fabsf(eB), att4[j], sB4);
        }
        float sA = sA6 + sA4, sB = sB6 + sB4;
        #pragma unroll
        for (int o = 1; o <= 4; o <<= 1) {
            sA += __shfl_xor_sync(0xffffffffu, sA, o);
            sB += __shfl_xor_sync(0xffffffffu, sB, o);
        }
        float exA = __expf(sA);
        float exB = __expf(sB);
        den += exA + exB;
        #pragma unroll
        for (int j = 0; j < 8; j++) {
            acc[j] = fmaf(exA, xlA[j], acc[j]);
            acc[j] = fmaf(exB, xlB[j], acc[j]);
        }
    }
    if (i < row1) {
        int src = g_esrc[i];
        float xl[8];
        load_xl8(g_XL1h + (long long)src * HCc, lane, xl);
        float s6 = 0.f, s4 = 0.f;
        #pragma unroll
        for (int j = 0; j < 8; j++) {
            float e = xl[j] + xr[j];
            s6 = fmaf(e, att6[j], s6);
            s4 = fmaf(fabsf(e), att4[j], s4);
        }
        float s = s6 + s4;
        s += __shfl_xor_sync(0xffffffffu, s, 1);
        s += __shfl_xor_sync(0xffffffffu, s, 2);
        s += __shfl_xor_sync(0xffffffffu, s, 4);
        float ex = __expf(s);
        den += ex;
        #pragma unroll
        for (int j = 0; j < 8; j++) acc[j] = fmaf(ex, xl[j], acc[j]);
    }

    const float dinv = 1.0f / den;
    float v[8];
    {
        const float* sp = g_SKIP + (long long)n * HCc + lane * 8;
        float4 s0 = *(const float4*)sp;
        float4 s1 = *(const float4*)(sp + 4);
        float4 b0 = *(const float4*)(bias1 + lane * 8);
        float4 b1 = *(const float4*)(bias1 + lane * 8 + 4);
        float sk[8] = {s0.x,s0.y,s0.z,s0.w,s1.x,s1.y,s1.z,s1.w};
        float bb[8] = {b0.x,b0.y,b0.z,b0.w,b1.x,b1.y,b1.z,b1.w};
        #pragma unroll
        for (int j = 0; j < 8; j++) v[j] = acc[j] * dinv + bb[j] + sk[j];
    }

    float t = 0.f;
    #pragma unroll
    for (int j = 0; j < 8; j++) t += v[j];
    #pragma unroll
    for (int o = 16; o > 0; o >>= 1) t += __shfl_xor_sync(0xffffffffu, t, o);
    const float mu = t * (1.0f / 256.0f);
    float t2 = 0.f;
    #pragma unroll
    for (int j = 0; j < 8; j++) { float d = v[j] - mu; t2 = fmaf(d, d, t2); }
    #pragma unroll
    for (int o = 16; o > 0; o >>= 1) t2 += __shfl_xor_sync(0xffffffffu, t2, o);
    const float rstd = rsqrtf(t2 * (1.0f / 256.0f) + 1e-5f);

    float h[8];
    {
        float4 g0 = *(const float4*)(gamma + lane * 8);
        float4 g1 = *(const float4*)(gamma + lane * 8 + 4);
        float4 e0 = *(const float4*)(beta + lane * 8);
        float4 e1 = *(const float4*)(beta + lane * 8 + 4);
        float gg[8] = {g0.x,g0.y,g0.z,g0.w,g1.x,g1.y,g1.z,g1.w};
        float be[8] = {e0.x,e0.y,e0.z,e0.w,e1.x,e1.y,e1.z,e1.w};
        #pragma unroll
        for (int j = 0; j < 8; j++) {
            float hh = (v[j] - mu) * rstd * gg[j] + be[j];
            h[j] = hh > 0.f ? hh : expm1f(hh);
        }
    }

    float p0 = 0.f, p1 = 0.f, p2 = 0.f, p3 = 0.f;
    {
        const float* wl = W2l + lane * 16;
        const float* wr = W2r + lane * 16;
        float4 wl0 = *(const float4*)wl;
        float4 wl1 = *(const float4*)(wl + 4);
        float4 wl2 = *(const float4*)(wl + 8);
        float4 wl3 = *(const float4*)(wl + 12);
        float4 wr0 = *(const float4*)wr;
        float4 wr1 = *(const float4*)(wr + 4);
        float4 wr2 = *(const float4*)(wr + 8);
        float4 wr3 = *(const float4*)(wr + 12);
        float wlv[16] = {wl0.x,wl0.y,wl0.z,wl0.w, wl1.x,wl1.y,wl1.z,wl1.w,
                         wl2.x,wl2.y,wl2.z,wl2.w, wl3.x,wl3.y,wl3.z,wl3.w};
        float wrv[16] = {wr0.x,wr0.y,wr0.z,wr0.w, wr1.x,wr1.y,wr1.z,wr1.w,
                         wr2.x,wr2.y,wr2.z,wr2.w, wr3.x,wr3.y,wr3.z,wr3.w};
        #pragma unroll
        for (int j = 0; j < 8; j++) {
            p0 = fmaf(h[j], wlv[2 * j + 0], p0);
            p1 = fmaf(h[j], wlv[2 * j + 1], p1);
            p2 = fmaf(h[j], wrv[2 * j + 0], p2);
            p3 = fmaf(h[j], wrv[2 * j + 1], p3);
        }
    }
    #pragma unroll
    for (int o = 16; o > 0; o >>= 1) {
        p0 += __shfl_xor_sync(0xffffffffu, p0, o);
        p1 += __shfl_xor_sync(0xffffffffu, p1, o);
        p2 += __shfl_xor_sync(0xffffffffu, p2, o);
        p3 += __shfl_xor_sync(0xffffffffu, p3, o);
    }
    if (lane == 0) {
        float2 xl2, xr2;
        xl2.x = p0 + b2l[0]; xl2.y = p1 + b2l[1];
        xr2.x = p2 + b2r[0]; xr2.y = p3 + b2r[1];
        *(float2*)&g_XL2[n * 2] = xl2;
        *(float2*)&g_XR2[n * 2] = xr2;
    }
}

// ------------- conv2 CSR + final output (warp per node) --------------------
__global__ __launch_bounds__(256) void conv2_csr_kernel(
    const float* __restrict__ att2, const float* __restrict__ bias2,
    float* __restrict__ out, int N)
{
    const int n = blockIdx.x * 8 + (threadIdx.x >> 5);
    const int lane = threadIdx.x & 31;
    if (n >= N) return;
    const float a0 = att2[0], a1 = att2[1];
    const float a06 = 0.6f * a0, a04 = 0.4f * a0;
    const float a16 = 0.6f * a1, a14 = 0.4f * a1;
    float2 xls = *(const float2*)&g_XL2[n * 2];
    float2 xr  = *(const float2*)&g_XR2[n * 2];

    float den = 0.f, s0 = 0.f, s1 = 0.f;
    const int row0 = g_rowptr[n], row1 = g_rowptr[n + 1];
    for (int i = row0 + lane; i < row1; i += 32) {
        int src = g_esrc[i];
        float2 xl = *(const float2*)&g_XL2[src * 2];
        float f0 = xl.x + xr.x;
        float f1 = xl.y + xr.y;
        float s = fmaf(f0, a06, fmaf(fabsf(f0), a04,
                  fmaf(f1, a16, fabsf(f1) * a14)));
        float exi = __expf(s);
        den += exi;
        s0 = fmaf(exi, xl.x, s0);
        s1 = fmaf(exi, xl.y, s1);
    }
    #pragma unroll
    for (int o = 16; o > 0; o >>= 1) {
        den += __shfl_xor_sync(0xffffffffu, den, o);
        s0  += __shfl_xor_sync(0xffffffffu, s0, o);
        s1  += __shfl_xor_sync(0xffffffffu, s1, o);
    }
    if (lane == 0) {
        float f0 = xls.x + xr.x;
        float f1 = xls.y + xr.y;
        float s = fmaf(f0, a06, fmaf(fabsf(f0), a04,
                  fmaf(f1, a16, fabsf(f1) * a14)));
        float ex = __expf(s);
        den += ex;
        s0 = fmaf(ex, xls.x, s0);
        s1 = fmaf(ex, xls.y, s1);
        float dinv = 1.0f / den;
        float2 o;
        o.x = s0 * dinv + bias2[0];
        o.y = s1 * dinv + bias2[1];
        *(float2*)(out + n * 2) = o;
    }
}

// ---------------------------------------------------------------------------
extern "C" void kernel_launch(void* const* d_in, const int* in_sizes, int n_in,
                              void* d_out, int out_size) {
    const float* x     = (const float*)d_in[0];
    const void*  ei    = d_in[1];
    const float* W1l   = (const float*)d_in[2];
    const float* b1l   = (const float*)d_in[3];
    const float* W1r   = (const float*)d_in[4];
    const float* b1r   = (const float*)d_in[5];
    const float* att1  = (const float*)d_in[6];
    const float* bias1 = (const float*)d_in[7];
    const float* W2l   = (const float*)d_in[8];
    const float* b2l   = (const float*)d_in[9];
    const float* W2r   = (const float*)d_in[10];
    const float* b2r   = (const float*)d_in[11];
    const float* att2  = (const float*)d_in[12];
    const float* bias2 = (const float*)d_in[13];
    const float* Wskip = (const float*)d_in[14];
    const float* bskip = (const float*)d_in[15];
    const float* gamma = (const float*)d_in[16];
    const float* beta  = (const float*)d_in[17];
    float* out = (float*)d_out;

    const int       N = in_sizes[0] / DIN;            // 50000
    const long long E = (long long)in_sizes[1] / 2;   // 800000

    float *dXR1, *dSKIP;
    cudaGetSymbolAddress((void**)&dXR1, g_XR1);
    cudaGetSymbolAddress((void**)&dSKIP, g_SKIP);

    // one-time infra
    static cudaStream_t s2 = nullptr;
    static cudaEvent_t evFork = nullptr, evJoin = nullptr;
    if (s2 == nullptr) {
        cudaStreamCreateWithFlags(&s2, cudaStreamNonBlocking);
        cudaEventCreateWithFlags(&evFork, cudaEventDisableTiming);
        cudaEventCreateWithFlags(&evJoin, cudaEventDisableTiming);
    }

    // ---- stage 0 (main stream): init ----
    init_kernel<<<(N + 255) / 256, 256>>>((const unsigned int*)ei, N);

    // ---- fork: CSR build on s2, concurrent with prep+GEMM on main ----
    cudaEventRecord(evFork, 0);
    cudaStreamWaitEvent(s2, evFork, 0);

    const int SB = (N + 1023) / 1024;
    hist_kernel<<<(int)((E + 255) / 256), 256, 0, s2>>>(ei, E);
    scanA_kernel<<<SB, 1024, 0, s2>>>(N);
    scanB_kernel<<<1, 32, 0, s2>>>(SB);
    scanC_kernel<<<SB, 1024, 0, s2>>>(N);
    scatter_kernel<<<(int)((E + 255) / 256), 256, 0, s2>>>(ei, E);
    cudaEventRecord(evJoin, s2);

    // main stream: prep + GEMM
    {
        int ablocks = (int)(((long long)N * 256 + 1023) / 1024);
        prep_ab_kernel<<<768 + ablocks, 256>>>(x, W1l, W1r, Wskip, N);
    }
    {
        dim3 g(6, (N + 127) / 128);
        gemm_mma_kernel<<<g, 256>>>(b1l, b1r, bskip, dXR1, dSKIP, N);
    }

    // ---- join ----
    cudaStreamWaitEvent(0, evJoin, 0);

    conv1_csr_kernel<<<(N + 7) / 8, 256>>>(att1, bias1, gamma, beta,
                                           W2l, b2l, W2r, b2r, att2, N);
    conv2_csr_kernel<<<(N + 7) / 8, 256>>>(att2, bias2, out, N);
}

// round 17
// speedup vs baseline: 1.3835x; 1.0197x over previous
#include <cuda_runtime.h>
#include <cuda_fp16.h>
#include <math.h>
#include <stdint.h>

// Problem constants
#define DIN   256
#define HCc   256
#define NEG   0.2f
#define MAXN  50000
#define MAXE  1000000
#define MPAD  (MAXN + 128)

// ---------------- scratch (static device globals) --------------------------
__device__ __half g_XL1h[(long long)MAXN * HCc];
__device__ __half g_XR1h[(long long)MAXN * HCc];
__device__ __half g_SKIPh[(long long)MAXN * HCc];
__device__ float g_XL2[MAXN * 2];
__device__ float g_XR2[MAXN * 2];
__device__ int   g_deg[MAXN];
__device__ int   g_rowptr[MAXN + 1];
__device__ int   g_cur[MAXN];
__device__ int   g_esrc[MAXE];
__device__ int   g_bsum[64];
__device__ int   g_boff[64];
__device__ int   g_is64;
__device__ __half g_BTf[3 * 256 * 256];
__device__ __half g_AT_hi[(long long)MPAD * 256];
__device__ __half g_AT_lo[(long long)MPAD * 256];

// ---------------- small helpers ---------------------------------------------
__device__ __forceinline__ uint32_t smem_u32(const void* p) {
    uint32_t a;
    asm("{ .reg .u64 t; cvta.to.shared.u64 t, %1; cvt.u32.u64 %0, t; }"
        : "=r"(a) : "l"(p));
    return a;
}
__device__ __forceinline__ void ldsm_x4(uint32_t* r, uint32_t addr) {
    asm volatile("ldmatrix.sync.aligned.m8n8.x4.shared.b16 {%0,%1,%2,%3}, [%4];"
        : "=r"(r[0]), "=r"(r[1]), "=r"(r[2]), "=r"(r[3]) : "r"(addr));
}
__device__ __forceinline__ void mma_fp16(float* c, const uint32_t* a,
                                         uint32_t b0, uint32_t b1) {
    asm volatile(
        "mma.sync.aligned.m16n8k16.row.col.f32.f16.f16.f32 "
        "{%0,%1,%2,%3}, {%4,%5,%6,%7}, {%8,%9}, {%0,%1,%2,%3};"
        : "+f"(c[0]), "+f"(c[1]), "+f"(c[2]), "+f"(c[3])
        : "r"(a[0]), "r"(a[1]), "r"(a[2]), "r"(a[3]), "r"(b0), "r"(b1));
}
__device__ __forceinline__ void cp_async16(uint32_t dst, const void* src) {
    asm volatile("cp.async.ca.shared.global [%0], [%1], 16;"
                 :: "r"(dst), "l"(src) : "memory");
}
#define CP_COMMIT() asm volatile("cp.async.commit_group;" ::: "memory")
#define CP_WAIT0()  asm volatile("cp.async.wait_group 0;" ::: "memory")

__device__ __forceinline__ int ld_idx(const void* ei, long long pos, int is64) {
    if (is64) return (int)(((const long long*)ei)[pos]);
    return ((const int*)ei)[pos];
}

// ---------------- fused init: zero deg + edge dtype detect ------------------
__global__ void init_kernel(const unsigned int* __restrict__ w, int N) {
    int i = blockIdx.x * blockDim.x + threadIdx.x;
    if (i < N) g_deg[i] = 0;
    if (i == 0) {
        int ok = 1;
        #pragma unroll
        for (int j = 0; j < 32; j++) {
            if (w[2 * j + 1] != 0u) { ok = 0; break; }
        }
        g_is64 = ok;
    }
}

// ---------------- fused prep: B transpose (fp16) AND A split (fp16 hi/lo) ---
__global__ void prep_ab_kernel(const float* __restrict__ x,
                               const float* __restrict__ W0,
                               const float* __restrict__ W1,
                               const float* __restrict__ W2, int N) {
    int b = blockIdx.x;
    if (b < 768) {
        int s = b >> 8, k = b & 255, n = threadIdx.x;
        const float* W = (s == 0) ? W0 : (s == 1) ? W1 : W2;
        float v = W[k * 256 + n];
        g_BTf[(s * 256 + n) * 256 + k] = __float2half(v);
    } else {
        long long eb = (long long)(b - 768) * 1024 + threadIdx.x * 4;
        if (eb < (long long)N * 256) {
            float4 v = *(const float4*)(x + eb);
            float f[4] = {v.x, v.y, v.z, v.w};
            __half h[4], l[4];
            #pragma unroll
            for (int j = 0; j < 4; j++) {
                h[j] = __float2half(f[j]);
                l[j] = __float2half(f[j] - __half2float(h[j]));
            }
            *(ulonglong1*)(g_AT_hi + eb) = *(ulonglong1*)h;
            *(ulonglong1*)(g_AT_lo + eb) = *(ulonglong1*)l;
        }
    }
}

// ---------------- CSR build -------------------------------------------------
__global__ void hist_kernel(const void* __restrict__ ei, long long E) {
    long long e = (long long)blockIdx.x * blockDim.x + threadIdx.x;
    if (e >= E) return;
    int dst = ld_idx(ei, E + e, g_is64);
    atomicAdd(&g_deg[dst], 1);
}
__global__ __launch_bounds__(1024) void scanA_kernel(int N) {
    __shared__ int wsum[32];
    const int lane = threadIdx.x & 31, warp = threadIdx.x >> 5;
    int i = blockIdx.x * 1024 + threadIdx.x;
    int v = (i < N) ? g_deg[i] : 0;
    int x = v;
    #pragma unroll
    for (int o = 1; o < 32; o <<= 1) {
        int y = __shfl_up_sync(0xffffffffu, x, o);
        if (lane >= o) x += y;
    }
    if (lane == 31) wsum[warp] = x;
    __syncthreads();
    if (warp == 0) {
        int w = wsum[lane];
        #pragma unroll
        for (int o = 1; o < 32; o <<= 1) {
            int y = __shfl_up_sync(0xffffffffu, w, o);
            if (lane >= o) w += y;
        }
        wsum[lane] = w;
    }
    __syncthreads();
    int incl = x + (warp > 0 ? wsum[warp - 1] : 0);
    if (i < N) g_rowptr[i + 1] = incl;
    if (threadIdx.x == 1023) g_bsum[blockIdx.x] = incl;
}
__global__ void scanB_kernel(int B) {
    if (threadIdx.x == 0) {
        int acc = 0;
        for (int b = 0; b < B; b++) { int v = g_bsum[b]; g_boff[b] = acc; acc += v; }
    }
}
__global__ __launch_bounds__(1024) void scanC_kernel(int N) {
    int i = blockIdx.x * 1024 + threadIdx.x;
    if (i == 0) g_rowptr[0] = 0;
    if (i < N) {
        int r = g_rowptr[i + 1] + g_boff[blockIdx.x];
        g_rowptr[i + 1] = r;
        g_cur[i] = r - g_deg[i];
    }
}
__global__ void scatter_kernel(const void* __restrict__ ei, long long E) {
    long long e = (long long)blockIdx.x * blockDim.x + threadIdx.x;
    if (e >= E) return;
    int is64 = g_is64;
    int src = ld_idx(ei, e, is64);
    int dst = ld_idx(ei, E + e, is64);
    int pos = atomicAdd(&g_cur[dst], 1);
    g_esrc[pos] = src;
}

// ---------------- mma.sync fp16 triple GEMM ---------------------------------
// sel 0 (XL1, 2-term), sel 1 (XR1, 2-term), sel 2 (SKIP, 1-term).
// ALL outputs stored fp16.
#define PADK 24
#define ABUF (128 * PADK)
#define OPB  (ABUF * 2)
#define BUFB (OPB * 3)

__global__ __launch_bounds__(256, 2) void gemm_mma_kernel(
    const float* __restrict__ bias0, const float* __restrict__ bias1,
    const float* __restrict__ bias2, int M)
{
    __shared__ __half sm[2 * 3 * ABUF];   // 36KB

    const int sel = blockIdx.x >> 1;
    const int n0  = (blockIdx.x & 1) * 128;
    const int m0  = blockIdx.y * 128;
    const float* bias = (sel == 0) ? bias0 : (sel == 1) ? bias1 : bias2;
    __half* Ch = (sel == 0) ? g_XL1h : (sel == 1) ? g_XR1h : g_SKIPh;
    const __half* BTf = g_BTf + sel * 65536 + (long long)n0 * 256;
    const bool two_term = (sel != 2);

    const int tid  = threadIdx.x;
    const int lane = tid & 31;
    const int wid  = tid >> 5;
    const int wm0  = (wid >> 2) * 64;
    const int wn0  = (wid & 3) * 32;

    const int ar = tid >> 1;
    const int ak = (tid & 1) * 8;
    const __half* gAh = g_AT_hi + (long long)(m0 + ar) * 256 + ak;
    const __half* gAl = g_AT_lo + (long long)(m0 + ar) * 256 + ak;
    const __half* gBf = BTf + (long long)ar * 256 + ak;
    const uint32_t dFill = smem_u32(&sm[ar * PADK + ak]);

    uint32_t a_h[4], b_f[2];
    {
        int arow = lane & 15;
        int acol = (lane >> 4) * 8;
        #pragma unroll
        for (int fm = 0; fm < 4; fm++)
            a_h[fm] = smem_u32(&sm[(wm0 + fm * 16 + arow) * PADK + acol]);
        int brow = (lane & 7) + (lane >> 4) * 8;
        int bcol = ((lane >> 3) & 1) * 8;
        #pragma unroll
        for (int nb = 0; nb < 2; nb++)
            b_f[nb] = smem_u32(&sm[2 * ABUF + (wn0 + nb * 16 + brow) * PADK + bcol]);
    }

    float acc[16][4];
    #pragma unroll
    for (int i = 0; i < 16; i++)
        #pragma unroll
        for (int j = 0; j < 4; j++) acc[i][j] = 0.f;

    cp_async16(dFill,           gAh);
    if (two_term) cp_async16(dFill + OPB, gAl);
    cp_async16(dFill + 2 * OPB, gBf);
    CP_COMMIT();
    CP_WAIT0();
    __syncthreads();

    int buf = 0;
    for (int ks = 0; ks < 256; ks += 16) {
        const int nb = buf ^ 1;
        const bool has_next = (ks + 16) < 256;
        if (has_next) {
            const uint32_t d = dFill + nb * BUFB;
            cp_async16(d,           gAh + ks + 16);
            if (two_term) cp_async16(d + OPB, gAl + ks + 16);
            cp_async16(d + 2 * OPB, gBf + ks + 16);
            CP_COMMIT();
        }
        const uint32_t bofs = buf * BUFB;
        uint32_t AF[4][4], BF[2][4];
        #pragma unroll
        for (int fm = 0; fm < 4; fm++) ldsm_x4(AF[fm], a_h[fm] + bofs);
        ldsm_x4(BF[0], b_f[0] + bofs);
        ldsm_x4(BF[1], b_f[1] + bofs);
        #pragma unroll
        for (int fm = 0; fm < 4; fm++)
            #pragma unroll
            for (int fn = 0; fn < 4; fn++)
                mma_fp16(acc[fm * 4 + fn], AF[fm],
                         BF[fn >> 1][(fn & 1) * 2], BF[fn >> 1][(fn & 1) * 2 + 1]);
        if (two_term) {
            #pragma unroll
            for (int fm = 0; fm < 4; fm++) ldsm_x4(AF[fm], a_h[fm] + bofs + OPB);
            #pragma unroll
            for (int fm = 0; fm < 4; fm++)
                #pragma unroll
                for (int fn = 0; fn < 4; fn++)
                    mma_fp16(acc[fm * 4 + fn], AF[fm],
                             BF[fn >> 1][(fn & 1) * 2], BF[fn >> 1][(fn & 1) * 2 + 1]);
        }
        if (has_next) CP_WAIT0();
        __syncthreads();
        buf = nb;
    }

    #pragma unroll
    for (int fm = 0; fm < 4; fm++) {
        int r0 = m0 + wm0 + fm * 16 + (lane >> 2);
        #pragma unroll
        for (int fn = 0; fn < 4; fn++) {
            int col = n0 + wn0 + fn * 8 + (lane & 3) * 2;
            float2 bv = *(const float2*)(bias + col);
            float* a4 = acc[fm * 4 + fn];
            int r1 = r0 + 8;
            if (r0 < M) *(__half2*)(Ch + (long long)r0 * 256 + col) =
                __floats2half2_rn(a4[0] + bv.x, a4[1] + bv.y);
            if (r1 < M) *(__half2*)(Ch + (long long)r1 * 256 + col) =
                __floats2half2_rn(a4[2] + bv.x, a4[3] + bv.y);
        }
    }
}

// ------- fused conv1 CSR + softmax + skip + LN + ELU + conv2 projection ----
__device__ __forceinline__ void load_h8(const __half* base, int lane, float* xl) {
    uint4 hv = *(const uint4*)(base + lane * 8);
    float2 f0 = __half22float2(*(__half2*)&hv.x);
    float2 f1 = __half22float2(*(__half2*)&hv.y);
    float2 f2 = __half22float2(*(__half2*)&hv.z);
    float2 f3 = __half22float2(*(__half2*)&hv.w);
    xl[0]=f0.x; xl[1]=f0.y; xl[2]=f1.x; xl[3]=f1.y;
    xl[4]=f2.x; xl[5]=f2.y; xl[6]=f3.x; xl[7]=f3.y;
}

__global__ __launch_bounds__(256, 4) void conv1_csr_kernel(
    const float* __restrict__ att1, const float* __restrict__ bias1,
    const float* __restrict__ gamma, const float* __restrict__ beta,
    const float* __restrict__ W2l, const float* __restrict__ b2l,
    const float* __restrict__ W2r, const float* __restrict__ b2r,
    const float* __restrict__ att2, int N)
{
    const int n = blockIdx.x * 8 + (threadIdx.x >> 5);
    const int lane = threadIdx.x & 31;
    if (n >= N) return;

    float att6[8], att4[8];
    {
        float4 a0 = *(const float4*)(att1 + lane * 8);
        float4 a1 = *(const float4*)(att1 + lane * 8 + 4);
        float av[8] = {a0.x,a0.y,a0.z,a0.w,a1.x,a1.y,a1.z,a1.w};
        #pragma unroll
        for (int j = 0; j < 8; j++) { att6[j] = 0.6f * av[j]; att4[j] = 0.4f * av[j]; }
    }
    float xr[8];
    load_h8(g_XR1h + (long long)n * HCc, lane, xr);

    float acc[8], den;
    {
        float xl[8];
        load_h8(g_XL1h + (long long)n * HCc, lane, xl);
        float s6 = 0.f, s4 = 0.f;
        #pragma unroll
        for (int j = 0; j < 8; j++) {
            float e = xl[j] + xr[j];
            s6 = fmaf(e, att6[j], s6);
            s4 = fmaf(fabsf(e), att4[j], s4);
        }
        float s = s6 + s4;
        s += __shfl_xor_sync(0xffffffffu, s, 1);
        s += __shfl_xor_sync(0xffffffffu, s, 2);
        s += __shfl_xor_sync(0xffffffffu, s, 4);
        float ex = __expf(s);
        den = ex;
        #pragma unroll
        for (int j = 0; j < 8; j++) acc[j] = ex * xl[j];
    }

    const int row0 = g_rowptr[n];
    const int row1 = g_rowptr[n + 1];
    int i = row0;
    for (; i + 1 < row1; i += 2) {
        int srcA = g_esrc[i];
        int srcB = g_esrc[i + 1];
        float xlA[8], xlB[8];
        load_h8(g_XL1h + (long long)srcA * HCc, lane, xlA);
        load_h8(g_XL1h + (long long)srcB * HCc, lane, xlB);
        float sA6 = 0.f, sA4 = 0.f, sB6 = 0.f, sB4 = 0.f;
        #pragma unroll
        for (int j = 0; j < 8; j++) {
            float eA = xlA[j] + xr[j];
            float eB = xlB[j] + xr[j];
            sA6 = fmaf(eA, att6[j], sA6);
            sA4 = fmaf(fabsf(eA), att4[j], sA4);
            sB6 = fmaf(eB, att6[j], sB6);
            sB4 = fmaf(fabsf(eB), att4[j], sB4);
        }
        float sA = sA6 + sA4, sB = sB6 + sB4;
        #pragma unroll
        for (int o = 1; o <= 4; o <<= 1) {
            sA += __shfl_xor_sync(0xffffffffu, sA, o);
            sB += __shfl_xor_sync(0xffffffffu, sB, o);
        }
        float exA = __expf(sA);
        float exB = __expf(sB);
        den += exA + exB;
        #pragma unroll
        for (int j = 0; j < 8; j++) {
            acc[j] = fmaf(exA, xlA[j], acc[j]);
            acc[j] = fmaf(exB, xlB[j], acc[j]);
        }
    }
    if (i < row1) {
        int src = g_esrc[i];
        float xl[8];
        load_h8(g_XL1h + (long long)src * HCc, lane, xl);
        float s6 = 0.f, s4 = 0.f;
        #pragma unroll
        for (int j = 0; j < 8; j++) {
            float e = xl[j] + xr[j];
            s6 = fmaf(e, att6[j], s6);
            s4 = fmaf(fabsf(e), att4[j], s4);
        }
        float s = s6 + s4;
        s += __shfl_xor_sync(0xffffffffu, s, 1);
        s += __shfl_xor_sync(0xffffffffu, s, 2);
        s += __shfl_xor_sync(0xffffffffu, s, 4);
        float ex = __expf(s);
        den += ex;
        #pragma unroll
        for (int j = 0; j < 8; j++) acc[j] = fmaf(ex, xl[j], acc[j]);
    }

    const float dinv = 1.0f / den;
    float v[8];
    {
        float sk[8];
        load_h8(g_SKIPh + (long long)n * HCc, lane, sk);
        float4 b0 = *(const float4*)(bias1 + lane * 8);
        float4 b1 = *(const float4*)(bias1 + lane * 8 + 4);
        float bb[8] = {b0.x,b0.y,b0.z,b0.w,b1.x,b1.y,b1.z,b1.w};
        #pragma unroll
        for (int j = 0; j < 8; j++) v[j] = acc[j] * dinv + bb[j] + sk[j];
    }

    float t = 0.f;
    #pragma unroll
    for (int j = 0; j < 8; j++) t += v[j];
    #pragma unroll
    for (int o = 16; o > 0; o >>= 1) t += __shfl_xor_sync(0xffffffffu, t, o);
    const float mu = t * (1.0f / 256.0f);
    float t2 = 0.f;
    #pragma unroll
    for (int j = 0; j < 8; j++) { float d = v[j] - mu; t2 = fmaf(d, d, t2); }
    #pragma unroll
    for (int o = 16; o > 0; o >>= 1) t2 += __shfl_xor_sync(0xffffffffu, t2, o);
    const float rstd = rsqrtf(t2 * (1.0f / 256.0f) + 1e-5f);

    float h[8];
    {
        float4 g0 = *(const float4*)(gamma + lane * 8);
        float4 g1 = *(const float4*)(gamma + lane * 8 + 4);
        float4 e0 = *(const float4*)(beta + lane * 8);
        float4 e1 = *(const float4*)(beta + lane * 8 + 4);
        float gg[8] = {g0.x,g0.y,g0.z,g0.w,g1.x,g1.y,g1.z,g1.w};
        float be[8] = {e0.x,e0.y,e0.z,e0.w,e1.x,e1.y,e1.z,e1.w};
        #pragma unroll
        for (int j = 0; j < 8; j++) {
            float hh = (v[j] - mu) * rstd * gg[j] + be[j];
            h[j] = hh > 0.f ? hh : expm1f(hh);
        }
    }

    float p0 = 0.f, p1 = 0.f, p2 = 0.f, p3 = 0.f;
    {
        const float* wl = W2l + lane * 16;
        const float* wr = W2r + lane * 16;
        float4 wl0 = *(const float4*)wl;
        float4 wl1 = *(const float4*)(wl + 4);
        float4 wl2 = *(const float4*)(wl + 8);
        float4 wl3 = *(const float4*)(wl + 12);
        float4 wr0 = *(const float4*)wr;
        float4 wr1 = *(const float4*)(wr + 4);
        float4 wr2 = *(const float4*)(wr + 8);
        float4 wr3 = *(const float4*)(wr + 12);
        float wlv[16] = {wl0.x,wl0.y,wl0.z,wl0.w, wl1.x,wl1.y,wl1.z,wl1.w,
                         wl2.x,wl2.y,wl2.z,wl2.w, wl3.x,wl3.y,wl3.z,wl3.w};
        float wrv[16] = {wr0.x,wr0.y,wr0.z,wr0.w, wr1.x,wr1.y,wr1.z,wr1.w,
                         wr2.x,wr2.y,wr2.z,wr2.w, wr3.x,wr3.y,wr3.z,wr3.w};
        #pragma unroll
        for (int j = 0; j < 8; j++) {
            p0 = fmaf(h[j], wlv[2 * j + 0], p0);
            p1 = fmaf(h[j], wlv[2 * j + 1], p1);
            p2 = fmaf(h[j], wrv[2 * j + 0], p2);
            p3 = fmaf(h[j], wrv[2 * j + 1], p3);
        }
    }
    #pragma unroll
    for (int o = 16; o > 0; o >>= 1) {
        p0 += __shfl_xor_sync(0xffffffffu, p0, o);
        p1 += __shfl_xor_sync(0xffffffffu, p1, o);
        p2 += __shfl_xor_sync(0xffffffffu, p2, o);
        p3 += __shfl_xor_sync(0xffffffffu, p3, o);
    }
    if (lane == 0) {
        float2 xl2, xr2;
        xl2.x = p0 + b2l[0]; xl2.y = p1 + b2l[1];
        xr2.x = p2 + b2r[0]; xr2.y = p3 + b2r[1];
        *(float2*)&g_XL2[n * 2] = xl2;
        *(float2*)&g_XR2[n * 2] = xr2;
    }
}

// ------------- conv2 CSR + final output (warp per node) --------------------
__global__ __launch_bounds__(256) void conv2_csr_kernel(
    const float* __restrict__ att2, const float* __restrict__ bias2,
    float* __restrict__ out, int N)
{
    const int n = blockIdx.x * 8 + (threadIdx.x >> 5);
    const int lane = threadIdx.x & 31;
    if (n >= N) return;
    const float a0 = att2[0], a1 = att2[1];
    const float a06 = 0.6f * a0, a04 = 0.4f * a0;
    const float a16 = 0.6f * a1, a14 = 0.4f * a1;
    float2 xls = *(const float2*)&g_XL2[n * 2];
    float2 xr  = *(const float2*)&g_XR2[n * 2];

    float den = 0.f, s0 = 0.f, s1 = 0.f;
    const int row0 = g_rowptr[n], row1 = g_rowptr[n + 1];
    for (int i = row0 + lane; i < row1; i += 32) {
        int src = g_esrc[i];
        float2 xl = *(const float2*)&g_XL2[src * 2];
        float f0 = xl.x + xr.x;
        float f1 = xl.y + xr.y;
        float s = fmaf(f0, a06, fmaf(fabsf(f0), a04,
                  fmaf(f1, a16, fabsf(f1) * a14)));
        float exi = __expf(s);
        den += exi;
        s0 = fmaf(exi, xl.x, s0);
        s1 = fmaf(exi, xl.y, s1);
    }
    #pragma unroll
    for (int o = 16; o > 0; o >>= 1) {
        den += __shfl_xor_sync(0xffffffffu, den, o);
        s0  += __shfl_xor_sync(0xffffffffu, s0, o);
        s1  += __shfl_xor_sync(0xffffffffu, s1, o);
    }
    if (lane == 0) {
        float f0 = xls.x + xr.x;
        float f1 = xls.y + xr.y;
        float s = fmaf(f0, a06, fmaf(fabsf(f0), a04,
                  fmaf(f1, a16, fabsf(f1) * a14)));
        float ex = __expf(s);
        den += ex;
        s0 = fmaf(ex, xls.x, s0);
        s1 = fmaf(ex, xls.y, s1);
        float dinv = 1.0f / den;
        float2 o;
        o.x = s0 * dinv + bias2[0];
        o.y = s1 * dinv + bias2[1];
        *(float2*)(out + n * 2) = o;
    }
}

// ---------------------------------------------------------------------------
extern "C" void kernel_launch(void* const* d_in, const int* in_sizes, int n_in,
                              void* d_out, int out_size) {
    const float* x     = (const float*)d_in[0];
    const void*  ei    = d_in[1];
    const float* W1l   = (const float*)d_in[2];
    const float* b1l   = (const float*)d_in[3];
    const float* W1r   = (const float*)d_in[4];
    const float* b1r   = (const float*)d_in[5];
    const float* att1  = (const float*)d_in[6];
    const float* bias1 = (const float*)d_in[7];
    const float* W2l   = (const float*)d_in[8];
    const float* b2l   = (const float*)d_in[9];
    const float* W2r   = (const float*)d_in[10];
    const float* b2r   = (const float*)d_in[11];
    const float* att2  = (const float*)d_in[12];
    const float* bias2 = (const float*)d_in[13];
    const float* Wskip = (const float*)d_in[14];
    const float* bskip = (const float*)d_in[15];
    const float* gamma = (const float*)d_in[16];
    const float* beta  = (const float*)d_in[17];
    float* out = (float*)d_out;

    const int       N = in_sizes[0] / DIN;            // 50000
    const long long E = (long long)in_sizes[1] / 2;   // 800000

    // one-time infra
    static cudaStream_t s2 = nullptr;
    static cudaEvent_t evFork = nullptr, evJoin = nullptr;
    if (s2 == nullptr) {
        cudaStreamCreateWithFlags(&s2, cudaStreamNonBlocking);
        cudaEventCreateWithFlags(&evFork, cudaEventDisableTiming);
        cudaEventCreateWithFlags(&evJoin, cudaEventDisableTiming);
    }

    // ---- stage 0 (main stream): init ----
    init_kernel<<<(N + 255) / 256, 256>>>((const unsigned int*)ei, N);

    // ---- fork: CSR build on s2, concurrent with prep+GEMM on main ----
    cudaEventRecord(evFork, 0);
    cudaStreamWaitEvent(s2, evFork, 0);

    const int SB = (N + 1023) / 1024;
    hist_kernel<<<(int)((E + 255) / 256), 256, 0, s2>>>(ei, E);
    scanA_kernel<<<SB, 1024, 0, s2>>>(N);
    scanB_kernel<<<1, 32, 0, s2>>>(SB);
    scanC_kernel<<<SB, 1024, 0, s2>>>(N);
    scatter_kernel<<<(int)((E + 255) / 256), 256, 0, s2>>>(ei, E);
    cudaEventRecord(evJoin, s2);

    // main stream: prep + GEMM
    {
        int ablocks = (int)(((long long)N * 256 + 1023) / 1024);
        prep_ab_kernel<<<768 + ablocks, 256>>>(x, W1l, W1r, Wskip, N);
    }
    {
        dim3 g(6, (N + 127) / 128);
        gemm_mma_kernel<<<g, 256>>>(b1l, b1r, bskip, N);
    }

    // ---- join ----
    cudaStreamWaitEvent(0, evJoin, 0);

    conv1_csr_kernel<<<(N + 7) / 8, 256>>>(att1, bias1, gamma, beta,
                                           W2l, b2l, W2r, b2r, att2, N);
    conv2_csr_kernel<<<(N + 7) / 8, 256>>>(att2, bias2, out, N);
}